// round 6
// baseline (speedup 1.0000x reference)
#include <cuda_runtime.h>
#include <math.h>
#include <stdint.h>

// Problem constants
#define NN 20000
#define EE 320000
#define RR 100
#define FF 256
#define HH 8
#define DD 32
#define FHID 1024
#define PF 768            // packed projection stride (fh|ftl|fen)
#define ALPHA 0.1f
#define SLOPE 0.2f

// ---------------------------------------------------------------------------
__device__ __forceinline__ uint32_t smem_u32(const void* p) {
    uint32_t a;
    asm("{ .reg .u64 t; cvta.to.shared.u64 t, %1; cvt.u32.u64 %0, t; }" : "=r"(a) : "l"(p));
    return a;
}
#define CP_ASYNC16(dst, src) \
    asm volatile("cp.async.cg.shared.global [%0], [%1], 16;" :: "r"(dst), "l"(src) : "memory")
#define CP_COMMIT() asm volatile("cp.async.commit_group;" ::: "memory")
#define CP_WAIT(n)  asm volatile("cp.async.wait_group %0;" :: "n"(n) : "memory")

#define LDSM_X4(r0, r1, r2, r3, addr) \
    asm volatile("ldmatrix.sync.aligned.m8n8.x4.shared.b16 {%0,%1,%2,%3}, [%4];" \
                 : "=r"(r0), "=r"(r1), "=r"(r2), "=r"(r3) : "r"(addr))
#define MMA_TF32(c, a, b) \
    asm volatile("mma.sync.aligned.m16n8k8.row.col.f32.tf32.tf32.f32 " \
                 "{%0,%1,%2,%3},{%4,%5,%6,%7},{%8,%9},{%0,%1,%2,%3};" \
                 : "+f"((c)[0]), "+f"((c)[1]), "+f"((c)[2]), "+f"((c)[3]) \
                 : "r"((a)[0]), "r"((a)[1]), "r"((a)[2]), "r"((a)[3]), \
                   "r"((b)[0]), "r"((b)[1]))

__device__ __forceinline__ float tf32_rnd(float x) {
    uint32_t u = __float_as_uint(x), o;
    asm("cvt.rna.tf32.f32 %0, %1;" : "=r"(o) : "r"(u));
    return __uint_as_float(o);
}

// ------------------------- scratch (device globals) -------------------------
__device__ float g_xln[NN * FF];
__device__ float g_proj[NN * PF];      // [fh | ftl | fen] packed per row
__device__ float g_rln[RR * FF];
__device__ float g_fr [RR * FF];
__device__ int   g_cnt [NN];
__device__ int   g_fill[NN];
__device__ int   g_rowptr[NN + 1];
__device__ int   g_srcs[EE];
__device__ int   g_rids[EE];
__device__ float g_e[EE * HH];
__device__ float g_a[EE * HH];
__device__ float g_fa[NN * FF];
__device__ float g_fb[NN * FF];
__device__ float g_rst[NN * FF];
__device__ float g_y  [NN * FF];
__device__ float g_hid[NN * FHID];
__device__ float g_wcatT[PF * FF];     // K-major [768,256]: Whead|Wtail|Went rows
__device__ float g_wrelT [FF * FF];
__device__ float g_w1T[FHID * FF];
__device__ float g_w2T[FF * FHID];

// ------------------------- LayerNorm (outputs tf32-rounded) -------------------
__global__ void ln_kernel(const float* __restrict__ in, float* __restrict__ out,
                          const float* __restrict__ gam, const float* __restrict__ bet) {
    int row = blockIdx.x;
    int t = threadIdx.x;
    float x = in[row * FF + t];
    float s = x, s2 = x * x;
    #pragma unroll
    for (int o = 16; o; o >>= 1) {
        s  += __shfl_xor_sync(0xffffffffu, s,  o);
        s2 += __shfl_xor_sync(0xffffffffu, s2, o);
    }
    __shared__ float rs[8], rs2[8];
    int w = t >> 5, l = t & 31;
    if (l == 0) { rs[w] = s; rs2[w] = s2; }
    __syncthreads();
    s = 0.f; s2 = 0.f;
    #pragma unroll
    for (int i = 0; i < 8; i++) { s += rs[i]; s2 += rs2[i]; }
    float m = s * (1.0f / FF);
    float var = s2 * (1.0f / FF) - m * m;
    float inv = rsqrtf(var + 1e-5f);
    out[row * FF + t] = tf32_rnd((x - m) * inv * gam[t] + bet[t]);
}

// ------------------------- weight transpose (+tf32 round) --------------------
__global__ void transpose_rnd(const float* __restrict__ B, float* __restrict__ BT,
                              int K, int N) {
    __shared__ float t[32][33];
    int n0 = blockIdx.x * 32, k0 = blockIdx.y * 32;
    int x = threadIdx.x, y = threadIdx.y;
    #pragma unroll
    for (int r = 0; r < 32; r += 8)
        t[y + r][x] = B[(size_t)(k0 + y + r) * N + n0 + x];
    __syncthreads();
    #pragma unroll
    for (int r = 0; r < 32; r += 8)
        BT[(size_t)(n0 + y + r) * K + k0 + x] = tf32_rnd(t[x][y + r]);
}
__global__ void transpose4_rnd(const float* __restrict__ Wh, const float* __restrict__ Wt,
                               const float* __restrict__ We, const float* __restrict__ Wr,
                               float* __restrict__ wcat, float* __restrict__ wrel) {
    __shared__ float t[32][33];
    int z = blockIdx.z;
    const float* B = (z == 0) ? Wh : (z == 1) ? Wt : (z == 2) ? We : Wr;
    float* BT = (z < 3) ? (wcat + (size_t)z * FF * FF) : wrel;
    int n0 = blockIdx.x * 32, k0 = blockIdx.y * 32;
    int x = threadIdx.x, y = threadIdx.y;
    #pragma unroll
    for (int r = 0; r < 32; r += 8)
        t[y + r][x] = B[(size_t)(k0 + y + r) * FF + n0 + x];
    __syncthreads();
    #pragma unroll
    for (int r = 0; r < 32; r += 8)
        BT[(size_t)(n0 + y + r) * FF + k0 + x] = tf32_rnd(t[x][y + r]);
}

// ------------------------- tf32 mma.sync GEMM (R4 config) --------------------
// C[M,Nc] = A[M,K] @ BT[Nc,K]^T (+bias) (relu if mode&1) (tf32-round if mode&2)
// (+res if res != null). 128x128 block tile, BK=32, 3-stage cp.async, 8 warps.
#define GSTAGES 3
#define GSTG 32768
#define GSMEM_BYTES (GSTAGES * GSTG)

__global__ void __launch_bounds__(256, 2)
mma_gemm(const float* __restrict__ A, const float* __restrict__ BT,
         float* __restrict__ C, int M, int Nc, int K,
         const float* __restrict__ bias, const float* __restrict__ res, int mode) {
    extern __shared__ float smemf[];
    const uint32_t sb = smem_u32(smemf);

    const int m0 = blockIdx.y * 128;
    const int n0 = blockIdx.x * 128;
    const int tid = threadIdx.x;
    const int warp = tid >> 5, lane = tid & 31;
    const int wm = warp >> 2, wn = warp & 3;          // 2 x 4 warps

    // ---- async load setup: each thread owns half a 128B row of A and B ----
    const int lrow = tid >> 1, lhalf = tid & 1;
    int aRow = m0 + lrow; if (aRow >= M) aRow = M - 1;
    const float* aG = A + (size_t)aRow * K + lhalf * 16;
    const float* bG = BT + (size_t)(n0 + lrow) * K + lhalf * 16;
    const uint32_t sA = sb + (uint32_t)lrow * 128;
    const uint32_t sB = sb + 16384 + (uint32_t)lrow * 128;
    uint32_t swz[4];
    #pragma unroll
    for (int j = 0; j < 4; j++)
        swz[j] = (uint32_t)(((lhalf * 4 + j) ^ (lrow & 7)) << 4);

    const int nCh = K >> 5;

    float c[4][4][4];
    #pragma unroll
    for (int mt = 0; mt < 4; mt++)
        #pragma unroll
        for (int nt = 0; nt < 4; nt++)
            #pragma unroll
            for (int q = 0; q < 4; q++) c[mt][nt][q] = 0.f;

    // prologue: stages 0 and 1
    #pragma unroll
    for (int s = 0; s < 2; s++) {
        const uint32_t off = (uint32_t)s * GSTG;
        const float* ag = aG + s * 32;
        const float* bg = bG + s * 32;
        #pragma unroll
        for (int j = 0; j < 4; j++) CP_ASYNC16(sA + off + swz[j], ag + j * 4);
        #pragma unroll
        for (int j = 0; j < 4; j++) CP_ASYNC16(sB + off + swz[j], bg + j * 4);
        CP_COMMIT();
    }

    const int q8 = lane >> 3, r8 = lane & 7;

    for (int i = 0; i < nCh; i++) {
        __syncthreads();                     // WAR: stage (i+2)%3 free
        if (i + 2 < nCh) {
            const uint32_t off = (uint32_t)((i + 2) % GSTAGES) * GSTG;
            const float* ag = aG + (i + 2) * 32;
            const float* bg = bG + (i + 2) * 32;
            #pragma unroll
            for (int j = 0; j < 4; j++) CP_ASYNC16(sA + off + swz[j], ag + j * 4);
            #pragma unroll
            for (int j = 0; j < 4; j++) CP_ASYNC16(sB + off + swz[j], bg + j * 4);
        }
        CP_COMMIT();                          // constant group count per iter
        CP_WAIT(2);                           // chunk i resident
        __syncthreads();

        const uint32_t Ab = sb + (uint32_t)(i % GSTAGES) * GSTG;
        const uint32_t Bb = Ab + 16384;
        #pragma unroll
        for (int ks = 0; ks < 4; ks++) {
            uint32_t a[4][4];
            #pragma unroll
            for (int mt = 0; mt < 4; mt++) {
                const int rl = wm * 64 + mt * 16 + (q8 & 1) * 8 + r8;
                const int kc = ks * 2 + (q8 >> 1);
                const uint32_t ad = Ab + (uint32_t)rl * 128 + (uint32_t)((kc ^ (rl & 7)) << 4);
                LDSM_X4(a[mt][0], a[mt][1], a[mt][2], a[mt][3], ad);
            }
            uint32_t b[4][2];
            #pragma unroll
            for (int ntp = 0; ntp < 2; ntp++) {
                const int nl = wn * 32 + ntp * 16 + (q8 >> 1) * 8 + r8;
                const int kc = ks * 2 + (q8 & 1);
                const uint32_t bd = Bb + (uint32_t)nl * 128 + (uint32_t)((kc ^ (nl & 7)) << 4);
                LDSM_X4(b[ntp * 2][0], b[ntp * 2][1], b[ntp * 2 + 1][0], b[ntp * 2 + 1][1], bd);
            }
            #pragma unroll
            for (int mt = 0; mt < 4; mt++)
                #pragma unroll
                for (int nt = 0; nt < 4; nt++)
                    MMA_TF32(c[mt][nt], a[mt], b[nt]);
        }
    }

    // ---- epilogue ----
    const int g = lane >> 2, t4 = lane & 3;
    #pragma unroll
    for (int mt = 0; mt < 4; mt++) {
        #pragma unroll
        for (int half = 0; half < 2; half++) {
            const int m = m0 + wm * 64 + mt * 16 + g + half * 8;
            if (m < M) {
                float* cRow = C + (size_t)m * Nc + n0 + wn * 32;
                const float* rRow = res ? (res + (size_t)m * Nc + n0 + wn * 32) : nullptr;
                #pragma unroll
                for (int nt = 0; nt < 4; nt++) {
                    const int colb = nt * 8 + 2 * t4;
                    float v0 = c[mt][nt][half * 2 + 0];
                    float v1 = c[mt][nt][half * 2 + 1];
                    if (bias) {
                        const float* bp = bias + n0 + wn * 32 + colb;
                        v0 += bp[0]; v1 += bp[1];
                    }
                    if (mode & 1) { v0 = fmaxf(v0, 0.f); v1 = fmaxf(v1, 0.f); }
                    if (mode & 2) { v0 = tf32_rnd(v0); v1 = tf32_rnd(v1); }
                    if (rRow) { v0 += rRow[colb]; v1 += rRow[colb + 1]; }
                    float2 v; v.x = v0; v.y = v1;
                    *(float2*)(cRow + colb) = v;
                }
            }
        }
    }
}

// ------------------------- CSR build -----------------------------------------
__global__ void zero_kernel() {
    int i = blockIdx.x * blockDim.x + threadIdx.x;
    if (i < NN) { g_cnt[i] = 0; g_fill[i] = 0; }
}
__global__ void count_kernel(const int* __restrict__ dst) {
    int i = blockIdx.x * blockDim.x + threadIdx.x;
    if (i < EE) atomicAdd(&g_cnt[dst[i]], 1);
}
__global__ void scan_kernel() {
    __shared__ int ss[1024];
    int t = threadIdx.x;
    const int CH = (NN + 1023) / 1024;
    int base = t * CH;
    int loc = 0;
    for (int i = 0; i < CH; i++) {
        int idx = base + i;
        if (idx < NN) loc += g_cnt[idx];
    }
    ss[t] = loc;
    __syncthreads();
    for (int off = 1; off < 1024; off <<= 1) {
        int v = (t >= off) ? ss[t - off] : 0;
        __syncthreads();
        ss[t] += v;
        __syncthreads();
    }
    int run = (t == 0) ? 0 : ss[t - 1];
    for (int i = 0; i < CH; i++) {
        int idx = base + i;
        if (idx < NN) { g_rowptr[idx] = run; run += g_cnt[idx]; }
    }
    if (t == 0) g_rowptr[NN] = EE;
}
__global__ void scatter_kernel(const int* __restrict__ src, const int* __restrict__ dst,
                               const int* __restrict__ rid) {
    int i = blockIdx.x * blockDim.x + threadIdx.x;
    if (i < EE) {
        int d = dst[i];
        int pos = g_rowptr[d] + atomicAdd(&g_fill[d], 1);
        g_srcs[pos] = src[i];
        g_rids[pos] = rid[i];
    }
}

// ------------------------- edge attention + softmax ---------------------------
// one warp per dst node. Lane layout (score phase): h = lane>>2 owns head h,
// d-block = (lane&3)*8 (8 contiguous floats). Warp loads are fully coalesced.
__global__ void attn_kernel(const float* __restrict__ attn) {
    int w = (blockIdx.x * blockDim.x + threadIdx.x) >> 5;
    int lane = threadIdx.x & 31;
    if (w >= NN) return;
    int node = w;
    const int h = lane >> 2;            // head for score phase
    const int db = (lane & 3) * 8;      // d-offset within head
    const int off = h * DD + db;

    float4 tl0 = *(const float4*)(g_proj + (size_t)node * PF + FF + off);
    float4 tl1 = *(const float4*)(g_proj + (size_t)node * PF + FF + off + 4);
    float4 av0 = *(const float4*)(attn + off);
    float4 av1 = *(const float4*)(attn + off + 4);

    int beg = g_rowptr[node], end = g_rowptr[node + 1];
    float scale = logf((float)(end - beg)) * (1.0f / DD);

    for (int p = beg; p < end; p++) {
        int s = g_srcs[p], r = g_rids[p];
        const float* fhp = g_proj + (size_t)s * PF + off;
        const float* frp = g_fr + (size_t)r * FF + off;
        float4 fh0 = *(const float4*)(fhp);
        float4 fh1 = *(const float4*)(fhp + 4);
        float4 fr0 = *(const float4*)(frp);
        float4 fr1 = *(const float4*)(frp + 4);
        float v = 0.f;
        {
            float x;
            x = fh0.x * tl0.x * fr0.x; x = (x > 0.f) ? x : SLOPE * x; v += x * av0.x;
            x = fh0.y * tl0.y * fr0.y; x = (x > 0.f) ? x : SLOPE * x; v += x * av0.y;
            x = fh0.z * tl0.z * fr0.z; x = (x > 0.f) ? x : SLOPE * x; v += x * av0.z;
            x = fh0.w * tl0.w * fr0.w; x = (x > 0.f) ? x : SLOPE * x; v += x * av0.w;
            x = fh1.x * tl1.x * fr1.x; x = (x > 0.f) ? x : SLOPE * x; v += x * av1.x;
            x = fh1.y * tl1.y * fr1.y; x = (x > 0.f) ? x : SLOPE * x; v += x * av1.y;
            x = fh1.z * tl1.z * fr1.z; x = (x > 0.f) ? x : SLOPE * x; v += x * av1.z;
            x = fh1.w * tl1.w * fr1.w; x = (x > 0.f) ? x : SLOPE * x; v += x * av1.w;
        }
        v += __shfl_xor_sync(0xffffffffu, v, 1);
        v += __shfl_xor_sync(0xffffffffu, v, 2);
        if ((lane & 3) == 0) g_e[p * HH + h] = v * scale;
    }
    __syncwarp();

    // softmax phase: lane -> (edge-slot pi = lane>>3, head hs = lane&7)
    const int hs = lane & 7, pi = lane >> 3;
    float m = -1e30f;
    for (int p = beg + pi; p < end; p += 4) m = fmaxf(m, g_e[p * HH + hs]);
    m = fmaxf(m, __shfl_xor_sync(0xffffffffu, m, 8));
    m = fmaxf(m, __shfl_xor_sync(0xffffffffu, m, 16));
    float ssum = 0.f;
    for (int p = beg + pi; p < end; p += 4) ssum += expf(g_e[p * HH + hs] - m);
    ssum += __shfl_xor_sync(0xffffffffu, ssum, 8);
    ssum += __shfl_xor_sync(0xffffffffu, ssum, 16);
    float inv = 1.0f / ssum;
    for (int p = beg + pi; p < end; p += 4)
        g_a[p * HH + hs] = expf(g_e[p * HH + hs] - m) * inv;
}

// ------------------------- diffusion hop --------------------------------------
// one warp per dst node; lane owns 8 contiguous floats (cols lane*8..lane*8+7),
// i.e. head lane>>2. Per edge: 2x LDG.128 + 1 broadcast a-load.
__global__ void hop_kernel(const float* __restrict__ fin, int fstride,
                           float* __restrict__ fout, const float* __restrict__ ent) {
    int w = (blockIdx.x * blockDim.x + threadIdx.x) >> 5;
    int lane = threadIdx.x & 31;
    if (w >= NN) return;
    int node = w;
    const int col = lane * 8;
    const int h = lane >> 2;
    int beg = g_rowptr[node], end = g_rowptr[node + 1];

    float4 a0 = make_float4(0.f, 0.f, 0.f, 0.f);
    float4 a1 = make_float4(0.f, 0.f, 0.f, 0.f);
    for (int p = beg; p < end; p++) {
        int s = g_srcs[p];
        float av = g_a[p * HH + h];
        const float* frow = fin + (size_t)s * fstride + col;
        float4 f0 = *(const float4*)(frow);
        float4 f1 = *(const float4*)(frow + 4);
        a0.x += av * f0.x; a0.y += av * f0.y; a0.z += av * f0.z; a0.w += av * f0.w;
        a1.x += av * f1.x; a1.y += av * f1.y; a1.z += av * f1.z; a1.w += av * f1.w;
    }
    const float* f0p = g_proj + (size_t)node * PF + 2 * FF + col;
    float4 e0 = *(const float4*)(f0p);
    float4 e1 = *(const float4*)(f0p + 4);
    float4 o0, o1;
    o0.x = (1.0f - ALPHA) * a0.x + ALPHA * e0.x;
    o0.y = (1.0f - ALPHA) * a0.y + ALPHA * e0.y;
    o0.z = (1.0f - ALPHA) * a0.z + ALPHA * e0.z;
    o0.w = (1.0f - ALPHA) * a0.w + ALPHA * e0.w;
    o1.x = (1.0f - ALPHA) * a1.x + ALPHA * e1.x;
    o1.y = (1.0f - ALPHA) * a1.y + ALPHA * e1.y;
    o1.z = (1.0f - ALPHA) * a1.z + ALPHA * e1.z;
    o1.w = (1.0f - ALPHA) * a1.w + ALPHA * e1.w;
    if (ent) {
        const float* ep = ent + (size_t)node * FF + col;
        float4 n0 = *(const float4*)(ep);
        float4 n1 = *(const float4*)(ep + 4);
        o0.x += n0.x; o0.y += n0.y; o0.z += n0.z; o0.w += n0.w;
        o1.x += n1.x; o1.y += n1.y; o1.z += n1.z; o1.w += n1.w;
    }
    float* op = fout + (size_t)node * FF + col;
    *(float4*)(op) = o0;
    *(float4*)(op + 4) = o1;
}

// ------------------------- launcher -------------------------------------------
extern "C" void kernel_launch(void* const* d_in, const int* in_sizes, int n_in,
                              void* d_out, int out_size) {
    const float* ent_feat = (const float*)d_in[0];
    const float* rel_feat = (const float*)d_in[1];
    const float* W_head   = (const float*)d_in[2];
    const float* W_tail   = (const float*)d_in[3];
    const float* W_ent    = (const float*)d_in[4];
    const float* W_rel    = (const float*)d_in[5];
    const float* attn     = (const float*)d_in[6];
    const float* ln_ent_g = (const float*)d_in[7];
    const float* ln_ent_b = (const float*)d_in[8];
    const float* ln_rel_g = (const float*)d_in[9];
    const float* ln_rel_b = (const float*)d_in[10];
    const float* ln_ff_g  = (const float*)d_in[11];
    const float* ln_ff_b  = (const float*)d_in[12];
    const float* W1       = (const float*)d_in[13];
    const float* b1       = (const float*)d_in[14];
    const float* W2       = (const float*)d_in[15];
    const float* b2       = (const float*)d_in[16];
    const int*   src      = (const int*)d_in[17];
    const int*   dst      = (const int*)d_in[18];
    const int*   rid      = (const int*)d_in[19];
    float* out = (float*)d_out;

    cudaFuncSetAttribute(mma_gemm, cudaFuncAttributeMaxDynamicSharedMemorySize, GSMEM_BYTES);

    float *xln, *proj, *rln, *fr, *fa, *fb, *rst, *y, *hid, *wcat, *wrel, *w1T, *w2T;
    cudaGetSymbolAddress((void**)&xln,  g_xln);
    cudaGetSymbolAddress((void**)&proj, g_proj);
    cudaGetSymbolAddress((void**)&rln,  g_rln);
    cudaGetSymbolAddress((void**)&fr,   g_fr);
    cudaGetSymbolAddress((void**)&fa,   g_fa);
    cudaGetSymbolAddress((void**)&fb,   g_fb);
    cudaGetSymbolAddress((void**)&rst,  g_rst);
    cudaGetSymbolAddress((void**)&y,    g_y);
    cudaGetSymbolAddress((void**)&hid,  g_hid);
    cudaGetSymbolAddress((void**)&wcat, g_wcatT);
    cudaGetSymbolAddress((void**)&wrel, g_wrelT);
    cudaGetSymbolAddress((void**)&w1T,  g_w1T);
    cudaGetSymbolAddress((void**)&w2T,  g_w2T);

    // 0) transpose + tf32-round weights
    dim3 tb(32, 8);
    transpose4_rnd<<<dim3(FF / 32, FF / 32, 4), tb>>>(W_head, W_tail, W_ent, W_rel, wcat, wrel);
    transpose_rnd<<<dim3(FHID / 32, FF / 32), tb>>>(W1, w1T, FF, FHID);
    transpose_rnd<<<dim3(FF / 32, FHID / 32), tb>>>(W2, w2T, FHID, FF);

    // 1) LayerNorms (tf32-rounded outputs; only consumed by GEMMs)
    ln_kernel<<<NN, 256>>>(ent_feat, xln, ln_ent_g, ln_ent_b);
    ln_kernel<<<RR, 256>>>(rel_feat, rln, ln_rel_g, ln_rel_b);

    // 2) Projections: rel + fused head/tail/ent (Nc=768)
    const int mT = (NN + 127) / 128;   // 157
    mma_gemm<<<dim3(FF / 128, 1), 256, GSMEM_BYTES>>>(rln, wrel, fr, RR, FF, FF, nullptr, nullptr, 0);
    mma_gemm<<<dim3(PF / 128, mT), 256, GSMEM_BYTES>>>(xln, wcat, proj, NN, PF, FF, nullptr, nullptr, 0);

    // 3) CSR build (sorted by dst)
    zero_kernel<<<(NN + 255) / 256, 256>>>();
    count_kernel<<<(EE + 255) / 256, 256>>>(dst);
    scan_kernel<<<1, 1024>>>();
    scatter_kernel<<<(EE + 255) / 256, 256>>>(src, dst, rid);

    // 4) edge attention + per-node softmax
    attn_kernel<<<NN / 8, 256>>>(attn);

    // 5) 5 PPR hops (ping-pong), last adds ent_feat residual -> g_rst
    hop_kernel<<<NN / 8, 256>>>(proj + 2 * FF, PF, fa, nullptr);
    hop_kernel<<<NN / 8, 256>>>(fa, FF, fb, nullptr);
    hop_kernel<<<NN / 8, 256>>>(fb, FF, fa, nullptr);
    hop_kernel<<<NN / 8, 256>>>(fa, FF, fb, nullptr);
    hop_kernel<<<NN / 8, 256>>>(fb, FF, rst, ent_feat);

    // 6) FFN with pre-LN and residual
    ln_kernel<<<NN, 256>>>(rst, y, ln_ff_g, ln_ff_b);
    mma_gemm<<<dim3(FHID / 128, mT), 256, GSMEM_BYTES>>>(y, w1T, hid, NN, FHID, FF, b1, nullptr, 1 | 2);
    mma_gemm<<<dim3(FF / 128, mT), 256, GSMEM_BYTES>>>(hid, w2T, out, NN, FF, FHID, b2, rst, 0);
}

// round 7
// speedup vs baseline: 1.5312x; 1.5312x over previous
#include <cuda_runtime.h>
#include <math.h>
#include <stdint.h>

// Problem constants
#define NN 20000
#define EE 320000
#define RR 100
#define FF 256
#define HH 8
#define DD 32
#define FHID 1024
#define PF 768            // packed projection stride (fh|ftl|fen)
#define ALPHA 0.1f
#define SLOPE 0.2f

// ---------------------------------------------------------------------------
__device__ __forceinline__ uint32_t smem_u32(const void* p) {
    uint32_t a;
    asm("{ .reg .u64 t; cvta.to.shared.u64 t, %1; cvt.u32.u64 %0, t; }" : "=r"(a) : "l"(p));
    return a;
}
#define CP_ASYNC16(dst, src) \
    asm volatile("cp.async.cg.shared.global [%0], [%1], 16;" :: "r"(dst), "l"(src) : "memory")
#define CP_COMMIT() asm volatile("cp.async.commit_group;" ::: "memory")
#define CP_WAIT(n)  asm volatile("cp.async.wait_group %0;" :: "n"(n) : "memory")

#define LDSM_X4(r0, r1, r2, r3, addr) \
    asm volatile("ldmatrix.sync.aligned.m8n8.x4.shared.b16 {%0,%1,%2,%3}, [%4];" \
                 : "=r"(r0), "=r"(r1), "=r"(r2), "=r"(r3) : "r"(addr))
#define MMA_TF32(c, a, b) \
    asm volatile("mma.sync.aligned.m16n8k8.row.col.f32.tf32.tf32.f32 " \
                 "{%0,%1,%2,%3},{%4,%5,%6,%7},{%8,%9},{%0,%1,%2,%3};" \
                 : "+f"((c)[0]), "+f"((c)[1]), "+f"((c)[2]), "+f"((c)[3]) \
                 : "r"((a)[0]), "r"((a)[1]), "r"((a)[2]), "r"((a)[3]), \
                   "r"((b)[0]), "r"((b)[1]))

__device__ __forceinline__ float tf32_rnd(float x) {
    uint32_t u = __float_as_uint(x), o;
    asm("cvt.rna.tf32.f32 %0, %1;" : "=r"(o) : "r"(u));
    return __uint_as_float(o);
}

// ------------------------- scratch (device globals) -------------------------
__device__ float g_xln[NN * FF];
__device__ float g_proj[NN * PF];      // [fh | ftl | fen] packed per row
__device__ float g_rln[RR * FF];
__device__ float g_fr [RR * FF];
__device__ int   g_cnt [NN];
__device__ int   g_fill[NN];
__device__ int   g_rowptr[NN + 1];
__device__ int   g_srcs[EE];
__device__ int   g_rids[EE];
__device__ float g_e[EE * HH];
__device__ float g_a[EE * HH];
__device__ float g_fa[NN * FF];
__device__ float g_fb[NN * FF];
__device__ float g_rst[NN * FF];
__device__ float g_y  [NN * FF];
__device__ float g_hid[NN * FHID];
__device__ float g_wcatT[PF * FF];     // K-major [768,256]: Whead|Wtail|Went rows
__device__ float g_wrelT [FF * FF];
__device__ float g_w1T[FHID * FF];
__device__ float g_w2T[FF * FHID];

// ------------------------- LayerNorm (outputs tf32-rounded) -------------------
__global__ void ln_kernel(const float* __restrict__ in, float* __restrict__ out,
                          const float* __restrict__ gam, const float* __restrict__ bet) {
    int row = blockIdx.x;
    int t = threadIdx.x;
    float x = in[row * FF + t];
    float s = x, s2 = x * x;
    #pragma unroll
    for (int o = 16; o; o >>= 1) {
        s  += __shfl_xor_sync(0xffffffffu, s,  o);
        s2 += __shfl_xor_sync(0xffffffffu, s2, o);
    }
    __shared__ float rs[8], rs2[8];
    int w = t >> 5, l = t & 31;
    if (l == 0) { rs[w] = s; rs2[w] = s2; }
    __syncthreads();
    s = 0.f; s2 = 0.f;
    #pragma unroll
    for (int i = 0; i < 8; i++) { s += rs[i]; s2 += rs2[i]; }
    float m = s * (1.0f / FF);
    float var = s2 * (1.0f / FF) - m * m;
    float inv = rsqrtf(var + 1e-5f);
    out[row * FF + t] = tf32_rnd((x - m) * inv * gam[t] + bet[t]);
}

// ------------------------- weight transpose (+tf32 round) --------------------
__global__ void transpose_rnd(const float* __restrict__ B, float* __restrict__ BT,
                              int K, int N) {
    __shared__ float t[32][33];
    int n0 = blockIdx.x * 32, k0 = blockIdx.y * 32;
    int x = threadIdx.x, y = threadIdx.y;
    #pragma unroll
    for (int r = 0; r < 32; r += 8)
        t[y + r][x] = B[(size_t)(k0 + y + r) * N + n0 + x];
    __syncthreads();
    #pragma unroll
    for (int r = 0; r < 32; r += 8)
        BT[(size_t)(n0 + y + r) * K + k0 + x] = tf32_rnd(t[x][y + r]);
}
__global__ void transpose4_rnd(const float* __restrict__ Wh, const float* __restrict__ Wt,
                               const float* __restrict__ We, const float* __restrict__ Wr,
                               float* __restrict__ wcat, float* __restrict__ wrel) {
    __shared__ float t[32][33];
    int z = blockIdx.z;
    const float* B = (z == 0) ? Wh : (z == 1) ? Wt : (z == 2) ? We : Wr;
    float* BT = (z < 3) ? (wcat + (size_t)z * FF * FF) : wrel;
    int n0 = blockIdx.x * 32, k0 = blockIdx.y * 32;
    int x = threadIdx.x, y = threadIdx.y;
    #pragma unroll
    for (int r = 0; r < 32; r += 8)
        t[y + r][x] = B[(size_t)(k0 + y + r) * FF + n0 + x];
    __syncthreads();
    #pragma unroll
    for (int r = 0; r < 32; r += 8)
        BT[(size_t)(n0 + y + r) * FF + k0 + x] = tf32_rnd(t[x][y + r]);
}

// ------------------------- tf32 mma.sync GEMM (R4 config) --------------------
#define GSTAGES 3
#define GSTG 32768
#define GSMEM_BYTES (GSTAGES * GSTG)

__global__ void __launch_bounds__(256, 2)
mma_gemm(const float* __restrict__ A, const float* __restrict__ BT,
         float* __restrict__ C, int M, int Nc, int K,
         const float* __restrict__ bias, const float* __restrict__ res, int mode) {
    extern __shared__ float smemf[];
    const uint32_t sb = smem_u32(smemf);

    const int m0 = blockIdx.y * 128;
    const int n0 = blockIdx.x * 128;
    const int tid = threadIdx.x;
    const int warp = tid >> 5, lane = tid & 31;
    const int wm = warp >> 2, wn = warp & 3;          // 2 x 4 warps

    const int lrow = tid >> 1, lhalf = tid & 1;
    int aRow = m0 + lrow; if (aRow >= M) aRow = M - 1;
    const float* aG = A + (size_t)aRow * K + lhalf * 16;
    const float* bG = BT + (size_t)(n0 + lrow) * K + lhalf * 16;
    const uint32_t sA = sb + (uint32_t)lrow * 128;
    const uint32_t sB = sb + 16384 + (uint32_t)lrow * 128;
    uint32_t swz[4];
    #pragma unroll
    for (int j = 0; j < 4; j++)
        swz[j] = (uint32_t)(((lhalf * 4 + j) ^ (lrow & 7)) << 4);

    const int nCh = K >> 5;

    float c[4][4][4];
    #pragma unroll
    for (int mt = 0; mt < 4; mt++)
        #pragma unroll
        for (int nt = 0; nt < 4; nt++)
            #pragma unroll
            for (int q = 0; q < 4; q++) c[mt][nt][q] = 0.f;

    #pragma unroll
    for (int s = 0; s < 2; s++) {
        const uint32_t off = (uint32_t)s * GSTG;
        const float* ag = aG + s * 32;
        const float* bg = bG + s * 32;
        #pragma unroll
        for (int j = 0; j < 4; j++) CP_ASYNC16(sA + off + swz[j], ag + j * 4);
        #pragma unroll
        for (int j = 0; j < 4; j++) CP_ASYNC16(sB + off + swz[j], bg + j * 4);
        CP_COMMIT();
    }

    const int q8 = lane >> 3, r8 = lane & 7;

    for (int i = 0; i < nCh; i++) {
        __syncthreads();
        if (i + 2 < nCh) {
            const uint32_t off = (uint32_t)((i + 2) % GSTAGES) * GSTG;
            const float* ag = aG + (i + 2) * 32;
            const float* bg = bG + (i + 2) * 32;
            #pragma unroll
            for (int j = 0; j < 4; j++) CP_ASYNC16(sA + off + swz[j], ag + j * 4);
            #pragma unroll
            for (int j = 0; j < 4; j++) CP_ASYNC16(sB + off + swz[j], bg + j * 4);
        }
        CP_COMMIT();
        CP_WAIT(2);
        __syncthreads();

        const uint32_t Ab = sb + (uint32_t)(i % GSTAGES) * GSTG;
        const uint32_t Bb = Ab + 16384;
        #pragma unroll
        for (int ks = 0; ks < 4; ks++) {
            uint32_t a[4][4];
            #pragma unroll
            for (int mt = 0; mt < 4; mt++) {
                const int rl = wm * 64 + mt * 16 + (q8 & 1) * 8 + r8;
                const int kc = ks * 2 + (q8 >> 1);
                const uint32_t ad = Ab + (uint32_t)rl * 128 + (uint32_t)((kc ^ (rl & 7)) << 4);
                LDSM_X4(a[mt][0], a[mt][1], a[mt][2], a[mt][3], ad);
            }
            uint32_t b[4][2];
            #pragma unroll
            for (int ntp = 0; ntp < 2; ntp++) {
                const int nl = wn * 32 + ntp * 16 + (q8 >> 1) * 8 + r8;
                const int kc = ks * 2 + (q8 & 1);
                const uint32_t bd = Bb + (uint32_t)nl * 128 + (uint32_t)((kc ^ (nl & 7)) << 4);
                LDSM_X4(b[ntp * 2][0], b[ntp * 2][1], b[ntp * 2 + 1][0], b[ntp * 2 + 1][1], bd);
            }
            #pragma unroll
            for (int mt = 0; mt < 4; mt++)
                #pragma unroll
                for (int nt = 0; nt < 4; nt++)
                    MMA_TF32(c[mt][nt], a[mt], b[nt]);
        }
    }

    const int g = lane >> 2, t4 = lane & 3;
    #pragma unroll
    for (int mt = 0; mt < 4; mt++) {
        #pragma unroll
        for (int half = 0; half < 2; half++) {
            const int m = m0 + wm * 64 + mt * 16 + g + half * 8;
            if (m < M) {
                float* cRow = C + (size_t)m * Nc + n0 + wn * 32;
                const float* rRow = res ? (res + (size_t)m * Nc + n0 + wn * 32) : nullptr;
                #pragma unroll
                for (int nt = 0; nt < 4; nt++) {
                    const int colb = nt * 8 + 2 * t4;
                    float v0 = c[mt][nt][half * 2 + 0];
                    float v1 = c[mt][nt][half * 2 + 1];
                    if (bias) {
                        const float* bp = bias + n0 + wn * 32 + colb;
                        v0 += bp[0]; v1 += bp[1];
                    }
                    if (mode & 1) { v0 = fmaxf(v0, 0.f); v1 = fmaxf(v1, 0.f); }
                    if (mode & 2) { v0 = tf32_rnd(v0); v1 = tf32_rnd(v1); }
                    if (rRow) { v0 += rRow[colb]; v1 += rRow[colb + 1]; }
                    float2 v; v.x = v0; v.y = v1;
                    *(float2*)(cRow + colb) = v;
                }
            }
        }
    }
}

// ------------------------- CSR build -----------------------------------------
__global__ void count_kernel(const int* __restrict__ dst) {
    int i = blockIdx.x * blockDim.x + threadIdx.x;
    if (i < EE) atomicAdd(&g_cnt[dst[i]], 1);
}
__global__ void scan_kernel() {
    __shared__ int ss[1024];
    int t = threadIdx.x;
    const int CH = (NN + 1023) / 1024;
    int base = t * CH;
    int loc = 0;
    for (int i = 0; i < CH; i++) {
        int idx = base + i;
        if (idx < NN) loc += g_cnt[idx];
    }
    ss[t] = loc;
    __syncthreads();
    for (int off = 1; off < 1024; off <<= 1) {
        int v = (t >= off) ? ss[t - off] : 0;
        __syncthreads();
        ss[t] += v;
        __syncthreads();
    }
    int run = (t == 0) ? 0 : ss[t - 1];
    for (int i = 0; i < CH; i++) {
        int idx = base + i;
        if (idx < NN) { g_rowptr[idx] = run; run += g_cnt[idx]; }
    }
    if (t == 0) g_rowptr[NN] = EE;
}
__global__ void scatter_kernel(const int* __restrict__ src, const int* __restrict__ dst,
                               const int* __restrict__ rid) {
    int i = blockIdx.x * blockDim.x + threadIdx.x;
    if (i < EE) {
        int d = dst[i];
        int pos = g_rowptr[d] + atomicAdd(&g_fill[d], 1);
        g_srcs[pos] = src[i];
        g_rids[pos] = rid[i];
    }
}

// ---------------- edge attention + softmax + first PPR hop -------------------
// one warp per dst node. Score phase lanes: (h = lane>>2, db = (lane&3)*8).
// Softmax lanes: (pi = lane>>3 edge-slot, hs = lane&7). Hop lanes: col = lane*8.
__global__ void attn_hop1_kernel(const float* __restrict__ attn,
                                 float* __restrict__ fout) {
    int w = (blockIdx.x * blockDim.x + threadIdx.x) >> 5;
    int lane = threadIdx.x & 31;
    if (w >= NN) return;
    int node = w;
    const int h = lane >> 2;
    const int db = (lane & 3) * 8;
    const int off = h * DD + db;

    float4 tl0 = *(const float4*)(g_proj + (size_t)node * PF + FF + off);
    float4 tl1 = *(const float4*)(g_proj + (size_t)node * PF + FF + off + 4);
    float4 av0 = *(const float4*)(attn + off);
    float4 av1 = *(const float4*)(attn + off + 4);

    int beg = g_rowptr[node], end = g_rowptr[node + 1];
    float scale = logf((float)(end - beg)) * (1.0f / DD);

    float mloc = -1e30f;                 // running max for head h (all 4 lanes)
    for (int p = beg; p < end; p++) {
        int s = g_srcs[p], r = g_rids[p];
        const float* fhp = g_proj + (size_t)s * PF + off;
        const float* frp = g_fr + (size_t)r * FF + off;
        float4 fh0 = *(const float4*)(fhp);
        float4 fh1 = *(const float4*)(fhp + 4);
        float4 fr0 = *(const float4*)(frp);
        float4 fr1 = *(const float4*)(frp + 4);
        float v = 0.f;
        {
            float x;
            x = fh0.x * tl0.x * fr0.x; x = (x > 0.f) ? x : SLOPE * x; v += x * av0.x;
            x = fh0.y * tl0.y * fr0.y; x = (x > 0.f) ? x : SLOPE * x; v += x * av0.y;
            x = fh0.z * tl0.z * fr0.z; x = (x > 0.f) ? x : SLOPE * x; v += x * av0.z;
            x = fh0.w * tl0.w * fr0.w; x = (x > 0.f) ? x : SLOPE * x; v += x * av0.w;
            x = fh1.x * tl1.x * fr1.x; x = (x > 0.f) ? x : SLOPE * x; v += x * av1.x;
            x = fh1.y * tl1.y * fr1.y; x = (x > 0.f) ? x : SLOPE * x; v += x * av1.y;
            x = fh1.z * tl1.z * fr1.z; x = (x > 0.f) ? x : SLOPE * x; v += x * av1.z;
            x = fh1.w * tl1.w * fr1.w; x = (x > 0.f) ? x : SLOPE * x; v += x * av1.w;
        }
        v += __shfl_xor_sync(0xffffffffu, v, 1);
        v += __shfl_xor_sync(0xffffffffu, v, 2);
        v *= scale;
        mloc = fmaxf(mloc, v);
        if ((lane & 3) == 0) g_e[p * HH + h] = v;
    }
    __syncwarp();

    // softmax phase: lane -> (pi = lane>>3, hs = lane&7); max from group 4*hs
    const int hs = lane & 7, pi = lane >> 3;
    float m = __shfl_sync(0xffffffffu, mloc, hs * 4);
    float ssum = 0.f;
    for (int p = beg + pi; p < end; p += 4) ssum += expf(g_e[p * HH + hs] - m);
    ssum += __shfl_xor_sync(0xffffffffu, ssum, 8);
    ssum += __shfl_xor_sync(0xffffffffu, ssum, 16);
    float inv = 1.0f / ssum;
    for (int p = beg + pi; p < end; p += 4)
        g_a[p * HH + hs] = expf(g_e[p * HH + hs] - m) * inv;
    __syncwarp();

    // first hop: lane owns cols lane*8 .. lane*8+7 (head lane>>2)
    const int col = lane * 8;
    float4 a0 = make_float4(0.f, 0.f, 0.f, 0.f);
    float4 a1 = make_float4(0.f, 0.f, 0.f, 0.f);
    for (int p = beg; p < end; p++) {
        int s = g_srcs[p];
        float av = g_a[p * HH + h];
        const float* frow = g_proj + (size_t)s * PF + 2 * FF + col;
        float4 f0 = *(const float4*)(frow);
        float4 f1 = *(const float4*)(frow + 4);
        a0.x += av * f0.x; a0.y += av * f0.y; a0.z += av * f0.z; a0.w += av * f0.w;
        a1.x += av * f1.x; a1.y += av * f1.y; a1.z += av * f1.z; a1.w += av * f1.w;
    }
    const float* f0p = g_proj + (size_t)node * PF + 2 * FF + col;
    float4 e0 = *(const float4*)(f0p);
    float4 e1 = *(const float4*)(f0p + 4);
    float4 o0, o1;
    o0.x = (1.0f - ALPHA) * a0.x + ALPHA * e0.x;
    o0.y = (1.0f - ALPHA) * a0.y + ALPHA * e0.y;
    o0.z = (1.0f - ALPHA) * a0.z + ALPHA * e0.z;
    o0.w = (1.0f - ALPHA) * a0.w + ALPHA * e0.w;
    o1.x = (1.0f - ALPHA) * a1.x + ALPHA * e1.x;
    o1.y = (1.0f - ALPHA) * a1.y + ALPHA * e1.y;
    o1.z = (1.0f - ALPHA) * a1.z + ALPHA * e1.z;
    o1.w = (1.0f - ALPHA) * a1.w + ALPHA * e1.w;
    float* op = fout + (size_t)node * FF + col;
    *(float4*)(op) = o0;
    *(float4*)(op + 4) = o1;
}

// ------------------------- diffusion hop --------------------------------------
__global__ void hop_kernel(const float* __restrict__ fin, int fstride,
                           float* __restrict__ fout, const float* __restrict__ ent) {
    int w = (blockIdx.x * blockDim.x + threadIdx.x) >> 5;
    int lane = threadIdx.x & 31;
    if (w >= NN) return;
    int node = w;
    const int col = lane * 8;
    const int h = lane >> 2;
    int beg = g_rowptr[node], end = g_rowptr[node + 1];

    float4 a0 = make_float4(0.f, 0.f, 0.f, 0.f);
    float4 a1 = make_float4(0.f, 0.f, 0.f, 0.f);
    for (int p = beg; p < end; p++) {
        int s = g_srcs[p];
        float av = g_a[p * HH + h];
        const float* frow = fin + (size_t)s * fstride + col;
        float4 f0 = *(const float4*)(frow);
        float4 f1 = *(const float4*)(frow + 4);
        a0.x += av * f0.x; a0.y += av * f0.y; a0.z += av * f0.z; a0.w += av * f0.w;
        a1.x += av * f1.x; a1.y += av * f1.y; a1.z += av * f1.z; a1.w += av * f1.w;
    }
    const float* f0p = g_proj + (size_t)node * PF + 2 * FF + col;
    float4 e0 = *(const float4*)(f0p);
    float4 e1 = *(const float4*)(f0p + 4);
    float4 o0, o1;
    o0.x = (1.0f - ALPHA) * a0.x + ALPHA * e0.x;
    o0.y = (1.0f - ALPHA) * a0.y + ALPHA * e0.y;
    o0.z = (1.0f - ALPHA) * a0.z + ALPHA * e0.z;
    o0.w = (1.0f - ALPHA) * a0.w + ALPHA * e0.w;
    o1.x = (1.0f - ALPHA) * a1.x + ALPHA * e1.x;
    o1.y = (1.0f - ALPHA) * a1.y + ALPHA * e1.y;
    o1.z = (1.0f - ALPHA) * a1.z + ALPHA * e1.z;
    o1.w = (1.0f - ALPHA) * a1.w + ALPHA * e1.w;
    if (ent) {
        const float* ep = ent + (size_t)node * FF + col;
        float4 n0 = *(const float4*)(ep);
        float4 n1 = *(const float4*)(ep + 4);
        o0.x += n0.x; o0.y += n0.y; o0.z += n0.z; o0.w += n0.w;
        o1.x += n1.x; o1.y += n1.y; o1.z += n1.z; o1.w += n1.w;
    }
    float* op = fout + (size_t)node * FF + col;
    *(float4*)(op) = o0;
    *(float4*)(op + 4) = o1;
}

// ------------------------- launcher -------------------------------------------
extern "C" void kernel_launch(void* const* d_in, const int* in_sizes, int n_in,
                              void* d_out, int out_size) {
    const float* ent_feat = (const float*)d_in[0];
    const float* rel_feat = (const float*)d_in[1];
    const float* W_head   = (const float*)d_in[2];
    const float* W_tail   = (const float*)d_in[3];
    const float* W_ent    = (const float*)d_in[4];
    const float* W_rel    = (const float*)d_in[5];
    const float* attn     = (const float*)d_in[6];
    const float* ln_ent_g = (const float*)d_in[7];
    const float* ln_ent_b = (const float*)d_in[8];
    const float* ln_rel_g = (const float*)d_in[9];
    const float* ln_rel_b = (const float*)d_in[10];
    const float* ln_ff_g  = (const float*)d_in[11];
    const float* ln_ff_b  = (const float*)d_in[12];
    const float* W1       = (const float*)d_in[13];
    const float* b1       = (const float*)d_in[14];
    const float* W2       = (const float*)d_in[15];
    const float* b2       = (const float*)d_in[16];
    const int*   src      = (const int*)d_in[17];
    const int*   dst      = (const int*)d_in[18];
    const int*   rid      = (const int*)d_in[19];
    float* out = (float*)d_out;

    cudaFuncSetAttribute(mma_gemm, cudaFuncAttributeMaxDynamicSharedMemorySize, GSMEM_BYTES);

    float *xln, *proj, *rln, *fr, *fa, *fb, *rst, *y, *hid, *wcat, *wrel, *w1T, *w2T;
    int *cnt, *fill;
    cudaGetSymbolAddress((void**)&xln,  g_xln);
    cudaGetSymbolAddress((void**)&proj, g_proj);
    cudaGetSymbolAddress((void**)&rln,  g_rln);
    cudaGetSymbolAddress((void**)&fr,   g_fr);
    cudaGetSymbolAddress((void**)&fa,   g_fa);
    cudaGetSymbolAddress((void**)&fb,   g_fb);
    cudaGetSymbolAddress((void**)&rst,  g_rst);
    cudaGetSymbolAddress((void**)&y,    g_y);
    cudaGetSymbolAddress((void**)&hid,  g_hid);
    cudaGetSymbolAddress((void**)&wcat, g_wcatT);
    cudaGetSymbolAddress((void**)&wrel, g_wrelT);
    cudaGetSymbolAddress((void**)&w1T,  g_w1T);
    cudaGetSymbolAddress((void**)&w2T,  g_w2T);
    cudaGetSymbolAddress((void**)&cnt,  g_cnt);
    cudaGetSymbolAddress((void**)&fill, g_fill);

    // 0) transpose + tf32-round weights; zero CSR counters (memset, capturable)
    cudaMemsetAsync(cnt, 0, NN * sizeof(int));
    cudaMemsetAsync(fill, 0, NN * sizeof(int));
    dim3 tb(32, 8);
    transpose4_rnd<<<dim3(FF / 32, FF / 32, 4), tb>>>(W_head, W_tail, W_ent, W_rel, wcat, wrel);
    transpose_rnd<<<dim3(FHID / 32, FF / 32), tb>>>(W1, w1T, FF, FHID);
    transpose_rnd<<<dim3(FF / 32, FHID / 32), tb>>>(W2, w2T, FHID, FF);

    // 1) LayerNorms (tf32-rounded outputs; only consumed by GEMMs)
    ln_kernel<<<NN, 256>>>(ent_feat, xln, ln_ent_g, ln_ent_b);
    ln_kernel<<<RR, 256>>>(rel_feat, rln, ln_rel_g, ln_rel_b);

    // 2) Projections: rel + fused head/tail/ent (Nc=768)
    const int mT = (NN + 127) / 128;   // 157
    mma_gemm<<<dim3(FF / 128, 1), 256, GSMEM_BYTES>>>(rln, wrel, fr, RR, FF, FF, nullptr, nullptr, 0);
    mma_gemm<<<dim3(PF / 128, mT), 256, GSMEM_BYTES>>>(xln, wcat, proj, NN, PF, FF, nullptr, nullptr, 0);

    // 3) CSR build (sorted by dst)
    count_kernel<<<(EE + 255) / 256, 256>>>(dst);
    scan_kernel<<<1, 1024>>>();
    scatter_kernel<<<(EE + 255) / 256, 256>>>(src, dst, rid);

    // 4) edge attention + softmax + hop 1 (fused) -> fa
    attn_hop1_kernel<<<NN / 8, 256>>>(attn, fa);

    // 5) remaining 4 PPR hops (ping-pong), last adds ent_feat residual -> g_rst
    hop_kernel<<<NN / 8, 256>>>(fa, FF, fb, nullptr);
    hop_kernel<<<NN / 8, 256>>>(fb, FF, fa, nullptr);
    hop_kernel<<<NN / 8, 256>>>(fa, FF, fb, nullptr);
    hop_kernel<<<NN / 8, 256>>>(fb, FF, rst, ent_feat);

    // 6) FFN with pre-LN and residual
    ln_kernel<<<NN, 256>>>(rst, y, ln_ff_g, ln_ff_b);
    mma_gemm<<<dim3(FHID / 128, mT), 256, GSMEM_BYTES>>>(y, w1T, hid, NN, FHID, FF, b1, nullptr, 1 | 2);
    mma_gemm<<<dim3(FF / 128, mT), 256, GSMEM_BYTES>>>(hid, w2T, out, NN, FF, FHID, b2, rst, 0);
}

// round 8
// speedup vs baseline: 1.9570x; 1.2781x over previous
#include <cuda_runtime.h>
#include <cuda_fp16.h>
#include <math.h>
#include <stdint.h>

// Problem constants
#define NN 20000
#define EE 320000
#define RR 100
#define FF 256
#define HH 8
#define DD 32
#define FHID 1024
#define PF 768            // packed projection stride (fh|ftl|fen)
#define ALPHA 0.1f
#define SLOPE 0.2f

// ---------------------------------------------------------------------------
__device__ __forceinline__ uint32_t smem_u32(const void* p) {
    uint32_t a;
    asm("{ .reg .u64 t; cvta.to.shared.u64 t, %1; cvt.u32.u64 %0, t; }" : "=r"(a) : "l"(p));
    return a;
}
#define CP_ASYNC16(dst, src) \
    asm volatile("cp.async.cg.shared.global [%0], [%1], 16;" :: "r"(dst), "l"(src) : "memory")
#define CP_COMMIT() asm volatile("cp.async.commit_group;" ::: "memory")
#define CP_WAIT(n)  asm volatile("cp.async.wait_group %0;" :: "n"(n) : "memory")

#define LDSM_X4(r0, r1, r2, r3, addr) \
    asm volatile("ldmatrix.sync.aligned.m8n8.x4.shared.b16 {%0,%1,%2,%3}, [%4];" \
                 : "=r"(r0), "=r"(r1), "=r"(r2), "=r"(r3) : "r"(addr))
#define MMA_F16(c, a, b) \
    asm volatile("mma.sync.aligned.m16n8k16.row.col.f32.f16.f16.f32 " \
                 "{%0,%1,%2,%3},{%4,%5,%6,%7},{%8,%9},{%0,%1,%2,%3};" \
                 : "+f"((c)[0]), "+f"((c)[1]), "+f"((c)[2]), "+f"((c)[3]) \
                 : "r"((a)[0]), "r"((a)[1]), "r"((a)[2]), "r"((a)[3]), \
                   "r"((b)[0]), "r"((b)[1]))

// ------------------------- scratch (device globals) -------------------------
__device__ __half g_xln[NN * FF];
__device__ float  g_proj[NN * PF];      // [fh | ftl | fen] packed per row (fp32)
__device__ __half g_rln[RR * FF];
__device__ float  g_fr [RR * FF];
__device__ int    g_cnt [NN];
__device__ int    g_fill[NN];
__device__ int    g_rowptr[NN + 1];
__device__ int    g_srcs[EE];
__device__ int    g_rids[EE];
__device__ float  g_e[EE * HH];
__device__ float  g_a[EE * HH];
__device__ float  g_fa[NN * FF];
__device__ float  g_fb[NN * FF];
__device__ float  g_rst[NN * FF];
__device__ __half g_y  [NN * FF];
__device__ __half g_hid[NN * FHID];
__device__ __half g_wcatT[PF * FF];     // K-major [768,256]: Whead|Wtail|Went
__device__ __half g_wrelT [FF * FF];
__device__ __half g_w1T[FHID * FF];
__device__ __half g_w2T[FF * FHID];

// ------------------------- LayerNorm (outputs fp16) --------------------------
__global__ void ln_kernel(const float* __restrict__ in, __half* __restrict__ out,
                          const float* __restrict__ gam, const float* __restrict__ bet) {
    int row = blockIdx.x;
    int t = threadIdx.x;
    float x = in[row * FF + t];
    float s = x, s2 = x * x;
    #pragma unroll
    for (int o = 16; o; o >>= 1) {
        s  += __shfl_xor_sync(0xffffffffu, s,  o);
        s2 += __shfl_xor_sync(0xffffffffu, s2, o);
    }
    __shared__ float rs[8], rs2[8];
    int w = t >> 5, l = t & 31;
    if (l == 0) { rs[w] = s; rs2[w] = s2; }
    __syncthreads();
    s = 0.f; s2 = 0.f;
    #pragma unroll
    for (int i = 0; i < 8; i++) { s += rs[i]; s2 += rs2[i]; }
    float m = s * (1.0f / FF);
    float var = s2 * (1.0f / FF) - m * m;
    float inv = rsqrtf(var + 1e-5f);
    out[row * FF + t] = __float2half_rn((x - m) * inv * gam[t] + bet[t]);
}

// ------------------------- weight transpose (fp32 -> fp16 K-major) -----------
__global__ void transpose_rnd(const float* __restrict__ B, __half* __restrict__ BT,
                              int K, int N) {
    __shared__ float t[32][33];
    int n0 = blockIdx.x * 32, k0 = blockIdx.y * 32;
    int x = threadIdx.x, y = threadIdx.y;
    #pragma unroll
    for (int r = 0; r < 32; r += 8)
        t[y + r][x] = B[(size_t)(k0 + y + r) * N + n0 + x];
    __syncthreads();
    #pragma unroll
    for (int r = 0; r < 32; r += 8)
        BT[(size_t)(n0 + y + r) * K + k0 + x] = __float2half_rn(t[x][y + r]);
}
__global__ void transpose4_rnd(const float* __restrict__ Wh, const float* __restrict__ Wt,
                               const float* __restrict__ We, const float* __restrict__ Wr,
                               __half* __restrict__ wcat, __half* __restrict__ wrel) {
    __shared__ float t[32][33];
    int z = blockIdx.z;
    const float* B = (z == 0) ? Wh : (z == 1) ? Wt : (z == 2) ? We : Wr;
    __half* BT = (z < 3) ? (wcat + (size_t)z * FF * FF) : wrel;
    int n0 = blockIdx.x * 32, k0 = blockIdx.y * 32;
    int x = threadIdx.x, y = threadIdx.y;
    #pragma unroll
    for (int r = 0; r < 32; r += 8)
        t[y + r][x] = B[(size_t)(k0 + y + r) * FF + n0 + x];
    __syncthreads();
    #pragma unroll
    for (int r = 0; r < 32; r += 8)
        BT[(size_t)(n0 + y + r) * FF + k0 + x] = __float2half_rn(t[x][y + r]);
}

// ------------------------- fp16 mma.sync GEMM --------------------------------
// C[M,Nc] = A[M,K] @ BT[Nc,K]^T. A,BT fp16; accum fp32.
// mode&1: relu. mode&2: store fp16 (C is __half*), else fp32 (C is float*).
// bias fp32 (optional), res fp32 (optional, fp32 path only).
// 128x128 block tile, BK=64 (128B fp16 rows), 3-stage cp.async, 8 warps (2x4).
#define GSTAGES 3
#define GSTG 32768
#define GSMEM_BYTES (GSTAGES * GSTG)

__global__ void __launch_bounds__(256, 2)
mma_gemm(const __half* __restrict__ A, const __half* __restrict__ BT,
         void* __restrict__ Cv, int M, int Nc, int K,
         const float* __restrict__ bias, const float* __restrict__ res, int mode) {
    extern __shared__ float smemf[];
    const uint32_t sb = smem_u32(smemf);

    const int m0 = blockIdx.y * 128;
    const int n0 = blockIdx.x * 128;
    const int tid = threadIdx.x;
    const int warp = tid >> 5, lane = tid & 31;
    const int wm = warp >> 2, wn = warp & 3;          // 2 x 4 warps, 64x32 tiles

    // loaders: each thread owns half a 128B row (A rows 128, B rows 128)
    const int lrow = tid >> 1, lhalf = tid & 1;
    int aRow = m0 + lrow; if (aRow >= M) aRow = M - 1;
    const __half* aG = A + (size_t)aRow * K + lhalf * 32;
    const __half* bG = BT + (size_t)(n0 + lrow) * K + lhalf * 32;
    const uint32_t sA = sb + (uint32_t)lrow * 128;
    const uint32_t sB = sb + 16384 + (uint32_t)lrow * 128;
    uint32_t swz[4];
    #pragma unroll
    for (int j = 0; j < 4; j++)
        swz[j] = (uint32_t)(((lhalf * 4 + j) ^ (lrow & 7)) << 4);

    const int nCh = K >> 6;   // K / 64

    float c[4][4][4];
    #pragma unroll
    for (int mt = 0; mt < 4; mt++)
        #pragma unroll
        for (int nt = 0; nt < 4; nt++)
            #pragma unroll
            for (int q = 0; q < 4; q++) c[mt][nt][q] = 0.f;

    #pragma unroll
    for (int s = 0; s < 2; s++) {
        const uint32_t off = (uint32_t)s * GSTG;
        const __half* ag = aG + s * 64;
        const __half* bg = bG + s * 64;
        #pragma unroll
        for (int j = 0; j < 4; j++) CP_ASYNC16(sA + off + swz[j], ag + j * 8);
        #pragma unroll
        for (int j = 0; j < 4; j++) CP_ASYNC16(sB + off + swz[j], bg + j * 8);
        CP_COMMIT();
    }

    const int q8 = lane >> 3, r8 = lane & 7;

    for (int i = 0; i < nCh; i++) {
        __syncthreads();
        if (i + 2 < nCh) {
            const uint32_t off = (uint32_t)((i + 2) % GSTAGES) * GSTG;
            const __half* ag = aG + (i + 2) * 64;
            const __half* bg = bG + (i + 2) * 64;
            #pragma unroll
            for (int j = 0; j < 4; j++) CP_ASYNC16(sA + off + swz[j], ag + j * 8);
            #pragma unroll
            for (int j = 0; j < 4; j++) CP_ASYNC16(sB + off + swz[j], bg + j * 8);
        }
        CP_COMMIT();
        CP_WAIT(2);
        __syncthreads();

        const uint32_t Ab = sb + (uint32_t)(i % GSTAGES) * GSTG;
        const uint32_t Bb = Ab + 16384;
        #pragma unroll
        for (int ks = 0; ks < 4; ks++) {     // 4 x k16 per 64-K chunk
            uint32_t a[4][4];
            #pragma unroll
            for (int mt = 0; mt < 4; mt++) {
                const int rl = wm * 64 + mt * 16 + (q8 & 1) * 8 + r8;
                const int kc = ks * 2 + (q8 >> 1);
                const uint32_t ad = Ab + (uint32_t)rl * 128 + (uint32_t)((kc ^ (rl & 7)) << 4);
                LDSM_X4(a[mt][0], a[mt][1], a[mt][2], a[mt][3], ad);
            }
            uint32_t b[4][2];
            #pragma unroll
            for (int p = 0; p < 2; p++) {
                const int nl = wn * 32 + (p * 2 + (q8 >> 1)) * 8 + r8;
                const int kc = ks * 2 + (q8 & 1);
                const uint32_t bd = Bb + (uint32_t)nl * 128 + (uint32_t)((kc ^ (nl & 7)) << 4);
                LDSM_X4(b[p * 2][0], b[p * 2][1], b[p * 2 + 1][0], b[p * 2 + 1][1], bd);
            }
            #pragma unroll
            for (int mt = 0; mt < 4; mt++)
                #pragma unroll
                for (int nt = 0; nt < 4; nt++)
                    MMA_F16(c[mt][nt], a[mt], b[nt]);
        }
    }

    // ---- epilogue ----
    const int g = lane >> 2, t4 = lane & 3;
    #pragma unroll
    for (int mt = 0; mt < 4; mt++) {
        #pragma unroll
        for (int half = 0; half < 2; half++) {
            const int m = m0 + wm * 64 + mt * 16 + g + half * 8;
            if (m < M) {
                #pragma unroll
                for (int nt = 0; nt < 4; nt++) {
                    const int colb = nt * 8 + 2 * t4;
                    const int col = n0 + wn * 32 + colb;
                    float v0 = c[mt][nt][half * 2 + 0];
                    float v1 = c[mt][nt][half * 2 + 1];
                    if (bias) { v0 += bias[col]; v1 += bias[col + 1]; }
                    if (mode & 1) { v0 = fmaxf(v0, 0.f); v1 = fmaxf(v1, 0.f); }
                    if (mode & 2) {
                        __half2 hv = __floats2half2_rn(v0, v1);
                        *(__half2*)((__half*)Cv + (size_t)m * Nc + col) = hv;
                    } else {
                        if (res) {
                            const float* rp = res + (size_t)m * Nc + col;
                            v0 += rp[0]; v1 += rp[1];
                        }
                        float2 v; v.x = v0; v.y = v1;
                        *(float2*)((float*)Cv + (size_t)m * Nc + col) = v;
                    }
                }
            }
        }
    }
}

// ------------------------- CSR build -----------------------------------------
__global__ void count_kernel(const int* __restrict__ dst) {
    int i = blockIdx.x * blockDim.x + threadIdx.x;
    if (i < EE) atomicAdd(&g_cnt[dst[i]], 1);
}
__global__ void scan_kernel() {
    __shared__ int ss[1024];
    int t = threadIdx.x;
    const int CH = (NN + 1023) / 1024;
    int base = t * CH;
    int loc = 0;
    for (int i = 0; i < CH; i++) {
        int idx = base + i;
        if (idx < NN) loc += g_cnt[idx];
    }
    ss[t] = loc;
    __syncthreads();
    for (int off = 1; off < 1024; off <<= 1) {
        int v = (t >= off) ? ss[t - off] : 0;
        __syncthreads();
        ss[t] += v;
        __syncthreads();
    }
    int run = (t == 0) ? 0 : ss[t - 1];
    for (int i = 0; i < CH; i++) {
        int idx = base + i;
        if (idx < NN) { g_rowptr[idx] = run; run += g_cnt[idx]; }
    }
    if (t == 0) g_rowptr[NN] = EE;
}
__global__ void scatter_kernel(const int* __restrict__ src, const int* __restrict__ dst,
                               const int* __restrict__ rid) {
    int i = blockIdx.x * blockDim.x + threadIdx.x;
    if (i < EE) {
        int d = dst[i];
        int pos = g_rowptr[d] + atomicAdd(&g_fill[d], 1);
        g_srcs[pos] = src[i];
        g_rids[pos] = rid[i];
    }
}

// ---------------- edge attention + softmax + first PPR hop -------------------
__global__ void attn_hop1_kernel(const float* __restrict__ attn,
                                 float* __restrict__ fout) {
    int w = (blockIdx.x * blockDim.x + threadIdx.x) >> 5;
    int lane = threadIdx.x & 31;
    if (w >= NN) return;
    int node = w;
    const int h = lane >> 2;
    const int db = (lane & 3) * 8;
    const int off = h * DD + db;

    float4 tl0 = *(const float4*)(g_proj + (size_t)node * PF + FF + off);
    float4 tl1 = *(const float4*)(g_proj + (size_t)node * PF + FF + off + 4);
    float4 av0 = *(const float4*)(attn + off);
    float4 av1 = *(const float4*)(attn + off + 4);

    int beg = g_rowptr[node], end = g_rowptr[node + 1];
    float scale = logf((float)(end - beg)) * (1.0f / DD);

    float mloc = -1e30f;
    for (int p = beg; p < end; p++) {
        int s = g_srcs[p], r = g_rids[p];
        const float* fhp = g_proj + (size_t)s * PF + off;
        const float* frp = g_fr + (size_t)r * FF + off;
        float4 fh0 = *(const float4*)(fhp);
        float4 fh1 = *(const float4*)(fhp + 4);
        float4 fr0 = *(const float4*)(frp);
        float4 fr1 = *(const float4*)(frp + 4);
        float v = 0.f;
        {
            float x;
            x = fh0.x * tl0.x * fr0.x; x = (x > 0.f) ? x : SLOPE * x; v += x * av0.x;
            x = fh0.y * tl0.y * fr0.y; x = (x > 0.f) ? x : SLOPE * x; v += x * av0.y;
            x = fh0.z * tl0.z * fr0.z; x = (x > 0.f) ? x : SLOPE * x; v += x * av0.z;
            x = fh0.w * tl0.w * fr0.w; x = (x > 0.f) ? x : SLOPE * x; v += x * av0.w;
            x = fh1.x * tl1.x * fr1.x; x = (x > 0.f) ? x : SLOPE * x; v += x * av1.x;
            x = fh1.y * tl1.y * fr1.y; x = (x > 0.f) ? x : SLOPE * x; v += x * av1.y;
            x = fh1.z * tl1.z * fr1.z; x = (x > 0.f) ? x : SLOPE * x; v += x * av1.z;
            x = fh1.w * tl1.w * fr1.w; x = (x > 0.f) ? x : SLOPE * x; v += x * av1.w;
        }
        v += __shfl_xor_sync(0xffffffffu, v, 1);
        v += __shfl_xor_sync(0xffffffffu, v, 2);
        v *= scale;
        mloc = fmaxf(mloc, v);
        if ((lane & 3) == 0) g_e[p * HH + h] = v;
    }
    __syncwarp();

    const int hs = lane & 7, pi = lane >> 3;
    float m = __shfl_sync(0xffffffffu, mloc, hs * 4);
    float ssum = 0.f;
    for (int p = beg + pi; p < end; p += 4) ssum += expf(g_e[p * HH + hs] - m);
    ssum += __shfl_xor_sync(0xffffffffu, ssum, 8);
    ssum += __shfl_xor_sync(0xffffffffu, ssum, 16);
    float inv = 1.0f / ssum;
    for (int p = beg + pi; p < end; p += 4)
        g_a[p * HH + hs] = expf(g_e[p * HH + hs] - m) * inv;
    __syncwarp();

    const int col = lane * 8;
    float4 a0 = make_float4(0.f, 0.f, 0.f, 0.f);
    float4 a1 = make_float4(0.f, 0.f, 0.f, 0.f);
    for (int p = beg; p < end; p++) {
        int s = g_srcs[p];
        float av = g_a[p * HH + h];
        const float* frow = g_proj + (size_t)s * PF + 2 * FF + col;
        float4 f0 = *(const float4*)(frow);
        float4 f1 = *(const float4*)(frow + 4);
        a0.x += av * f0.x; a0.y += av * f0.y; a0.z += av * f0.z; a0.w += av * f0.w;
        a1.x += av * f1.x; a1.y += av * f1.y; a1.z += av * f1.z; a1.w += av * f1.w;
    }
    const float* f0p = g_proj + (size_t)node * PF + 2 * FF + col;
    float4 e0 = *(const float4*)(f0p);
    float4 e1 = *(const float4*)(f0p + 4);
    float4 o0, o1;
    o0.x = (1.0f - ALPHA) * a0.x + ALPHA * e0.x;
    o0.y = (1.0f - ALPHA) * a0.y + ALPHA * e0.y;
    o0.z = (1.0f - ALPHA) * a0.z + ALPHA * e0.z;
    o0.w = (1.0f - ALPHA) * a0.w + ALPHA * e0.w;
    o1.x = (1.0f - ALPHA) * a1.x + ALPHA * e1.x;
    o1.y = (1.0f - ALPHA) * a1.y + ALPHA * e1.y;
    o1.z = (1.0f - ALPHA) * a1.z + ALPHA * e1.z;
    o1.w = (1.0f - ALPHA) * a1.w + ALPHA * e1.w;
    float* op = fout + (size_t)node * FF + col;
    *(float4*)(op) = o0;
    *(float4*)(op + 4) = o1;
}

// ------------------------- diffusion hop --------------------------------------
__global__ void hop_kernel(const float* __restrict__ fin, int fstride,
                           float* __restrict__ fout, const float* __restrict__ ent) {
    int w = (blockIdx.x * blockDim.x + threadIdx.x) >> 5;
    int lane = threadIdx.x & 31;
    if (w >= NN) return;
    int node = w;
    const int col = lane * 8;
    const int h = lane >> 2;
    int beg = g_rowptr[node], end = g_rowptr[node + 1];

    float4 a0 = make_float4(0.f, 0.f, 0.f, 0.f);
    float4 a1 = make_float4(0.f, 0.f, 0.f, 0.f);
    for (int p = beg; p < end; p++) {
        int s = g_srcs[p];
        float av = g_a[p * HH + h];
        const float* frow = fin + (size_t)s * fstride + col;
        float4 f0 = *(const float4*)(frow);
        float4 f1 = *(const float4*)(frow + 4);
        a0.x += av * f0.x; a0.y += av * f0.y; a0.z += av * f0.z; a0.w += av * f0.w;
        a1.x += av * f1.x; a1.y += av * f1.y; a1.z += av * f1.z; a1.w += av * f1.w;
    }
    const float* f0p = g_proj + (size_t)node * PF + 2 * FF + col;
    float4 e0 = *(const float4*)(f0p);
    float4 e1 = *(const float4*)(f0p + 4);
    float4 o0, o1;
    o0.x = (1.0f - ALPHA) * a0.x + ALPHA * e0.x;
    o0.y = (1.0f - ALPHA) * a0.y + ALPHA * e0.y;
    o0.z = (1.0f - ALPHA) * a0.z + ALPHA * e0.z;
    o0.w = (1.0f - ALPHA) * a0.w + ALPHA * e0.w;
    o1.x = (1.0f - ALPHA) * a1.x + ALPHA * e1.x;
    o1.y = (1.0f - ALPHA) * a1.y + ALPHA * e1.y;
    o1.z = (1.0f - ALPHA) * a1.z + ALPHA * e1.z;
    o1.w = (1.0f - ALPHA) * a1.w + ALPHA * e1.w;
    if (ent) {
        const float* ep = ent + (size_t)node * FF + col;
        float4 n0 = *(const float4*)(ep);
        float4 n1 = *(const float4*)(ep + 4);
        o0.x += n0.x; o0.y += n0.y; o0.z += n0.z; o0.w += n0.w;
        o1.x += n1.x; o1.y += n1.y; o1.z += n1.z; o1.w += n1.w;
    }
    float* op = fout + (size_t)node * FF + col;
    *(float4*)(op) = o0;
    *(float4*)(op + 4) = o1;
}

// ------------------------- launcher -------------------------------------------
extern "C" void kernel_launch(void* const* d_in, const int* in_sizes, int n_in,
                              void* d_out, int out_size) {
    const float* ent_feat = (const float*)d_in[0];
    const float* rel_feat = (const float*)d_in[1];
    const float* W_head   = (const float*)d_in[2];
    const float* W_tail   = (const float*)d_in[3];
    const float* W_ent    = (const float*)d_in[4];
    const float* W_rel    = (const float*)d_in[5];
    const float* attn     = (const float*)d_in[6];
    const float* ln_ent_g = (const float*)d_in[7];
    const float* ln_ent_b = (const float*)d_in[8];
    const float* ln_rel_g = (const float*)d_in[9];
    const float* ln_rel_b = (const float*)d_in[10];
    const float* ln_ff_g  = (const float*)d_in[11];
    const float* ln_ff_b  = (const float*)d_in[12];
    const float* W1       = (const float*)d_in[13];
    const float* b1       = (const float*)d_in[14];
    const float* W2       = (const float*)d_in[15];
    const float* b2       = (const float*)d_in[16];
    const int*   src      = (const int*)d_in[17];
    const int*   dst      = (const int*)d_in[18];
    const int*   rid      = (const int*)d_in[19];
    float* out = (float*)d_out;

    cudaFuncSetAttribute(mma_gemm, cudaFuncAttributeMaxDynamicSharedMemorySize, GSMEM_BYTES);

    float *proj, *fr, *fa, *fb, *rst;
    __half *xln, *rln, *y, *hid, *wcat, *wrel, *w1T, *w2T;
    int *cnt, *fill;
    cudaGetSymbolAddress((void**)&xln,  g_xln);
    cudaGetSymbolAddress((void**)&proj, g_proj);
    cudaGetSymbolAddress((void**)&rln,  g_rln);
    cudaGetSymbolAddress((void**)&fr,   g_fr);
    cudaGetSymbolAddress((void**)&fa,   g_fa);
    cudaGetSymbolAddress((void**)&fb,   g_fb);
    cudaGetSymbolAddress((void**)&rst,  g_rst);
    cudaGetSymbolAddress((void**)&y,    g_y);
    cudaGetSymbolAddress((void**)&hid,  g_hid);
    cudaGetSymbolAddress((void**)&wcat, g_wcatT);
    cudaGetSymbolAddress((void**)&wrel, g_wrelT);
    cudaGetSymbolAddress((void**)&w1T,  g_w1T);
    cudaGetSymbolAddress((void**)&w2T,  g_w2T);
    cudaGetSymbolAddress((void**)&cnt,  g_cnt);
    cudaGetSymbolAddress((void**)&fill, g_fill);

    // 0) transpose + fp16-round weights; zero CSR counters
    cudaMemsetAsync(cnt, 0, NN * sizeof(int));
    cudaMemsetAsync(fill, 0, NN * sizeof(int));
    dim3 tb(32, 8);
    transpose4_rnd<<<dim3(FF / 32, FF / 32, 4), tb>>>(W_head, W_tail, W_ent, W_rel, wcat, wrel);
    transpose_rnd<<<dim3(FHID / 32, FF / 32), tb>>>(W1, w1T, FF, FHID);
    transpose_rnd<<<dim3(FF / 32, FHID / 32), tb>>>(W2, w2T, FHID, FF);

    // 1) LayerNorms (fp16 outputs; only consumed by GEMMs)
    ln_kernel<<<NN, 256>>>(ent_feat, xln, ln_ent_g, ln_ent_b);
    ln_kernel<<<RR, 256>>>(rel_feat, rln, ln_rel_g, ln_rel_b);

    // 2) Projections: rel + fused head/tail/ent (Nc=768), fp32 outputs
    const int mT = (NN + 127) / 128;   // 157
    mma_gemm<<<dim3(FF / 128, 1), 256, GSMEM_BYTES>>>(rln, wrel, fr, RR, FF, FF, nullptr, nullptr, 0);
    mma_gemm<<<dim3(PF / 128, mT), 256, GSMEM_BYTES>>>(xln, wcat, proj, NN, PF, FF, nullptr, nullptr, 0);

    // 3) CSR build (sorted by dst)
    count_kernel<<<(EE + 255) / 256, 256>>>(dst);
    scan_kernel<<<1, 1024>>>();
    scatter_kernel<<<(EE + 255) / 256, 256>>>(src, dst, rid);

    // 4) edge attention + softmax + hop 1 (fused) -> fa
    attn_hop1_kernel<<<NN / 8, 256>>>(attn, fa);

    // 5) remaining 4 PPR hops (ping-pong), last adds ent_feat residual -> g_rst
    hop_kernel<<<NN / 8, 256>>>(fa, FF, fb, nullptr);
    hop_kernel<<<NN / 8, 256>>>(fb, FF, fa, nullptr);
    hop_kernel<<<NN / 8, 256>>>(fa, FF, fb, nullptr);
    hop_kernel<<<NN / 8, 256>>>(fb, FF, rst, ent_feat);

    // 6) FFN with pre-LN and residual
    ln_kernel<<<NN, 256>>>(rst, y, ln_ff_g, ln_ff_b);
    mma_gemm<<<dim3(FHID / 128, mT), 256, GSMEM_BYTES>>>(y, w1T, hid, NN, FHID, FF, b1, nullptr, 1 | 2);
    mma_gemm<<<dim3(FF / 128, mT), 256, GSMEM_BYTES>>>(hid, w2T, out, NN, FF, FHID, b2, rst, 0);
}

// round 9
// speedup vs baseline: 2.0420x; 1.0434x over previous
#include <cuda_runtime.h>
#include <cuda_fp16.h>
#include <math.h>
#include <stdint.h>

// Problem constants
#define NN 20000
#define EE 320000
#define RR 100
#define FF 256
#define HH 8
#define DD 32
#define FHID 1024
#define PF 768            // packed projection stride (fh|ftl|fen)
#define ALPHA 0.1f
#define SLOPE 0.2f

// ---------------------------------------------------------------------------
__device__ __forceinline__ uint32_t smem_u32(const void* p) {
    uint32_t a;
    asm("{ .reg .u64 t; cvta.to.shared.u64 t, %1; cvt.u32.u64 %0, t; }" : "=r"(a) : "l"(p));
    return a;
}
#define CP_ASYNC16(dst, src) \
    asm volatile("cp.async.cg.shared.global [%0], [%1], 16;" :: "r"(dst), "l"(src) : "memory")
#define CP_COMMIT() asm volatile("cp.async.commit_group;" ::: "memory")
#define CP_WAIT(n)  asm volatile("cp.async.wait_group %0;" :: "n"(n) : "memory")

#define LDSM_X4(r0, r1, r2, r3, addr) \
    asm volatile("ldmatrix.sync.aligned.m8n8.x4.shared.b16 {%0,%1,%2,%3}, [%4];" \
                 : "=r"(r0), "=r"(r1), "=r"(r2), "=r"(r3) : "r"(addr))
#define MMA_F16(c, a, b) \
    asm volatile("mma.sync.aligned.m16n8k16.row.col.f32.f16.f16.f32 " \
                 "{%0,%1,%2,%3},{%4,%5,%6,%7},{%8,%9},{%0,%1,%2,%3};" \
                 : "+f"((c)[0]), "+f"((c)[1]), "+f"((c)[2]), "+f"((c)[3]) \
                 : "r"((a)[0]), "r"((a)[1]), "r"((a)[2]), "r"((a)[3]), \
                   "r"((b)[0]), "r"((b)[1]))

// ------------------------- scratch (device globals) -------------------------
__device__ __half g_xln[NN * FF];
__device__ float  g_proj[NN * PF];      // [fh | ftl | fen] packed per row (fp32)
__device__ __half g_rln[RR * FF];
__device__ float  g_fr [RR * FF];
__device__ int    g_cnt [NN];
__device__ int    g_perm[EE];
__device__ int    g_rowptr[NN + 1];
__device__ int    g_srcs[EE];
__device__ int    g_rids[EE];
__device__ float  g_e[EE * HH];
__device__ float  g_a[EE * HH];
__device__ float  g_fa[NN * FF];
__device__ float  g_fb[NN * FF];
__device__ float  g_rst[NN * FF];
__device__ __half g_y  [NN * FF];
__device__ __half g_hid[NN * FHID];
__device__ __half g_wcatT[PF * FF];     // K-major [768,256]: Whead|Wtail|Went
__device__ __half g_wrelT [FF * FF];
__device__ __half g_w1T[FHID * FF];
__device__ __half g_w2T[FF * FHID];

// ------------------------- LayerNorm (warp per row, fp16 out) -----------------
__global__ void ln_kernel(const float* __restrict__ in, __half* __restrict__ out,
                          const float* __restrict__ gam, const float* __restrict__ bet,
                          int rows) {
    int warp = threadIdx.x >> 5;
    int row = blockIdx.x * 8 + warp;
    if (row >= rows) return;
    int lane = threadIdx.x & 31;
    const int col = lane * 8;
    const float* ip = in + (size_t)row * FF + col;
    float4 x0 = *(const float4*)(ip);
    float4 x1 = *(const float4*)(ip + 4);
    float s  = x0.x + x0.y + x0.z + x0.w + x1.x + x1.y + x1.z + x1.w;
    float s2 = x0.x*x0.x + x0.y*x0.y + x0.z*x0.z + x0.w*x0.w
             + x1.x*x1.x + x1.y*x1.y + x1.z*x1.z + x1.w*x1.w;
    #pragma unroll
    for (int o = 16; o; o >>= 1) {
        s  += __shfl_xor_sync(0xffffffffu, s,  o);
        s2 += __shfl_xor_sync(0xffffffffu, s2, o);
    }
    float m = s * (1.0f / FF);
    float var = s2 * (1.0f / FF) - m * m;
    float inv = rsqrtf(var + 1e-5f);
    float4 gg0 = *(const float4*)(gam + col);
    float4 gg1 = *(const float4*)(gam + col + 4);
    float4 bb0 = *(const float4*)(bet + col);
    float4 bb1 = *(const float4*)(bet + col + 4);
    __half2 h0 = __floats2half2_rn((x0.x - m) * inv * gg0.x + bb0.x,
                                   (x0.y - m) * inv * gg0.y + bb0.y);
    __half2 h1 = __floats2half2_rn((x0.z - m) * inv * gg0.z + bb0.z,
                                   (x0.w - m) * inv * gg0.w + bb0.w);
    __half2 h2 = __floats2half2_rn((x1.x - m) * inv * gg1.x + bb1.x,
                                   (x1.y - m) * inv * gg1.y + bb1.y);
    __half2 h3 = __floats2half2_rn((x1.z - m) * inv * gg1.z + bb1.z,
                                   (x1.w - m) * inv * gg1.w + bb1.w);
    uint4 u;
    u.x = *(uint32_t*)&h0; u.y = *(uint32_t*)&h1;
    u.z = *(uint32_t*)&h2; u.w = *(uint32_t*)&h3;
    *(uint4*)(out + (size_t)row * FF + col) = u;
}

// ------------------------- weight transpose (fp32 -> fp16 K-major) -----------
__global__ void transpose_rnd(const float* __restrict__ B, __half* __restrict__ BT,
                              int K, int N) {
    __shared__ float t[32][33];
    int n0 = blockIdx.x * 32, k0 = blockIdx.y * 32;
    int x = threadIdx.x, y = threadIdx.y;
    #pragma unroll
    for (int r = 0; r < 32; r += 8)
        t[y + r][x] = B[(size_t)(k0 + y + r) * N + n0 + x];
    __syncthreads();
    #pragma unroll
    for (int r = 0; r < 32; r += 8)
        BT[(size_t)(n0 + y + r) * K + k0 + x] = __float2half_rn(t[x][y + r]);
}
__global__ void transpose4_rnd(const float* __restrict__ Wh, const float* __restrict__ Wt,
                               const float* __restrict__ We, const float* __restrict__ Wr,
                               __half* __restrict__ wcat, __half* __restrict__ wrel) {
    __shared__ float t[32][33];
    int z = blockIdx.z;
    const float* B = (z == 0) ? Wh : (z == 1) ? Wt : (z == 2) ? We : Wr;
    __half* BT = (z < 3) ? (wcat + (size_t)z * FF * FF) : wrel;
    int n0 = blockIdx.x * 32, k0 = blockIdx.y * 32;
    int x = threadIdx.x, y = threadIdx.y;
    #pragma unroll
    for (int r = 0; r < 32; r += 8)
        t[y + r][x] = B[(size_t)(k0 + y + r) * FF + n0 + x];
    __syncthreads();
    #pragma unroll
    for (int r = 0; r < 32; r += 8)
        BT[(size_t)(n0 + y + r) * FF + k0 + x] = __float2half_rn(t[x][y + r]);
}

// ------------------------- fp16 mma.sync GEMM (R8 config) --------------------
#define GSTAGES 3
#define GSTG 32768
#define GSMEM_BYTES (GSTAGES * GSTG)

__global__ void __launch_bounds__(256, 2)
mma_gemm(const __half* __restrict__ A, const __half* __restrict__ BT,
         void* __restrict__ Cv, int M, int Nc, int K,
         const float* __restrict__ bias, const float* __restrict__ res, int mode) {
    extern __shared__ float smemf[];
    const uint32_t sb = smem_u32(smemf);

    const int m0 = blockIdx.y * 128;
    const int n0 = blockIdx.x * 128;
    const int tid = threadIdx.x;
    const int warp = tid >> 5, lane = tid & 31;
    const int wm = warp >> 2, wn = warp & 3;

    const int lrow = tid >> 1, lhalf = tid & 1;
    int aRow = m0 + lrow; if (aRow >= M) aRow = M - 1;
    const __half* aG = A + (size_t)aRow * K + lhalf * 32;
    const __half* bG = BT + (size_t)(n0 + lrow) * K + lhalf * 32;
    const uint32_t sA = sb + (uint32_t)lrow * 128;
    const uint32_t sB = sb + 16384 + (uint32_t)lrow * 128;
    uint32_t swz[4];
    #pragma unroll
    for (int j = 0; j < 4; j++)
        swz[j] = (uint32_t)(((lhalf * 4 + j) ^ (lrow & 7)) << 4);

    const int nCh = K >> 6;   // K / 64

    float c[4][4][4];
    #pragma unroll
    for (int mt = 0; mt < 4; mt++)
        #pragma unroll
        for (int nt = 0; nt < 4; nt++)
            #pragma unroll
            for (int q = 0; q < 4; q++) c[mt][nt][q] = 0.f;

    #pragma unroll
    for (int s = 0; s < 2; s++) {
        const uint32_t off = (uint32_t)s * GSTG;
        const __half* ag = aG + s * 64;
        const __half* bg = bG + s * 64;
        #pragma unroll
        for (int j = 0; j < 4; j++) CP_ASYNC16(sA + off + swz[j], ag + j * 8);
        #pragma unroll
        for (int j = 0; j < 4; j++) CP_ASYNC16(sB + off + swz[j], bg + j * 8);
        CP_COMMIT();
    }

    const int q8 = lane >> 3, r8 = lane & 7;

    for (int i = 0; i < nCh; i++) {
        __syncthreads();
        if (i + 2 < nCh) {
            const uint32_t off = (uint32_t)((i + 2) % GSTAGES) * GSTG;
            const __half* ag = aG + (i + 2) * 64;
            const __half* bg = bG + (i + 2) * 64;
            #pragma unroll
            for (int j = 0; j < 4; j++) CP_ASYNC16(sA + off + swz[j], ag + j * 8);
            #pragma unroll
            for (int j = 0; j < 4; j++) CP_ASYNC16(sB + off + swz[j], bg + j * 8);
        }
        CP_COMMIT();
        CP_WAIT(2);
        __syncthreads();

        const uint32_t Ab = sb + (uint32_t)(i % GSTAGES) * GSTG;
        const uint32_t Bb = Ab + 16384;
        #pragma unroll
        for (int ks = 0; ks < 4; ks++) {
            uint32_t a[4][4];
            #pragma unroll
            for (int mt = 0; mt < 4; mt++) {
                const int rl = wm * 64 + mt * 16 + (q8 & 1) * 8 + r8;
                const int kc = ks * 2 + (q8 >> 1);
                const uint32_t ad = Ab + (uint32_t)rl * 128 + (uint32_t)((kc ^ (rl & 7)) << 4);
                LDSM_X4(a[mt][0], a[mt][1], a[mt][2], a[mt][3], ad);
            }
            uint32_t b[4][2];
            #pragma unroll
            for (int p = 0; p < 2; p++) {
                const int nl = wn * 32 + (p * 2 + (q8 >> 1)) * 8 + r8;
                const int kc = ks * 2 + (q8 & 1);
                const uint32_t bd = Bb + (uint32_t)nl * 128 + (uint32_t)((kc ^ (nl & 7)) << 4);
                LDSM_X4(b[p * 2][0], b[p * 2][1], b[p * 2 + 1][0], b[p * 2 + 1][1], bd);
            }
            #pragma unroll
            for (int mt = 0; mt < 4; mt++)
                #pragma unroll
                for (int nt = 0; nt < 4; nt++)
                    MMA_F16(c[mt][nt], a[mt], b[nt]);
        }
    }

    const int g = lane >> 2, t4 = lane & 3;
    #pragma unroll
    for (int mt = 0; mt < 4; mt++) {
        #pragma unroll
        for (int half = 0; half < 2; half++) {
            const int m = m0 + wm * 64 + mt * 16 + g + half * 8;
            if (m < M) {
                #pragma unroll
                for (int nt = 0; nt < 4; nt++) {
                    const int colb = nt * 8 + 2 * t4;
                    const int col = n0 + wn * 32 + colb;
                    float v0 = c[mt][nt][half * 2 + 0];
                    float v1 = c[mt][nt][half * 2 + 1];
                    if (bias) { v0 += bias[col]; v1 += bias[col + 1]; }
                    if (mode & 1) { v0 = fmaxf(v0, 0.f); v1 = fmaxf(v1, 0.f); }
                    if (mode & 2) {
                        __half2 hv = __floats2half2_rn(v0, v1);
                        *(__half2*)((__half*)Cv + (size_t)m * Nc + col) = hv;
                    } else {
                        if (res) {
                            const float* rp = res + (size_t)m * Nc + col;
                            v0 += rp[0]; v1 += rp[1];
                        }
                        float2 v; v.x = v0; v.y = v1;
                        *(float2*)((float*)Cv + (size_t)m * Nc + col) = v;
                    }
                }
            }
        }
    }
}

// ------------------------- CSR build -----------------------------------------
__global__ void count_kernel(const int* __restrict__ dst) {
    int i = blockIdx.x * blockDim.x + threadIdx.x;
    if (i < EE) g_perm[i] = atomicAdd(&g_cnt[dst[i]], 1);
}
__global__ void scan_kernel() {
    __shared__ int ss[1024];
    int t = threadIdx.x;
    const int CH = (NN + 1023) / 1024;
    int base = t * CH;
    int loc = 0;
    for (int i = 0; i < CH; i++) {
        int idx = base + i;
        if (idx < NN) loc += g_cnt[idx];
    }
    ss[t] = loc;
    __syncthreads();
    for (int off = 1; off < 1024; off <<= 1) {
        int v = (t >= off) ? ss[t - off] : 0;
        __syncthreads();
        ss[t] += v;
        __syncthreads();
    }
    int run = (t == 0) ? 0 : ss[t - 1];
    for (int i = 0; i < CH; i++) {
        int idx = base + i;
        if (idx < NN) { g_rowptr[idx] = run; run += g_cnt[idx]; }
    }
    if (t == 0) g_rowptr[NN] = EE;
}
__global__ void scatter_kernel(const int* __restrict__ src, const int* __restrict__ dst,
                               const int* __restrict__ rid) {
    int i = blockIdx.x * blockDim.x + threadIdx.x;
    if (i < EE) {
        int pos = g_rowptr[dst[i]] + g_perm[i];
        g_srcs[pos] = src[i];
        g_rids[pos] = rid[i];
    }
}

// ---------------- edge attention + softmax + first PPR hop -------------------
__global__ void attn_hop1_kernel(const float* __restrict__ attn,
                                 float* __restrict__ fout) {
    int w = (blockIdx.x * blockDim.x + threadIdx.x) >> 5;
    int lane = threadIdx.x & 31;
    if (w >= NN) return;
    int node = w;
    const int h = lane >> 2;
    const int db = (lane & 3) * 8;
    const int off = h * DD + db;

    float4 tl0 = *(const float4*)(g_proj + (size_t)node * PF + FF + off);
    float4 tl1 = *(const float4*)(g_proj + (size_t)node * PF + FF + off + 4);
    float4 av0 = *(const float4*)(attn + off);
    float4 av1 = *(const float4*)(attn + off + 4);

    int beg = g_rowptr[node], end = g_rowptr[node + 1];
    float scale = logf((float)(end - beg)) * (1.0f / DD);

    float mloc = -1e30f;
    for (int p = beg; p < end; p++) {
        int s = g_srcs[p], r = g_rids[p];
        const float* fhp = g_proj + (size_t)s * PF + off;
        const float* frp = g_fr + (size_t)r * FF + off;
        float4 fh0 = *(const float4*)(fhp);
        float4 fh1 = *(const float4*)(fhp + 4);
        float4 fr0 = *(const float4*)(frp);
        float4 fr1 = *(const float4*)(frp + 4);
        float v = 0.f;
        {
            float x;
            x = fh0.x * tl0.x * fr0.x; x = (x > 0.f) ? x : SLOPE * x; v += x * av0.x;
            x = fh0.y * tl0.y * fr0.y; x = (x > 0.f) ? x : SLOPE * x; v += x * av0.y;
            x = fh0.z * tl0.z * fr0.z; x = (x > 0.f) ? x : SLOPE * x; v += x * av0.z;
            x = fh0.w * tl0.w * fr0.w; x = (x > 0.f) ? x : SLOPE * x; v += x * av0.w;
            x = fh1.x * tl1.x * fr1.x; x = (x > 0.f) ? x : SLOPE * x; v += x * av1.x;
            x = fh1.y * tl1.y * fr1.y; x = (x > 0.f) ? x : SLOPE * x; v += x * av1.y;
            x = fh1.z * tl1.z * fr1.z; x = (x > 0.f) ? x : SLOPE * x; v += x * av1.z;
            x = fh1.w * tl1.w * fr1.w; x = (x > 0.f) ? x : SLOPE * x; v += x * av1.w;
        }
        v += __shfl_xor_sync(0xffffffffu, v, 1);
        v += __shfl_xor_sync(0xffffffffu, v, 2);
        v *= scale;
        mloc = fmaxf(mloc, v);
        if ((lane & 3) == 0) g_e[p * HH + h] = v;
    }
    __syncwarp();

    const int hs = lane & 7, pi = lane >> 3;
    float m = __shfl_sync(0xffffffffu, mloc, hs * 4);
    float ssum = 0.f;
    for (int p = beg + pi; p < end; p += 4) ssum += expf(g_e[p * HH + hs] - m);
    ssum += __shfl_xor_sync(0xffffffffu, ssum, 8);
    ssum += __shfl_xor_sync(0xffffffffu, ssum, 16);
    float inv = 1.0f / ssum;
    for (int p = beg + pi; p < end; p += 4)
        g_a[p * HH + hs] = expf(g_e[p * HH + hs] - m) * inv;
    __syncwarp();

    // first hop (unroll 4): lane owns cols lane*8 .. lane*8+7
    const int col = lane * 8;
    float4 a0 = make_float4(0.f, 0.f, 0.f, 0.f);
    float4 a1 = make_float4(0.f, 0.f, 0.f, 0.f);
    int p = beg;
    for (; p + 4 <= end; p += 4) {
        int s0 = g_srcs[p], s1 = g_srcs[p + 1], s2 = g_srcs[p + 2], s3 = g_srcs[p + 3];
        float w0 = g_a[p * HH + h], w1 = g_a[(p + 1) * HH + h];
        float w2 = g_a[(p + 2) * HH + h], w3 = g_a[(p + 3) * HH + h];
        const float* r0 = g_proj + (size_t)s0 * PF + 2 * FF + col;
        const float* r1 = g_proj + (size_t)s1 * PF + 2 * FF + col;
        const float* r2 = g_proj + (size_t)s2 * PF + 2 * FF + col;
        const float* r3 = g_proj + (size_t)s3 * PF + 2 * FF + col;
        float4 f00 = *(const float4*)(r0), f01 = *(const float4*)(r0 + 4);
        float4 f10 = *(const float4*)(r1), f11 = *(const float4*)(r1 + 4);
        float4 f20 = *(const float4*)(r2), f21 = *(const float4*)(r2 + 4);
        float4 f30 = *(const float4*)(r3), f31 = *(const float4*)(r3 + 4);
        a0.x += w0*f00.x + w1*f10.x + w2*f20.x + w3*f30.x;
        a0.y += w0*f00.y + w1*f10.y + w2*f20.y + w3*f30.y;
        a0.z += w0*f00.z + w1*f10.z + w2*f20.z + w3*f30.z;
        a0.w += w0*f00.w + w1*f10.w + w2*f20.w + w3*f30.w;
        a1.x += w0*f01.x + w1*f11.x + w2*f21.x + w3*f31.x;
        a1.y += w0*f01.y + w1*f11.y + w2*f21.y + w3*f31.y;
        a1.z += w0*f01.z + w1*f11.z + w2*f21.z + w3*f31.z;
        a1.w += w0*f01.w + w1*f11.w + w2*f21.w + w3*f31.w;
    }
    for (; p < end; p++) {
        int s = g_srcs[p];
        float av = g_a[p * HH + h];
        const float* frow = g_proj + (size_t)s * PF + 2 * FF + col;
        float4 f0 = *(const float4*)(frow);
        float4 f1 = *(const float4*)(frow + 4);
        a0.x += av * f0.x; a0.y += av * f0.y; a0.z += av * f0.z; a0.w += av * f0.w;
        a1.x += av * f1.x; a1.y += av * f1.y; a1.z += av * f1.z; a1.w += av * f1.w;
    }
    const float* f0p = g_proj + (size_t)node * PF + 2 * FF + col;
    float4 e0 = *(const float4*)(f0p);
    float4 e1 = *(const float4*)(f0p + 4);
    float4 o0, o1;
    o0.x = (1.0f - ALPHA) * a0.x + ALPHA * e0.x;
    o0.y = (1.0f - ALPHA) * a0.y + ALPHA * e0.y;
    o0.z = (1.0f - ALPHA) * a0.z + ALPHA * e0.z;
    o0.w = (1.0f - ALPHA) * a0.w + ALPHA * e0.w;
    o1.x = (1.0f - ALPHA) * a1.x + ALPHA * e1.x;
    o1.y = (1.0f - ALPHA) * a1.y + ALPHA * e1.y;
    o1.z = (1.0f - ALPHA) * a1.z + ALPHA * e1.z;
    o1.w = (1.0f - ALPHA) * a1.w + ALPHA * e1.w;
    float* op = fout + (size_t)node * FF + col;
    *(float4*)(op) = o0;
    *(float4*)(op + 4) = o1;
}

// ------------------------- diffusion hop (unroll 4) ---------------------------
__global__ void hop_kernel(const float* __restrict__ fin, int fstride,
                           float* __restrict__ fout, const float* __restrict__ ent) {
    int w = (blockIdx.x * blockDim.x + threadIdx.x) >> 5;
    int lane = threadIdx.x & 31;
    if (w >= NN) return;
    int node = w;
    const int col = lane * 8;
    const int h = lane >> 2;
    int beg = g_rowptr[node], end = g_rowptr[node + 1];

    float4 a0 = make_float4(0.f, 0.f, 0.f, 0.f);
    float4 a1 = make_float4(0.f, 0.f, 0.f, 0.f);
    int p = beg;
    for (; p + 4 <= end; p += 4) {
        int s0 = g_srcs[p], s1 = g_srcs[p + 1], s2 = g_srcs[p + 2], s3 = g_srcs[p + 3];
        float w0 = g_a[p * HH + h], w1 = g_a[(p + 1) * HH + h];
        float w2 = g_a[(p + 2) * HH + h], w3 = g_a[(p + 3) * HH + h];
        const float* r0 = fin + (size_t)s0 * fstride + col;
        const float* r1 = fin + (size_t)s1 * fstride + col;
        const float* r2 = fin + (size_t)s2 * fstride + col;
        const float* r3 = fin + (size_t)s3 * fstride + col;
        float4 f00 = *(const float4*)(r0), f01 = *(const float4*)(r0 + 4);
        float4 f10 = *(const float4*)(r1), f11 = *(const float4*)(r1 + 4);
        float4 f20 = *(const float4*)(r2), f21 = *(const float4*)(r2 + 4);
        float4 f30 = *(const float4*)(r3), f31 = *(const float4*)(r3 + 4);
        a0.x += w0*f00.x + w1*f10.x + w2*f20.x + w3*f30.x;
        a0.y += w0*f00.y + w1*f10.y + w2*f20.y + w3*f30.y;
        a0.z += w0*f00.z + w1*f10.z + w2*f20.z + w3*f30.z;
        a0.w += w0*f00.w + w1*f10.w + w2*f20.w + w3*f30.w;
        a1.x += w0*f01.x + w1*f11.x + w2*f21.x + w3*f31.x;
        a1.y += w0*f01.y + w1*f11.y + w2*f21.y + w3*f31.y;
        a1.z += w0*f01.z + w1*f11.z + w2*f21.z + w3*f31.z;
        a1.w += w0*f01.w + w1*f11.w + w2*f21.w + w3*f31.w;
    }
    for (; p < end; p++) {
        int s = g_srcs[p];
        float av = g_a[p * HH + h];
        const float* frow = fin + (size_t)s * fstride + col;
        float4 f0 = *(const float4*)(frow);
        float4 f1 = *(const float4*)(frow + 4);
        a0.x += av * f0.x; a0.y += av * f0.y; a0.z += av * f0.z; a0.w += av * f0.w;
        a1.x += av * f1.x; a1.y += av * f1.y; a1.z += av * f1.z; a1.w += av * f1.w;
    }
    const float* f0p = g_proj + (size_t)node * PF + 2 * FF + col;
    float4 e0 = *(const float4*)(f0p);
    float4 e1 = *(const float4*)(f0p + 4);
    float4 o0, o1;
    o0.x = (1.0f - ALPHA) * a0.x + ALPHA * e0.x;
    o0.y = (1.0f - ALPHA) * a0.y + ALPHA * e0.y;
    o0.z = (1.0f - ALPHA) * a0.z + ALPHA * e0.z;
    o0.w = (1.0f - ALPHA) * a0.w + ALPHA * e0.w;
    o1.x = (1.0f - ALPHA) * a1.x + ALPHA * e1.x;
    o1.y = (1.0f - ALPHA) * a1.y + ALPHA * e1.y;
    o1.z = (1.0f - ALPHA) * a1.z + ALPHA * e1.z;
    o1.w = (1.0f - ALPHA) * a1.w + ALPHA * e1.w;
    if (ent) {
        const float* ep = ent + (size_t)node * FF + col;
        float4 n0 = *(const float4*)(ep);
        float4 n1 = *(const float4*)(ep + 4);
        o0.x += n0.x; o0.y += n0.y; o0.z += n0.z; o0.w += n0.w;
        o1.x += n1.x; o1.y += n1.y; o1.z += n1.z; o1.w += n1.w;
    }
    float* op = fout + (size_t)node * FF + col;
    *(float4*)(op) = o0;
    *(float4*)(op + 4) = o1;
}

// ------------------------- launcher -------------------------------------------
extern "C" void kernel_launch(void* const* d_in, const int* in_sizes, int n_in,
                              void* d_out, int out_size) {
    const float* ent_feat = (const float*)d_in[0];
    const float* rel_feat = (const float*)d_in[1];
    const float* W_head   = (const float*)d_in[2];
    const float* W_tail   = (const float*)d_in[3];
    const float* W_ent    = (const float*)d_in[4];
    const float* W_rel    = (const float*)d_in[5];
    const float* attn     = (const float*)d_in[6];
    const float* ln_ent_g = (const float*)d_in[7];
    const float* ln_ent_b = (const float*)d_in[8];
    const float* ln_rel_g = (const float*)d_in[9];
    const float* ln_rel_b = (const float*)d_in[10];
    const float* ln_ff_g  = (const float*)d_in[11];
    const float* ln_ff_b  = (const float*)d_in[12];
    const float* W1       = (const float*)d_in[13];
    const float* b1       = (const float*)d_in[14];
    const float* W2       = (const float*)d_in[15];
    const float* b2       = (const float*)d_in[16];
    const int*   src      = (const int*)d_in[17];
    const int*   dst      = (const int*)d_in[18];
    const int*   rid      = (const int*)d_in[19];
    float* out = (float*)d_out;

    cudaFuncSetAttribute(mma_gemm, cudaFuncAttributeMaxDynamicSharedMemorySize, GSMEM_BYTES);

    float *proj, *fr, *fa, *fb, *rst;
    __half *xln, *rln, *y, *hid, *wcat, *wrel, *w1T, *w2T;
    int *cnt;
    cudaGetSymbolAddress((void**)&xln,  g_xln);
    cudaGetSymbolAddress((void**)&proj, g_proj);
    cudaGetSymbolAddress((void**)&rln,  g_rln);
    cudaGetSymbolAddress((void**)&fr,   g_fr);
    cudaGetSymbolAddress((void**)&fa,   g_fa);
    cudaGetSymbolAddress((void**)&fb,   g_fb);
    cudaGetSymbolAddress((void**)&rst,  g_rst);
    cudaGetSymbolAddress((void**)&y,    g_y);
    cudaGetSymbolAddress((void**)&hid,  g_hid);
    cudaGetSymbolAddress((void**)&wcat, g_wcatT);
    cudaGetSymbolAddress((void**)&wrel, g_wrelT);
    cudaGetSymbolAddress((void**)&w1T,  g_w1T);
    cudaGetSymbolAddress((void**)&w2T,  g_w2T);
    cudaGetSymbolAddress((void**)&cnt,  g_cnt);

    // 0) transpose + fp16-round weights; zero CSR counters
    cudaMemsetAsync(cnt, 0, NN * sizeof(int));
    dim3 tb(32, 8);
    transpose4_rnd<<<dim3(FF / 32, FF / 32, 4), tb>>>(W_head, W_tail, W_ent, W_rel, wcat, wrel);
    transpose_rnd<<<dim3(FHID / 32, FF / 32), tb>>>(W1, w1T, FF, FHID);
    transpose_rnd<<<dim3(FF / 32, FHID / 32), tb>>>(W2, w2T, FHID, FF);

    // 1) LayerNorms (fp16 outputs; only consumed by GEMMs)
    ln_kernel<<<(NN + 7) / 8, 256>>>(ent_feat, xln, ln_ent_g, ln_ent_b, NN);
    ln_kernel<<<(RR + 7) / 8, 256>>>(rel_feat, rln, ln_rel_g, ln_rel_b, RR);

    // 2) Projections: rel + fused head/tail/ent (Nc=768), fp32 outputs
    const int mT = (NN + 127) / 128;   // 157
    mma_gemm<<<dim3(FF / 128, 1), 256, GSMEM_BYTES>>>(rln, wrel, fr, RR, FF, FF, nullptr, nullptr, 0);
    mma_gemm<<<dim3(PF / 128, mT), 256, GSMEM_BYTES>>>(xln, wcat, proj, NN, PF, FF, nullptr, nullptr, 0);

    // 3) CSR build (sorted by dst)
    count_kernel<<<(EE + 255) / 256, 256>>>(dst);
    scan_kernel<<<1, 1024>>>();
    scatter_kernel<<<(EE + 255) / 256, 256>>>(src, dst, rid);

    // 4) edge attention + softmax + hop 1 (fused) -> fa
    attn_hop1_kernel<<<NN / 8, 256>>>(attn, fa);

    // 5) remaining 4 PPR hops (ping-pong), last adds ent_feat residual -> g_rst
    hop_kernel<<<NN / 8, 256>>>(fa, FF, fb, nullptr);
    hop_kernel<<<NN / 8, 256>>>(fb, FF, fa, nullptr);
    hop_kernel<<<NN / 8, 256>>>(fa, FF, fb, nullptr);
    hop_kernel<<<NN / 8, 256>>>(fb, FF, rst, ent_feat);

    // 6) FFN with pre-LN and residual
    ln_kernel<<<(NN + 7) / 8, 256>>>(rst, y, ln_ff_g, ln_ff_b, NN);
    mma_gemm<<<dim3(FHID / 128, mT), 256, GSMEM_BYTES>>>(y, w1T, hid, NN, FHID, FF, b1, nullptr, 1 | 2);
    mma_gemm<<<dim3(FF / 128, mT), 256, GSMEM_BYTES>>>(hid, w2T, out, NN, FF, FHID, b2, rst, 0);
}

// round 10
// speedup vs baseline: 2.5323x; 1.2401x over previous
#include <cuda_runtime.h>
#include <cuda_fp16.h>
#include <math.h>
#include <stdint.h>

// Problem constants
#define NN 20000
#define EE 320000
#define RR 100
#define FF 256
#define HH 8
#define DD 32
#define FHID 1024
#define PF 768            // packed projection stride (fh|ftl|fen)
#define ALPHA 0.1f
#define SLOPE 0.2f

// ---------------------------------------------------------------------------
__device__ __forceinline__ uint32_t smem_u32(const void* p) {
    uint32_t a;
    asm("{ .reg .u64 t; cvta.to.shared.u64 t, %1; cvt.u32.u64 %0, t; }" : "=r"(a) : "l"(p));
    return a;
}
#define CP_ASYNC16(dst, src) \
    asm volatile("cp.async.cg.shared.global [%0], [%1], 16;" :: "r"(dst), "l"(src) : "memory")
#define CP_COMMIT() asm volatile("cp.async.commit_group;" ::: "memory")
#define CP_WAIT(n)  asm volatile("cp.async.wait_group %0;" :: "n"(n) : "memory")

#define LDSM_X4(r0, r1, r2, r3, addr) \
    asm volatile("ldmatrix.sync.aligned.m8n8.x4.shared.b16 {%0,%1,%2,%3}, [%4];" \
                 : "=r"(r0), "=r"(r1), "=r"(r2), "=r"(r3) : "r"(addr))
#define MMA_F16(c, a, b) \
    asm volatile("mma.sync.aligned.m16n8k16.row.col.f32.f16.f16.f32 " \
                 "{%0,%1,%2,%3},{%4,%5,%6,%7},{%8,%9},{%0,%1,%2,%3};" \
                 : "+f"((c)[0]), "+f"((c)[1]), "+f"((c)[2]), "+f"((c)[3]) \
                 : "r"((a)[0]), "r"((a)[1]), "r"((a)[2]), "r"((a)[3]), \
                   "r"((b)[0]), "r"((b)[1]))

// load/store 8 halves as 2x float4 (fp32 math in registers)
__device__ __forceinline__ void ld_h8(const __half* p, float4& f0, float4& f1) {
    uint4 u = *(const uint4*)(p);
    const __half2* h = (const __half2*)&u;
    float2 a = __half22float2(h[0]);
    float2 b = __half22float2(h[1]);
    float2 c = __half22float2(h[2]);
    float2 d = __half22float2(h[3]);
    f0 = make_float4(a.x, a.y, b.x, b.y);
    f1 = make_float4(c.x, c.y, d.x, d.y);
}
__device__ __forceinline__ void st_h8(__half* p, float4 f0, float4 f1) {
    __half2 h0 = __floats2half2_rn(f0.x, f0.y);
    __half2 h1 = __floats2half2_rn(f0.z, f0.w);
    __half2 h2 = __floats2half2_rn(f1.x, f1.y);
    __half2 h3 = __floats2half2_rn(f1.z, f1.w);
    uint4 u;
    u.x = *(uint32_t*)&h0; u.y = *(uint32_t*)&h1;
    u.z = *(uint32_t*)&h2; u.w = *(uint32_t*)&h3;
    *(uint4*)(p) = u;
}

// ------------------------- scratch (device globals) -------------------------
__device__ __half g_xln[NN * FF];
__device__ __half g_proj[NN * PF];      // [fh | ftl | fen] packed per row (fp16)
__device__ __half g_rln[RR * FF];
__device__ __half g_fr [RR * FF];
__device__ int    g_cnt [NN];
__device__ int    g_perm[EE];
__device__ int    g_rowptr[NN + 1];
__device__ int    g_srcs[EE];
__device__ int    g_rids[EE];
__device__ float  g_e[EE * HH];
__device__ float  g_a[EE * HH];
__device__ __half g_fa[NN * FF];
__device__ __half g_fb[NN * FF];
__device__ float  g_rst[NN * FF];
__device__ __half g_y  [NN * FF];
__device__ __half g_hid[NN * FHID];
__device__ __half g_wcatT[PF * FF];
__device__ __half g_wrelT [FF * FF];
__device__ __half g_w1T[FHID * FF];
__device__ __half g_w2T[FF * FHID];

// ------------------------- LayerNorm (warp per row, fp16 out) -----------------
__global__ void ln_kernel(const float* __restrict__ in, __half* __restrict__ out,
                          const float* __restrict__ gam, const float* __restrict__ bet,
                          int rows) {
    int warp = threadIdx.x >> 5;
    int row = blockIdx.x * 8 + warp;
    if (row >= rows) return;
    int lane = threadIdx.x & 31;
    const int col = lane * 8;
    const float* ip = in + (size_t)row * FF + col;
    float4 x0 = *(const float4*)(ip);
    float4 x1 = *(const float4*)(ip + 4);
    float s  = x0.x + x0.y + x0.z + x0.w + x1.x + x1.y + x1.z + x1.w;
    float s2 = x0.x*x0.x + x0.y*x0.y + x0.z*x0.z + x0.w*x0.w
             + x1.x*x1.x + x1.y*x1.y + x1.z*x1.z + x1.w*x1.w;
    #pragma unroll
    for (int o = 16; o; o >>= 1) {
        s  += __shfl_xor_sync(0xffffffffu, s,  o);
        s2 += __shfl_xor_sync(0xffffffffu, s2, o);
    }
    float m = s * (1.0f / FF);
    float var = s2 * (1.0f / FF) - m * m;
    float inv = rsqrtf(var + 1e-5f);
    float4 gg0 = *(const float4*)(gam + col);
    float4 gg1 = *(const float4*)(gam + col + 4);
    float4 bb0 = *(const float4*)(bet + col);
    float4 bb1 = *(const float4*)(bet + col + 4);
    float4 o0, o1;
    o0.x = (x0.x - m) * inv * gg0.x + bb0.x;
    o0.y = (x0.y - m) * inv * gg0.y + bb0.y;
    o0.z = (x0.z - m) * inv * gg0.z + bb0.z;
    o0.w = (x0.w - m) * inv * gg0.w + bb0.w;
    o1.x = (x1.x - m) * inv * gg1.x + bb1.x;
    o1.y = (x1.y - m) * inv * gg1.y + bb1.y;
    o1.z = (x1.z - m) * inv * gg1.z + bb1.z;
    o1.w = (x1.w - m) * inv * gg1.w + bb1.w;
    st_h8(out + (size_t)row * FF + col, o0, o1);
}

// ------------------------- weight transpose (fp32 -> fp16 K-major) -----------
__global__ void transpose_rnd(const float* __restrict__ B, __half* __restrict__ BT,
                              int K, int N) {
    __shared__ float t[32][33];
    int n0 = blockIdx.x * 32, k0 = blockIdx.y * 32;
    int x = threadIdx.x, y = threadIdx.y;
    #pragma unroll
    for (int r = 0; r < 32; r += 8)
        t[y + r][x] = B[(size_t)(k0 + y + r) * N + n0 + x];
    __syncthreads();
    #pragma unroll
    for (int r = 0; r < 32; r += 8)
        BT[(size_t)(n0 + y + r) * K + k0 + x] = __float2half_rn(t[x][y + r]);
}
__global__ void transpose4_rnd(const float* __restrict__ Wh, const float* __restrict__ Wt,
                               const float* __restrict__ We, const float* __restrict__ Wr,
                               __half* __restrict__ wcat, __half* __restrict__ wrel) {
    __shared__ float t[32][33];
    int z = blockIdx.z;
    const float* B = (z == 0) ? Wh : (z == 1) ? Wt : (z == 2) ? We : Wr;
    __half* BT = (z < 3) ? (wcat + (size_t)z * FF * FF) : wrel;
    int n0 = blockIdx.x * 32, k0 = blockIdx.y * 32;
    int x = threadIdx.x, y = threadIdx.y;
    #pragma unroll
    for (int r = 0; r < 32; r += 8)
        t[y + r][x] = B[(size_t)(k0 + y + r) * FF + n0 + x];
    __syncthreads();
    #pragma unroll
    for (int r = 0; r < 32; r += 8)
        BT[(size_t)(n0 + y + r) * FF + k0 + x] = __float2half_rn(t[x][y + r]);
}

// ------------------------- fp16 mma.sync GEMM (R8 config) --------------------
#define GSTAGES 3
#define GSTG 32768
#define GSMEM_BYTES (GSTAGES * GSTG)

__global__ void __launch_bounds__(256, 2)
mma_gemm(const __half* __restrict__ A, const __half* __restrict__ BT,
         void* __restrict__ Cv, int M, int Nc, int K,
         const float* __restrict__ bias, const float* __restrict__ res, int mode) {
    extern __shared__ float smemf[];
    const uint32_t sb = smem_u32(smemf);

    const int m0 = blockIdx.y * 128;
    const int n0 = blockIdx.x * 128;
    const int tid = threadIdx.x;
    const int warp = tid >> 5, lane = tid & 31;
    const int wm = warp >> 2, wn = warp & 3;

    const int lrow = tid >> 1, lhalf = tid & 1;
    int aRow = m0 + lrow; if (aRow >= M) aRow = M - 1;
    const __half* aG = A + (size_t)aRow * K + lhalf * 32;
    const __half* bG = BT + (size_t)(n0 + lrow) * K + lhalf * 32;
    const uint32_t sA = sb + (uint32_t)lrow * 128;
    const uint32_t sB = sb + 16384 + (uint32_t)lrow * 128;
    uint32_t swz[4];
    #pragma unroll
    for (int j = 0; j < 4; j++)
        swz[j] = (uint32_t)(((lhalf * 4 + j) ^ (lrow & 7)) << 4);

    const int nCh = K >> 6;

    float c[4][4][4];
    #pragma unroll
    for (int mt = 0; mt < 4; mt++)
        #pragma unroll
        for (int nt = 0; nt < 4; nt++)
            #pragma unroll
            for (int q = 0; q < 4; q++) c[mt][nt][q] = 0.f;

    #pragma unroll
    for (int s = 0; s < 2; s++) {
        const uint32_t off = (uint32_t)s * GSTG;
        const __half* ag = aG + s * 64;
        const __half* bg = bG + s * 64;
        #pragma unroll
        for (int j = 0; j < 4; j++) CP_ASYNC16(sA + off + swz[j], ag + j * 8);
        #pragma unroll
        for (int j = 0; j < 4; j++) CP_ASYNC16(sB + off + swz[j], bg + j * 8);
        CP_COMMIT();
    }

    const int q8 = lane >> 3, r8 = lane & 7;

    for (int i = 0; i < nCh; i++) {
        __syncthreads();
        if (i + 2 < nCh) {
            const uint32_t off = (uint32_t)((i + 2) % GSTAGES) * GSTG;
            const __half* ag = aG + (i + 2) * 64;
            const __half* bg = bG + (i + 2) * 64;
            #pragma unroll
            for (int j = 0; j < 4; j++) CP_ASYNC16(sA + off + swz[j], ag + j * 8);
            #pragma unroll
            for (int j = 0; j < 4; j++) CP_ASYNC16(sB + off + swz[j], bg + j * 8);
        }
        CP_COMMIT();
        CP_WAIT(2);
        __syncthreads();

        const uint32_t Ab = sb + (uint32_t)(i % GSTAGES) * GSTG;
        const uint32_t Bb = Ab + 16384;
        #pragma unroll
        for (int ks = 0; ks < 4; ks++) {
            uint32_t a[4][4];
            #pragma unroll
            for (int mt = 0; mt < 4; mt++) {
                const int rl = wm * 64 + mt * 16 + (q8 & 1) * 8 + r8;
                const int kc = ks * 2 + (q8 >> 1);
                const uint32_t ad = Ab + (uint32_t)rl * 128 + (uint32_t)((kc ^ (rl & 7)) << 4);
                LDSM_X4(a[mt][0], a[mt][1], a[mt][2], a[mt][3], ad);
            }
            uint32_t b[4][2];
            #pragma unroll
            for (int p = 0; p < 2; p++) {
                const int nl = wn * 32 + (p * 2 + (q8 >> 1)) * 8 + r8;
                const int kc = ks * 2 + (q8 & 1);
                const uint32_t bd = Bb + (uint32_t)nl * 128 + (uint32_t)((kc ^ (nl & 7)) << 4);
                LDSM_X4(b[p * 2][0], b[p * 2][1], b[p * 2 + 1][0], b[p * 2 + 1][1], bd);
            }
            #pragma unroll
            for (int mt = 0; mt < 4; mt++)
                #pragma unroll
                for (int nt = 0; nt < 4; nt++)
                    MMA_F16(c[mt][nt], a[mt], b[nt]);
        }
    }

    const int g = lane >> 2, t4 = lane & 3;
    #pragma unroll
    for (int mt = 0; mt < 4; mt++) {
        #pragma unroll
        for (int half = 0; half < 2; half++) {
            const int m = m0 + wm * 64 + mt * 16 + g + half * 8;
            if (m < M) {
                #pragma unroll
                for (int nt = 0; nt < 4; nt++) {
                    const int colb = nt * 8 + 2 * t4;
                    const int col = n0 + wn * 32 + colb;
                    float v0 = c[mt][nt][half * 2 + 0];
                    float v1 = c[mt][nt][half * 2 + 1];
                    if (bias) { v0 += bias[col]; v1 += bias[col + 1]; }
                    if (mode & 1) { v0 = fmaxf(v0, 0.f); v1 = fmaxf(v1, 0.f); }
                    if (mode & 2) {
                        __half2 hv = __floats2half2_rn(v0, v1);
                        *(__half2*)((__half*)Cv + (size_t)m * Nc + col) = hv;
                    } else {
                        if (res) {
                            const float* rp = res + (size_t)m * Nc + col;
                            v0 += rp[0]; v1 += rp[1];
                        }
                        float2 v; v.x = v0; v.y = v1;
                        *(float2*)((float*)Cv + (size_t)m * Nc + col) = v;
                    }
                }
            }
        }
    }
}

// ------------------------- CSR build -----------------------------------------
__global__ void count_kernel(const int* __restrict__ dst) {
    int i = blockIdx.x * blockDim.x + threadIdx.x;
    if (i < EE) g_perm[i] = atomicAdd(&g_cnt[dst[i]], 1);
}
__global__ void scan_kernel() {
    __shared__ int ss[1024];
    int t = threadIdx.x;
    const int CH = (NN + 1023) / 1024;
    int base = t * CH;
    int loc = 0;
    for (int i = 0; i < CH; i++) {
        int idx = base + i;
        if (idx < NN) loc += g_cnt[idx];
    }
    ss[t] = loc;
    __syncthreads();
    for (int off = 1; off < 1024; off <<= 1) {
        int v = (t >= off) ? ss[t - off] : 0;
        __syncthreads();
        ss[t] += v;
        __syncthreads();
    }
    int run = (t == 0) ? 0 : ss[t - 1];
    for (int i = 0; i < CH; i++) {
        int idx = base + i;
        if (idx < NN) { g_rowptr[idx] = run; run += g_cnt[idx]; }
    }
    if (t == 0) g_rowptr[NN] = EE;
}
__global__ void scatter_kernel(const int* __restrict__ src, const int* __restrict__ dst,
                               const int* __restrict__ rid) {
    int i = blockIdx.x * blockDim.x + threadIdx.x;
    if (i < EE) {
        int pos = g_rowptr[dst[i]] + g_perm[i];
        g_srcs[pos] = src[i];
        g_rids[pos] = rid[i];
    }
}

// ---------------- edge attention + softmax + first PPR hop -------------------
__global__ void attn_hop1_kernel(const float* __restrict__ attn,
                                 __half* __restrict__ fout) {
    int w = (blockIdx.x * blockDim.x + threadIdx.x) >> 5;
    int lane = threadIdx.x & 31;
    if (w >= NN) return;
    int node = w;
    const int h = lane >> 2;
    const int db = (lane & 3) * 8;
    const int off = h * DD + db;

    float4 tl0, tl1;
    ld_h8(g_proj + (size_t)node * PF + FF + off, tl0, tl1);
    float4 av0 = *(const float4*)(attn + off);
    float4 av1 = *(const float4*)(attn + off + 4);

    int beg = g_rowptr[node], end = g_rowptr[node + 1];
    float scale = logf((float)(end - beg)) * (1.0f / DD);

    float mloc = -1e30f;
    for (int p = beg; p < end; p++) {
        int s = g_srcs[p], r = g_rids[p];
        float4 fh0, fh1, fr0, fr1;
        ld_h8(g_proj + (size_t)s * PF + off, fh0, fh1);
        ld_h8(g_fr + (size_t)r * FF + off, fr0, fr1);
        float v = 0.f;
        {
            float x;
            x = fh0.x * tl0.x * fr0.x; x = (x > 0.f) ? x : SLOPE * x; v += x * av0.x;
            x = fh0.y * tl0.y * fr0.y; x = (x > 0.f) ? x : SLOPE * x; v += x * av0.y;
            x = fh0.z * tl0.z * fr0.z; x = (x > 0.f) ? x : SLOPE * x; v += x * av0.z;
            x = fh0.w * tl0.w * fr0.w; x = (x > 0.f) ? x : SLOPE * x; v += x * av0.w;
            x = fh1.x * tl1.x * fr1.x; x = (x > 0.f) ? x : SLOPE * x; v += x * av1.x;
            x = fh1.y * tl1.y * fr1.y; x = (x > 0.f) ? x : SLOPE * x; v += x * av1.y;
            x = fh1.z * tl1.z * fr1.z; x = (x > 0.f) ? x : SLOPE * x; v += x * av1.z;
            x = fh1.w * tl1.w * fr1.w; x = (x > 0.f) ? x : SLOPE * x; v += x * av1.w;
        }
        v += __shfl_xor_sync(0xffffffffu, v, 1);
        v += __shfl_xor_sync(0xffffffffu, v, 2);
        v *= scale;
        mloc = fmaxf(mloc, v);
        if ((lane & 3) == 0) g_e[p * HH + h] = v;
    }
    __syncwarp();

    const int hs = lane & 7, pi = lane >> 3;
    float m = __shfl_sync(0xffffffffu, mloc, hs * 4);
    float ssum = 0.f;
    for (int p = beg + pi; p < end; p += 4) ssum += expf(g_e[p * HH + hs] - m);
    ssum += __shfl_xor_sync(0xffffffffu, ssum, 8);
    ssum += __shfl_xor_sync(0xffffffffu, ssum, 16);
    float inv = 1.0f / ssum;
    for (int p = beg + pi; p < end; p += 4)
        g_a[p * HH + hs] = expf(g_e[p * HH + hs] - m) * inv;
    __syncwarp();

    // first hop: lane owns cols lane*8 .. lane*8+7
    const int col = lane * 8;
    float4 a0 = make_float4(0.f, 0.f, 0.f, 0.f);
    float4 a1 = make_float4(0.f, 0.f, 0.f, 0.f);
    int p = beg;
    for (; p + 2 <= end; p += 2) {
        int s0 = g_srcs[p], s1 = g_srcs[p + 1];
        float w0 = g_a[p * HH + h], w1 = g_a[(p + 1) * HH + h];
        float4 f00, f01, f10, f11;
        ld_h8(g_proj + (size_t)s0 * PF + 2 * FF + col, f00, f01);
        ld_h8(g_proj + (size_t)s1 * PF + 2 * FF + col, f10, f11);
        a0.x += w0 * f00.x + w1 * f10.x; a0.y += w0 * f00.y + w1 * f10.y;
        a0.z += w0 * f00.z + w1 * f10.z; a0.w += w0 * f00.w + w1 * f10.w;
        a1.x += w0 * f01.x + w1 * f11.x; a1.y += w0 * f01.y + w1 * f11.y;
        a1.z += w0 * f01.z + w1 * f11.z; a1.w += w0 * f01.w + w1 * f11.w;
    }
    for (; p < end; p++) {
        int s = g_srcs[p];
        float av = g_a[p * HH + h];
        float4 f0, f1;
        ld_h8(g_proj + (size_t)s * PF + 2 * FF + col, f0, f1);
        a0.x += av * f0.x; a0.y += av * f0.y; a0.z += av * f0.z; a0.w += av * f0.w;
        a1.x += av * f1.x; a1.y += av * f1.y; a1.z += av * f1.z; a1.w += av * f1.w;
    }
    float4 e0, e1;
    ld_h8(g_proj + (size_t)node * PF + 2 * FF + col, e0, e1);
    float4 o0, o1;
    o0.x = (1.0f - ALPHA) * a0.x + ALPHA * e0.x;
    o0.y = (1.0f - ALPHA) * a0.y + ALPHA * e0.y;
    o0.z = (1.0f - ALPHA) * a0.z + ALPHA * e0.z;
    o0.w = (1.0f - ALPHA) * a0.w + ALPHA * e0.w;
    o1.x = (1.0f - ALPHA) * a1.x + ALPHA * e1.x;
    o1.y = (1.0f - ALPHA) * a1.y + ALPHA * e1.y;
    o1.z = (1.0f - ALPHA) * a1.z + ALPHA * e1.z;
    o1.w = (1.0f - ALPHA) * a1.w + ALPHA * e1.w;
    st_h8(fout + (size_t)node * FF + col, o0, o1);
}

// ------------------------- diffusion hop (fp16 in; fp16 or fp32 out) ----------
__global__ void hop_kernel(const __half* __restrict__ fin,
                           __half* __restrict__ fout_h, float* __restrict__ fout_f,
                           const float* __restrict__ ent) {
    int w = (blockIdx.x * blockDim.x + threadIdx.x) >> 5;
    int lane = threadIdx.x & 31;
    if (w >= NN) return;
    int node = w;
    const int col = lane * 8;
    const int h = lane >> 2;
    int beg = g_rowptr[node], end = g_rowptr[node + 1];

    float4 a0 = make_float4(0.f, 0.f, 0.f, 0.f);
    float4 a1 = make_float4(0.f, 0.f, 0.f, 0.f);
    int p = beg;
    for (; p + 2 <= end; p += 2) {
        int s0 = g_srcs[p], s1 = g_srcs[p + 1];
        float w0 = g_a[p * HH + h], w1 = g_a[(p + 1) * HH + h];
        float4 f00, f01, f10, f11;
        ld_h8(fin + (size_t)s0 * FF + col, f00, f01);
        ld_h8(fin + (size_t)s1 * FF + col, f10, f11);
        a0.x += w0 * f00.x + w1 * f10.x; a0.y += w0 * f00.y + w1 * f10.y;
        a0.z += w0 * f00.z + w1 * f10.z; a0.w += w0 * f00.w + w1 * f10.w;
        a1.x += w0 * f01.x + w1 * f11.x; a1.y += w0 * f01.y + w1 * f11.y;
        a1.z += w0 * f01.z + w1 * f11.z; a1.w += w0 * f01.w + w1 * f11.w;
    }
    for (; p < end; p++) {
        int s = g_srcs[p];
        float av = g_a[p * HH + h];
        float4 f0, f1;
        ld_h8(fin + (size_t)s * FF + col, f0, f1);
        a0.x += av * f0.x; a0.y += av * f0.y; a0.z += av * f0.z; a0.w += av * f0.w;
        a1.x += av * f1.x; a1.y += av * f1.y; a1.z += av * f1.z; a1.w += av * f1.w;
    }
    float4 e0, e1;
    ld_h8(g_proj + (size_t)node * PF + 2 * FF + col, e0, e1);
    float4 o0, o1;
    o0.x = (1.0f - ALPHA) * a0.x + ALPHA * e0.x;
    o0.y = (1.0f - ALPHA) * a0.y + ALPHA * e0.y;
    o0.z = (1.0f - ALPHA) * a0.z + ALPHA * e0.z;
    o0.w = (1.0f - ALPHA) * a0.w + ALPHA * e0.w;
    o1.x = (1.0f - ALPHA) * a1.x + ALPHA * e1.x;
    o1.y = (1.0f - ALPHA) * a1.y + ALPHA * e1.y;
    o1.z = (1.0f - ALPHA) * a1.z + ALPHA * e1.z;
    o1.w = (1.0f - ALPHA) * a1.w + ALPHA * e1.w;
    if (fout_f) {
        const float* ep = ent + (size_t)node * FF + col;
        float4 n0 = *(const float4*)(ep);
        float4 n1 = *(const float4*)(ep + 4);
        o0.x += n0.x; o0.y += n0.y; o0.z += n0.z; o0.w += n0.w;
        o1.x += n1.x; o1.y += n1.y; o1.z += n1.z; o1.w += n1.w;
        float* op = fout_f + (size_t)node * FF + col;
        *(float4*)(op) = o0;
        *(float4*)(op + 4) = o1;
    } else {
        st_h8(fout_h + (size_t)node * FF + col, o0, o1);
    }
}

// ------------------------- launcher -------------------------------------------
extern "C" void kernel_launch(void* const* d_in, const int* in_sizes, int n_in,
                              void* d_out, int out_size) {
    const float* ent_feat = (const float*)d_in[0];
    const float* rel_feat = (const float*)d_in[1];
    const float* W_head   = (const float*)d_in[2];
    const float* W_tail   = (const float*)d_in[3];
    const float* W_ent    = (const float*)d_in[4];
    const float* W_rel    = (const float*)d_in[5];
    const float* attn     = (const float*)d_in[6];
    const float* ln_ent_g = (const float*)d_in[7];
    const float* ln_ent_b = (const float*)d_in[8];
    const float* ln_rel_g = (const float*)d_in[9];
    const float* ln_rel_b = (const float*)d_in[10];
    const float* ln_ff_g  = (const float*)d_in[11];
    const float* ln_ff_b  = (const float*)d_in[12];
    const float* W1       = (const float*)d_in[13];
    const float* b1       = (const float*)d_in[14];
    const float* W2       = (const float*)d_in[15];
    const float* b2       = (const float*)d_in[16];
    const int*   src      = (const int*)d_in[17];
    const int*   dst      = (const int*)d_in[18];
    const int*   rid      = (const int*)d_in[19];
    float* out = (float*)d_out;

    cudaFuncSetAttribute(mma_gemm, cudaFuncAttributeMaxDynamicSharedMemorySize, GSMEM_BYTES);

    float *rst;
    __half *xln, *proj, *rln, *fr, *fa, *fb, *y, *hid, *wcat, *wrel, *w1T, *w2T;
    int *cnt;
    cudaGetSymbolAddress((void**)&xln,  g_xln);
    cudaGetSymbolAddress((void**)&proj, g_proj);
    cudaGetSymbolAddress((void**)&rln,  g_rln);
    cudaGetSymbolAddress((void**)&fr,   g_fr);
    cudaGetSymbolAddress((void**)&fa,   g_fa);
    cudaGetSymbolAddress((void**)&fb,   g_fb);
    cudaGetSymbolAddress((void**)&rst,  g_rst);
    cudaGetSymbolAddress((void**)&y,    g_y);
    cudaGetSymbolAddress((void**)&hid,  g_hid);
    cudaGetSymbolAddress((void**)&wcat, g_wcatT);
    cudaGetSymbolAddress((void**)&wrel, g_wrelT);
    cudaGetSymbolAddress((void**)&w1T,  g_w1T);
    cudaGetSymbolAddress((void**)&w2T,  g_w2T);
    cudaGetSymbolAddress((void**)&cnt,  g_cnt);

    // 0) transpose + fp16-round weights; zero CSR counters
    cudaMemsetAsync(cnt, 0, NN * sizeof(int));
    dim3 tb(32, 8);
    transpose4_rnd<<<dim3(FF / 32, FF / 32, 4), tb>>>(W_head, W_tail, W_ent, W_rel, wcat, wrel);
    transpose_rnd<<<dim3(FHID / 32, FF / 32), tb>>>(W1, w1T, FF, FHID);
    transpose_rnd<<<dim3(FF / 32, FHID / 32), tb>>>(W2, w2T, FHID, FF);

    // 1) LayerNorms (fp16 outputs; only consumed by GEMMs)
    ln_kernel<<<(NN + 7) / 8, 256>>>(ent_feat, xln, ln_ent_g, ln_ent_b, NN);
    ln_kernel<<<(RR + 7) / 8, 256>>>(rel_feat, rln, ln_rel_g, ln_rel_b, RR);

    // 2) Projections: rel + fused head/tail/ent (Nc=768), fp16 outputs
    const int mT = (NN + 127) / 128;   // 157
    mma_gemm<<<dim3(FF / 128, 1), 256, GSMEM_BYTES>>>(rln, wrel, fr, RR, FF, FF, nullptr, nullptr, 2);
    mma_gemm<<<dim3(PF / 128, mT), 256, GSMEM_BYTES>>>(xln, wcat, proj, NN, PF, FF, nullptr, nullptr, 2);

    // 3) CSR build (sorted by dst)
    count_kernel<<<(EE + 255) / 256, 256>>>(dst);
    scan_kernel<<<1, 1024>>>();
    scatter_kernel<<<(EE + 255) / 256, 256>>>(src, dst, rid);

    // 4) edge attention + softmax + hop 1 (fused) -> fa (fp16)
    attn_hop1_kernel<<<NN / 8, 256>>>(attn, fa);

    // 5) remaining 4 PPR hops (ping-pong fp16), last writes fp32 rst (+ent)
    hop_kernel<<<NN / 8, 256>>>(fa, fb, nullptr, nullptr);
    hop_kernel<<<NN / 8, 256>>>(fb, fa, nullptr, nullptr);
    hop_kernel<<<NN / 8, 256>>>(fa, fb, nullptr, nullptr);
    hop_kernel<<<NN / 8, 256>>>(fb, nullptr, rst, ent_feat);

    // 6) FFN with pre-LN and residual
    ln_kernel<<<(NN + 7) / 8, 256>>>(rst, y, ln_ff_g, ln_ff_b, NN);
    mma_gemm<<<dim3(FHID / 128, mT), 256, GSMEM_BYTES>>>(y, w1T, hid, NN, FHID, FF, b1, nullptr, 1 | 2);
    mma_gemm<<<dim3(FF / 128, mT), 256, GSMEM_BYTES>>>(hid, w2T, out, NN, FF, FHID, b2, rst, 0);
}

// round 12
// speedup vs baseline: 2.7834x; 1.0992x over previous
#include <cuda_runtime.h>
#include <cuda_fp16.h>
#include <math.h>
#include <stdint.h>

// Problem constants
#define NN 20000
#define EE 320000
#define RR 100
#define FF 256
#define HH 8
#define DD 32
#define FHID 1024
#define PF 768            // packed projection stride (fh|ftl|fen)
#define ALPHA 0.1f
#define SLOPE 0.2f

// ---------------------------------------------------------------------------
__device__ __forceinline__ uint32_t smem_u32(const void* p) {
    uint32_t a;
    asm("{ .reg .u64 t; cvta.to.shared.u64 t, %1; cvt.u32.u64 %0, t; }" : "=r"(a) : "l"(p));
    return a;
}
#define CP_ASYNC16(dst, src) \
    asm volatile("cp.async.cg.shared.global [%0], [%1], 16;" :: "r"(dst), "l"(src) : "memory")
#define CP_COMMIT() asm volatile("cp.async.commit_group;" ::: "memory")
#define CP_WAIT(n)  asm volatile("cp.async.wait_group %0;" :: "n"(n) : "memory")

#define LDSM_X4(r0, r1, r2, r3, addr) \
    asm volatile("ldmatrix.sync.aligned.m8n8.x4.shared.b16 {%0,%1,%2,%3}, [%4];" \
                 : "=r"(r0), "=r"(r1), "=r"(r2), "=r"(r3) : "r"(addr))
#define MMA_F16(c, a, b) \
    asm volatile("mma.sync.aligned.m16n8k16.row.col.f32.f16.f16.f32 " \
                 "{%0,%1,%2,%3},{%4,%5,%6,%7},{%8,%9},{%0,%1,%2,%3};" \
                 : "+f"((c)[0]), "+f"((c)[1]), "+f"((c)[2]), "+f"((c)[3]) \
                 : "r"((a)[0]), "r"((a)[1]), "r"((a)[2]), "r"((a)[3]), \
                   "r"((b)[0]), "r"((b)[1]))

// load/store 8 halves as 2x float4 (fp32 math in registers)
__device__ __forceinline__ void ld_h8(const __half* p, float4& f0, float4& f1) {
    uint4 u = *(const uint4*)(p);
    const __half2* h = (const __half2*)&u;
    float2 a = __half22float2(h[0]);
    float2 b = __half22float2(h[1]);
    float2 c = __half22float2(h[2]);
    float2 d = __half22float2(h[3]);
    f0 = make_float4(a.x, a.y, b.x, b.y);
    f1 = make_float4(c.x, c.y, d.x, d.y);
}
__device__ __forceinline__ void st_h8(__half* p, float4 f0, float4 f1) {
    __half2 h0 = __floats2half2_rn(f0.x, f0.y);
    __half2 h1 = __floats2half2_rn(f0.z, f0.w);
    __half2 h2 = __floats2half2_rn(f1.x, f1.y);
    __half2 h3 = __floats2half2_rn(f1.z, f1.w);
    uint4 u;
    u.x = *(uint32_t*)&h0; u.y = *(uint32_t*)&h1;
    u.z = *(uint32_t*)&h2; u.w = *(uint32_t*)&h3;
    *(uint4*)(p) = u;
}

// ------------------------- scratch (device globals) -------------------------
__device__ __half g_xln[NN * FF];
__device__ __half g_proj[NN * PF];      // [fh | ftl | fen] packed per row (fp16)
__device__ __half g_rln[RR * FF];
__device__ __half g_fr [RR * FF];
__device__ int    g_cnt [NN];
__device__ int    g_perm[EE];
__device__ int    g_rowptr[NN + 1];
__device__ int    g_srcs[EE];
__device__ int    g_rids[EE];
__device__ float  g_e[EE * HH];
__device__ float  g_a[EE * HH];
__device__ __half g_fa[NN * FF];
__device__ __half g_fb[NN * FF];
__device__ float  g_rst[NN * FF];
__device__ __half g_y  [NN * FF];
__device__ __half g_hid[NN * FHID];
__device__ __half g_wcatT[PF * FF];
__device__ __half g_wrelT [FF * FF];
__device__ __half g_w1T[FHID * FF];
__device__ __half g_w2T[FF * FHID];

// ------------------------- LayerNorm (warp per row, fp16 out) -----------------
__global__ void ln_kernel(const float* __restrict__ in, __half* __restrict__ out,
                          const float* __restrict__ gam, const float* __restrict__ bet,
                          int rows) {
    int warp = threadIdx.x >> 5;
    int row = blockIdx.x * 8 + warp;
    if (row >= rows) return;
    int lane = threadIdx.x & 31;
    const int col = lane * 8;
    const float* ip = in + (size_t)row * FF + col;
    float4 x0 = *(const float4*)(ip);
    float4 x1 = *(const float4*)(ip + 4);
    float s  = x0.x + x0.y + x0.z + x0.w + x1.x + x1.y + x1.z + x1.w;
    float s2 = x0.x*x0.x + x0.y*x0.y + x0.z*x0.z + x0.w*x0.w
             + x1.x*x1.x + x1.y*x1.y + x1.z*x1.z + x1.w*x1.w;
    #pragma unroll
    for (int o = 16; o; o >>= 1) {
        s  += __shfl_xor_sync(0xffffffffu, s,  o);
        s2 += __shfl_xor_sync(0xffffffffu, s2, o);
    }
    float m = s * (1.0f / FF);
    float var = s2 * (1.0f / FF) - m * m;
    float inv = rsqrtf(var + 1e-5f);
    float4 gg0 = *(const float4*)(gam + col);
    float4 gg1 = *(const float4*)(gam + col + 4);
    float4 bb0 = *(const float4*)(bet + col);
    float4 bb1 = *(const float4*)(bet + col + 4);
    float4 o0, o1;
    o0.x = (x0.x - m) * inv * gg0.x + bb0.x;
    o0.y = (x0.y - m) * inv * gg0.y + bb0.y;
    o0.z = (x0.z - m) * inv * gg0.z + bb0.z;
    o0.w = (x0.w - m) * inv * gg0.w + bb0.w;
    o1.x = (x1.x - m) * inv * gg1.x + bb1.x;
    o1.y = (x1.y - m) * inv * gg1.y + bb1.y;
    o1.z = (x1.z - m) * inv * gg1.z + bb1.z;
    o1.w = (x1.w - m) * inv * gg1.w + bb1.w;
    st_h8(out + (size_t)row * FF + col, o0, o1);
}

// ------------------------- weight transpose (fp32 -> fp16 K-major) -----------
__global__ void transpose_rnd(const float* __restrict__ B, __half* __restrict__ BT,
                              int K, int N) {
    __shared__ float t[32][33];
    int n0 = blockIdx.x * 32, k0 = blockIdx.y * 32;
    int x = threadIdx.x, y = threadIdx.y;
    #pragma unroll
    for (int r = 0; r < 32; r += 8)
        t[y + r][x] = B[(size_t)(k0 + y + r) * N + n0 + x];
    __syncthreads();
    #pragma unroll
    for (int r = 0; r < 32; r += 8)
        BT[(size_t)(n0 + y + r) * K + k0 + x] = __float2half_rn(t[x][y + r]);
}
__global__ void transpose4_rnd(const float* __restrict__ Wh, const float* __restrict__ Wt,
                               const float* __restrict__ We, const float* __restrict__ Wr,
                               __half* __restrict__ wcat, __half* __restrict__ wrel) {
    __shared__ float t[32][33];
    int z = blockIdx.z;
    const float* B = (z == 0) ? Wh : (z == 1) ? Wt : (z == 2) ? We : Wr;
    __half* BT = (z < 3) ? (wcat + (size_t)z * FF * FF) : wrel;
    int n0 = blockIdx.x * 32, k0 = blockIdx.y * 32;
    int x = threadIdx.x, y = threadIdx.y;
    #pragma unroll
    for (int r = 0; r < 32; r += 8)
        t[y + r][x] = B[(size_t)(k0 + y + r) * FF + n0 + x];
    __syncthreads();
    #pragma unroll
    for (int r = 0; r < 32; r += 8)
        BT[(size_t)(n0 + y + r) * FF + k0 + x] = __float2half_rn(t[x][y + r]);
}

// ------------------------- fp16 mma.sync GEMM (R8 config) --------------------
#define GSTAGES 3
#define GSTG 32768
#define GSMEM_BYTES (GSTAGES * GSTG)

__global__ void __launch_bounds__(256, 2)
mma_gemm(const __half* __restrict__ A, const __half* __restrict__ BT,
         void* __restrict__ Cv, int M, int Nc, int K,
         const float* __restrict__ bias, const float* __restrict__ res, int mode) {
    extern __shared__ float smemf[];
    const uint32_t sb = smem_u32(smemf);

    const int m0 = blockIdx.y * 128;
    const int n0 = blockIdx.x * 128;
    const int tid = threadIdx.x;
    const int warp = tid >> 5, lane = tid & 31;
    const int wm = warp >> 2, wn = warp & 3;

    const int lrow = tid >> 1, lhalf = tid & 1;
    int aRow = m0 + lrow; if (aRow >= M) aRow = M - 1;
    const __half* aG = A + (size_t)aRow * K + lhalf * 32;
    const __half* bG = BT + (size_t)(n0 + lrow) * K + lhalf * 32;
    const uint32_t sA = sb + (uint32_t)lrow * 128;
    const uint32_t sB = sb + 16384 + (uint32_t)lrow * 128;
    uint32_t swz[4];
    #pragma unroll
    for (int j = 0; j < 4; j++)
        swz[j] = (uint32_t)(((lhalf * 4 + j) ^ (lrow & 7)) << 4);

    const int nCh = K >> 6;

    float c[4][4][4];
    #pragma unroll
    for (int mt = 0; mt < 4; mt++)
        #pragma unroll
        for (int nt = 0; nt < 4; nt++)
            #pragma unroll
            for (int q = 0; q < 4; q++) c[mt][nt][q] = 0.f;

    #pragma unroll
    for (int s = 0; s < 2; s++) {
        const uint32_t off = (uint32_t)s * GSTG;
        const __half* ag = aG + s * 64;
        const __half* bg = bG + s * 64;
        #pragma unroll
        for (int j = 0; j < 4; j++) CP_ASYNC16(sA + off + swz[j], ag + j * 8);
        #pragma unroll
        for (int j = 0; j < 4; j++) CP_ASYNC16(sB + off + swz[j], bg + j * 8);
        CP_COMMIT();
    }

    const int q8 = lane >> 3, r8 = lane & 7;

    for (int i = 0; i < nCh; i++) {
        __syncthreads();
        if (i + 2 < nCh) {
            const uint32_t off = (uint32_t)((i + 2) % GSTAGES) * GSTG;
            const __half* ag = aG + (i + 2) * 64;
            const __half* bg = bG + (i + 2) * 64;
            #pragma unroll
            for (int j = 0; j < 4; j++) CP_ASYNC16(sA + off + swz[j], ag + j * 8);
            #pragma unroll
            for (int j = 0; j < 4; j++) CP_ASYNC16(sB + off + swz[j], bg + j * 8);
        }
        CP_COMMIT();
        CP_WAIT(2);
        __syncthreads();

        const uint32_t Ab = sb + (uint32_t)(i % GSTAGES) * GSTG;
        const uint32_t Bb = Ab + 16384;
        #pragma unroll
        for (int ks = 0; ks < 4; ks++) {
            uint32_t a[4][4];
            #pragma unroll
            for (int mt = 0; mt < 4; mt++) {
                const int rl = wm * 64 + mt * 16 + (q8 & 1) * 8 + r8;
                const int kc = ks * 2 + (q8 >> 1);
                const uint32_t ad = Ab + (uint32_t)rl * 128 + (uint32_t)((kc ^ (rl & 7)) << 4);
                LDSM_X4(a[mt][0], a[mt][1], a[mt][2], a[mt][3], ad);
            }
            uint32_t b[4][2];
            #pragma unroll
            for (int p = 0; p < 2; p++) {
                const int nl = wn * 32 + (p * 2 + (q8 >> 1)) * 8 + r8;
                const int kc = ks * 2 + (q8 & 1);
                const uint32_t bd = Bb + (uint32_t)nl * 128 + (uint32_t)((kc ^ (nl & 7)) << 4);
                LDSM_X4(b[p * 2][0], b[p * 2][1], b[p * 2 + 1][0], b[p * 2 + 1][1], bd);
            }
            #pragma unroll
            for (int mt = 0; mt < 4; mt++)
                #pragma unroll
                for (int nt = 0; nt < 4; nt++)
                    MMA_F16(c[mt][nt], a[mt], b[nt]);
        }
    }

    const int g = lane >> 2, t4 = lane & 3;
    #pragma unroll
    for (int mt = 0; mt < 4; mt++) {
        #pragma unroll
        for (int half = 0; half < 2; half++) {
            const int m = m0 + wm * 64 + mt * 16 + g + half * 8;
            if (m < M) {
                #pragma unroll
                for (int nt = 0; nt < 4; nt++) {
                    const int colb = nt * 8 + 2 * t4;
                    const int col = n0 + wn * 32 + colb;
                    float v0 = c[mt][nt][half * 2 + 0];
                    float v1 = c[mt][nt][half * 2 + 1];
                    if (bias) { v0 += bias[col]; v1 += bias[col + 1]; }
                    if (mode & 1) { v0 = fmaxf(v0, 0.f); v1 = fmaxf(v1, 0.f); }
                    if (mode & 2) {
                        __half2 hv = __floats2half2_rn(v0, v1);
                        *(__half2*)((__half*)Cv + (size_t)m * Nc + col) = hv;
                    } else {
                        if (res) {
                            const float* rp = res + (size_t)m * Nc + col;
                            v0 += rp[0]; v1 += rp[1];
                        }
                        float2 v; v.x = v0; v.y = v1;
                        *(float2*)((float*)Cv + (size_t)m * Nc + col) = v;
                    }
                }
            }
        }
    }
}

// ------------------------- CSR build -----------------------------------------
__global__ void count_kernel(const int* __restrict__ dst) {
    int i = blockIdx.x * blockDim.x + threadIdx.x;
    if (i < EE) g_perm[i] = atomicAdd(&g_cnt[dst[i]], 1);
}
__global__ void scan_kernel() {
    __shared__ int ss[1024];
    int t = threadIdx.x;
    const int CH = (NN + 1023) / 1024;
    int base = t * CH;
    int loc = 0;
    for (int i = 0; i < CH; i++) {
        int idx = base + i;
        if (idx < NN) loc += g_cnt[idx];
    }
    ss[t] = loc;
    __syncthreads();
    for (int off = 1; off < 1024; off <<= 1) {
        int v = (t >= off) ? ss[t - off] : 0;
        __syncthreads();
        ss[t] += v;
        __syncthreads();
    }
    int run = (t == 0) ? 0 : ss[t - 1];
    for (int i = 0; i < CH; i++) {
        int idx = base + i;
        if (idx < NN) { g_rowptr[idx] = run; run += g_cnt[idx]; }
    }
    if (t == 0) g_rowptr[NN] = EE;
}
__global__ void scatter_kernel(const int* __restrict__ src, const int* __restrict__ dst,
                               const int* __restrict__ rid) {
    int i = blockIdx.x * blockDim.x + threadIdx.x;
    if (i < EE) {
        int pos = g_rowptr[dst[i]] + g_perm[i];
        g_srcs[pos] = src[i];
        g_rids[pos] = rid[i];
    }
}

// ---------------- edge attention + softmax + first PPR hop -------------------
__global__ void attn_hop1_kernel(const float* __restrict__ attn,
                                 __half* __restrict__ fout) {
    int w = (blockIdx.x * blockDim.x + threadIdx.x) >> 5;
    int lane = threadIdx.x & 31;
    if (w >= NN) return;
    int node = w;
    const int h = lane >> 2;
    const int db = (lane & 3) * 8;
    const int off = h * DD + db;

    float4 tl0, tl1;
    ld_h8(g_proj + (size_t)node * PF + FF + off, tl0, tl1);
    float4 av0 = *(const float4*)(attn + off);
    float4 av1 = *(const float4*)(attn + off + 4);

    int beg = g_rowptr[node], end = g_rowptr[node + 1];
    float scale = logf((float)(end - beg)) * (1.0f / DD);

    float mloc = -1e30f;
    for (int p = beg; p < end; p++) {
        int s = g_srcs[p], r = g_rids[p];
        float4 fh0, fh1, fr0, fr1;
        ld_h8(g_proj + (size_t)s * PF + off, fh0, fh1);
        ld_h8(g_fr + (size_t)r * FF + off, fr0, fr1);
        float v = 0.f;
        {
            float x;
            x = fh0.x * tl0.x * fr0.x; x = (x > 0.f) ? x : SLOPE * x; v += x * av0.x;
            x = fh0.y * tl0.y * fr0.y; x = (x > 0.f) ? x : SLOPE * x; v += x * av0.y;
            x = fh0.z * tl0.z * fr0.z; x = (x > 0.f) ? x : SLOPE * x; v += x * av0.z;
            x = fh0.w * tl0.w * fr0.w; x = (x > 0.f) ? x : SLOPE * x; v += x * av0.w;
            x = fh1.x * tl1.x * fr1.x; x = (x > 0.f) ? x : SLOPE * x; v += x * av1.x;
            x = fh1.y * tl1.y * fr1.y; x = (x > 0.f) ? x : SLOPE * x; v += x * av1.y;
            x = fh1.z * tl1.z * fr1.z; x = (x > 0.f) ? x : SLOPE * x; v += x * av1.z;
            x = fh1.w * tl1.w * fr1.w; x = (x > 0.f) ? x : SLOPE * x; v += x * av1.w;
        }
        v += __shfl_xor_sync(0xffffffffu, v, 1);
        v += __shfl_xor_sync(0xffffffffu, v, 2);
        v *= scale;
        mloc = fmaxf(mloc, v);
        if ((lane & 3) == 0) g_e[p * HH + h] = v;
    }
    __syncwarp();

    const int hs = lane & 7, pi = lane >> 3;
    float m = __shfl_sync(0xffffffffu, mloc, hs * 4);
    float ssum = 0.f;
    for (int p = beg + pi; p < end; p += 4) ssum += expf(g_e[p * HH + hs] - m);
    ssum += __shfl_xor_sync(0xffffffffu, ssum, 8);
    ssum += __shfl_xor_sync(0xffffffffu, ssum, 16);
    float inv = 1.0f / ssum;
    for (int p = beg + pi; p < end; p += 4)
        g_a[p * HH + hs] = expf(g_e[p * HH + hs] - m) * inv;
    __syncwarp();

    const int col = lane * 8;
    float4 a0 = make_float4(0.f, 0.f, 0.f, 0.f);
    float4 a1 = make_float4(0.f, 0.f, 0.f, 0.f);
    int p = beg;
    for (; p + 2 <= end; p += 2) {
        int s0 = g_srcs[p], s1 = g_srcs[p + 1];
        float w0 = g_a[p * HH + h], w1 = g_a[(p + 1) * HH + h];
        float4 f00, f01, f10, f11;
        ld_h8(g_proj + (size_t)s0 * PF + 2 * FF + col, f00, f01);
        ld_h8(g_proj + (size_t)s1 * PF + 2 * FF + col, f10, f11);
        a0.x += w0 * f00.x + w1 * f10.x; a0.y += w0 * f00.y + w1 * f10.y;
        a0.z += w0 * f00.z + w1 * f10.z; a0.w += w0 * f00.w + w1 * f10.w;
        a1.x += w0 * f01.x + w1 * f11.x; a1.y += w0 * f01.y + w1 * f11.y;
        a1.z += w0 * f01.z + w1 * f11.z; a1.w += w0 * f01.w + w1 * f11.w;
    }
    for (; p < end; p++) {
        int s = g_srcs[p];
        float av = g_a[p * HH + h];
        float4 f0, f1;
        ld_h8(g_proj + (size_t)s * PF + 2 * FF + col, f0, f1);
        a0.x += av * f0.x; a0.y += av * f0.y; a0.z += av * f0.z; a0.w += av * f0.w;
        a1.x += av * f1.x; a1.y += av * f1.y; a1.z += av * f1.z; a1.w += av * f1.w;
    }
    float4 e0, e1;
    ld_h8(g_proj + (size_t)node * PF + 2 * FF + col, e0, e1);
    float4 o0, o1;
    o0.x = (1.0f - ALPHA) * a0.x + ALPHA * e0.x;
    o0.y = (1.0f - ALPHA) * a0.y + ALPHA * e0.y;
    o0.z = (1.0f - ALPHA) * a0.z + ALPHA * e0.z;
    o0.w = (1.0f - ALPHA) * a0.w + ALPHA * e0.w;
    o1.x = (1.0f - ALPHA) * a1.x + ALPHA * e1.x;
    o1.y = (1.0f - ALPHA) * a1.y + ALPHA * e1.y;
    o1.z = (1.0f - ALPHA) * a1.z + ALPHA * e1.z;
    o1.w = (1.0f - ALPHA) * a1.w + ALPHA * e1.w;
    st_h8(fout + (size_t)node * FF + col, o0, o1);
}

// ------------------------- diffusion hop (fp16 -> fp16) -----------------------
__global__ void hop_kernel(const __half* __restrict__ fin, __half* __restrict__ fout) {
    int w = (blockIdx.x * blockDim.x + threadIdx.x) >> 5;
    int lane = threadIdx.x & 31;
    if (w >= NN) return;
    int node = w;
    const int col = lane * 8;
    const int h = lane >> 2;
    int beg = g_rowptr[node], end = g_rowptr[node + 1];

    float4 a0 = make_float4(0.f, 0.f, 0.f, 0.f);
    float4 a1 = make_float4(0.f, 0.f, 0.f, 0.f);
    int p = beg;
    for (; p + 2 <= end; p += 2) {
        int s0 = g_srcs[p], s1 = g_srcs[p + 1];
        float w0 = g_a[p * HH + h], w1 = g_a[(p + 1) * HH + h];
        float4 f00, f01, f10, f11;
        ld_h8(fin + (size_t)s0 * FF + col, f00, f01);
        ld_h8(fin + (size_t)s1 * FF + col, f10, f11);
        a0.x += w0 * f00.x + w1 * f10.x; a0.y += w0 * f00.y + w1 * f10.y;
        a0.z += w0 * f00.z + w1 * f10.z; a0.w += w0 * f00.w + w1 * f10.w;
        a1.x += w0 * f01.x + w1 * f11.x; a1.y += w0 * f01.y + w1 * f11.y;
        a1.z += w0 * f01.z + w1 * f11.z; a1.w += w0 * f01.w + w1 * f11.w;
    }
    for (; p < end; p++) {
        int s = g_srcs[p];
        float av = g_a[p * HH + h];
        float4 f0, f1;
        ld_h8(fin + (size_t)s * FF + col, f0, f1);
        a0.x += av * f0.x; a0.y += av * f0.y; a0.z += av * f0.z; a0.w += av * f0.w;
        a1.x += av * f1.x; a1.y += av * f1.y; a1.z += av * f1.z; a1.w += av * f1.w;
    }
    float4 e0, e1;
    ld_h8(g_proj + (size_t)node * PF + 2 * FF + col, e0, e1);
    float4 o0, o1;
    o0.x = (1.0f - ALPHA) * a0.x + ALPHA * e0.x;
    o0.y = (1.0f - ALPHA) * a0.y + ALPHA * e0.y;
    o0.z = (1.0f - ALPHA) * a0.z + ALPHA * e0.z;
    o0.w = (1.0f - ALPHA) * a0.w + ALPHA * e0.w;
    o1.x = (1.0f - ALPHA) * a1.x + ALPHA * e1.x;
    o1.y = (1.0f - ALPHA) * a1.y + ALPHA * e1.y;
    o1.z = (1.0f - ALPHA) * a1.z + ALPHA * e1.z;
    o1.w = (1.0f - ALPHA) * a1.w + ALPHA * e1.w;
    st_h8(fout + (size_t)node * FF + col, o0, o1);
}

// ---------- last hop: + ent residual -> rst (fp32) AND y = LN(rst) (fp16) -----
__global__ void hop_last_ln_kernel(const __half* __restrict__ fin,
                                   float* __restrict__ rst, __half* __restrict__ yout,
                                   const float* __restrict__ ent,
                                   const float* __restrict__ gam,
                                   const float* __restrict__ bet) {
    int w = (blockIdx.x * blockDim.x + threadIdx.x) >> 5;
    int lane = threadIdx.x & 31;
    if (w >= NN) return;
    int node = w;
    const int col = lane * 8;
    const int h = lane >> 2;
    int beg = g_rowptr[node], end = g_rowptr[node + 1];

    float4 a0 = make_float4(0.f, 0.f, 0.f, 0.f);
    float4 a1 = make_float4(0.f, 0.f, 0.f, 0.f);
    int p = beg;
    for (; p + 2 <= end; p += 2) {
        int s0 = g_srcs[p], s1 = g_srcs[p + 1];
        float w0 = g_a[p * HH + h], w1 = g_a[(p + 1) * HH + h];
        float4 f00, f01, f10, f11;
        ld_h8(fin + (size_t)s0 * FF + col, f00, f01);
        ld_h8(fin + (size_t)s1 * FF + col, f10, f11);
        a0.x += w0 * f00.x + w1 * f10.x; a0.y += w0 * f00.y + w1 * f10.y;
        a0.z += w0 * f00.z + w1 * f10.z; a0.w += w0 * f00.w + w1 * f10.w;
        a1.x += w0 * f01.x + w1 * f11.x; a1.y += w0 * f01.y + w1 * f11.y;
        a1.z += w0 * f01.z + w1 * f11.z; a1.w += w0 * f01.w + w1 * f11.w;
    }
    for (; p < end; p++) {
        int s = g_srcs[p];
        float av = g_a[p * HH + h];
        float4 f0, f1;
        ld_h8(fin + (size_t)s * FF + col, f0, f1);
        a0.x += av * f0.x; a0.y += av * f0.y; a0.z += av * f0.z; a0.w += av * f0.w;
        a1.x += av * f1.x; a1.y += av * f1.y; a1.z += av * f1.z; a1.w += av * f1.w;
    }
    float4 e0, e1;
    ld_h8(g_proj + (size_t)node * PF + 2 * FF + col, e0, e1);
    const float* ep = ent + (size_t)node * FF + col;
    float4 n0 = *(const float4*)(ep);
    float4 n1 = *(const float4*)(ep + 4);
    float4 o0, o1;
    o0.x = (1.0f - ALPHA) * a0.x + ALPHA * e0.x + n0.x;
    o0.y = (1.0f - ALPHA) * a0.y + ALPHA * e0.y + n0.y;
    o0.z = (1.0f - ALPHA) * a0.z + ALPHA * e0.z + n0.z;
    o0.w = (1.0f - ALPHA) * a0.w + ALPHA * e0.w + n0.w;
    o1.x = (1.0f - ALPHA) * a1.x + ALPHA * e1.x + n1.x;
    o1.y = (1.0f - ALPHA) * a1.y + ALPHA * e1.y + n1.y;
    o1.z = (1.0f - ALPHA) * a1.z + ALPHA * e1.z + n1.z;
    o1.w = (1.0f - ALPHA) * a1.w + ALPHA * e1.w + n1.w;
    float* rp = rst + (size_t)node * FF + col;
    *(float4*)(rp) = o0;
    *(float4*)(rp + 4) = o1;

    // fused LayerNorm over the row this warp owns entirely
    float s  = o0.x + o0.y + o0.z + o0.w + o1.x + o1.y + o1.z + o1.w;
    float s2 = o0.x*o0.x + o0.y*o0.y + o0.z*o0.z + o0.w*o0.w
             + o1.x*o1.x + o1.y*o1.y + o1.z*o1.z + o1.w*o1.w;
    #pragma unroll
    for (int o = 16; o; o >>= 1) {
        s  += __shfl_xor_sync(0xffffffffu, s,  o);
        s2 += __shfl_xor_sync(0xffffffffu, s2, o);
    }
    float m = s * (1.0f / FF);
    float var = s2 * (1.0f / FF) - m * m;
    float inv = rsqrtf(var + 1e-5f);
    float4 gg0 = *(const float4*)(gam + col);
    float4 gg1 = *(const float4*)(gam + col + 4);
    float4 bb0 = *(const float4*)(bet + col);
    float4 bb1 = *(const float4*)(bet + col + 4);
    float4 y0, y1;
    y0.x = (o0.x - m) * inv * gg0.x + bb0.x;
    y0.y = (o0.y - m) * inv * gg0.y + bb0.y;
    y0.z = (o0.z - m) * inv * gg0.z + bb0.z;
    y0.w = (o0.w - m) * inv * gg0.w + bb0.w;
    y1.x = (o1.x - m) * inv * gg1.x + bb1.x;
    y1.y = (o1.y - m) * inv * gg1.y + bb1.y;
    y1.z = (o1.z - m) * inv * gg1.z + bb1.z;
    y1.w = (o1.w - m) * inv * gg1.w + bb1.w;
    st_h8(yout + (size_t)node * FF + col, y0, y1);
}

// ------------------------- launcher -------------------------------------------
extern "C" void kernel_launch(void* const* d_in, const int* in_sizes, int n_in,
                              void* d_out, int out_size) {
    const float* ent_feat = (const float*)d_in[0];
    const float* rel_feat = (const float*)d_in[1];
    const float* W_head   = (const float*)d_in[2];
    const float* W_tail   = (const float*)d_in[3];
    const float* W_ent    = (const float*)d_in[4];
    const float* W_rel    = (const float*)d_in[5];
    const float* attn     = (const float*)d_in[6];
    const float* ln_ent_g = (const float*)d_in[7];
    const float* ln_ent_b = (const float*)d_in[8];
    const float* ln_rel_g = (const float*)d_in[9];
    const float* ln_rel_b = (const float*)d_in[10];
    const float* ln_ff_g  = (const float*)d_in[11];
    const float* ln_ff_b  = (const float*)d_in[12];
    const float* W1       = (const float*)d_in[13];
    const float* b1       = (const float*)d_in[14];
    const float* W2       = (const float*)d_in[15];
    const float* b2       = (const float*)d_in[16];
    const int*   src      = (const int*)d_in[17];
    const int*   dst      = (const int*)d_in[18];
    const int*   rid      = (const int*)d_in[19];
    float* out = (float*)d_out;

    cudaFuncSetAttribute(mma_gemm, cudaFuncAttributeMaxDynamicSharedMemorySize, GSMEM_BYTES);

    float *rst;
    __half *xln, *proj, *rln, *fr, *fa, *fb, *y, *hid, *wcat, *wrel, *w1T, *w2T;
    int *cnt;
    cudaGetSymbolAddress((void**)&xln,  g_xln);
    cudaGetSymbolAddress((void**)&proj, g_proj);
    cudaGetSymbolAddress((void**)&rln,  g_rln);
    cudaGetSymbolAddress((void**)&fr,   g_fr);
    cudaGetSymbolAddress((void**)&fa,   g_fa);
    cudaGetSymbolAddress((void**)&fb,   g_fb);
    cudaGetSymbolAddress((void**)&rst,  g_rst);
    cudaGetSymbolAddress((void**)&y,    g_y);
    cudaGetSymbolAddress((void**)&hid,  g_hid);
    cudaGetSymbolAddress((void**)&wcat, g_wcatT);
    cudaGetSymbolAddress((void**)&wrel, g_wrelT);
    cudaGetSymbolAddress((void**)&w1T,  g_w1T);
    cudaGetSymbolAddress((void**)&w2T,  g_w2T);
    cudaGetSymbolAddress((void**)&cnt,  g_cnt);

    // side streams + events for capture fork/join (created once, outside capture)
    static cudaStream_t s1 = nullptr, s2 = nullptr;
    static cudaEvent_t evRoot = nullptr, evT4 = nullptr, evCsr = nullptr, evRel = nullptr;
    if (!s1) {
        cudaStreamCreateWithFlags(&s1, cudaStreamNonBlocking);
        cudaStreamCreateWithFlags(&s2, cudaStreamNonBlocking);
        cudaEventCreateWithFlags(&evRoot, cudaEventDisableTiming);
        cudaEventCreateWithFlags(&evT4,   cudaEventDisableTiming);
        cudaEventCreateWithFlags(&evCsr,  cudaEventDisableTiming);
        cudaEventCreateWithFlags(&evRel,  cudaEventDisableTiming);
    }

    // fork side streams off the capturing (default) stream
    cudaEventRecord(evRoot, 0);
    cudaStreamWaitEvent(s1, evRoot, 0);
    cudaStreamWaitEvent(s2, evRoot, 0);

    dim3 tb(32, 8);
    const int mT = (NN + 127) / 128;   // 157

    // --- stream s1: CSR build (independent) ---
    cudaMemsetAsync(cnt, 0, NN * sizeof(int), s1);
    count_kernel<<<(EE + 255) / 256, 256, 0, s1>>>(dst);
    scan_kernel<<<1, 1024, 0, s1>>>();
    scatter_kernel<<<(EE + 255) / 256, 256, 0, s1>>>(src, dst, rid);
    cudaEventRecord(evCsr, s1);

    // --- stream s2: weight transposes + rel chain + FFN weight prep ---
    transpose4_rnd<<<dim3(FF / 32, FF / 32, 4), tb, 0, s2>>>(W_head, W_tail, W_ent, W_rel, wcat, wrel);
    cudaEventRecord(evT4, s2);
    transpose_rnd<<<dim3(FHID / 32, FF / 32), tb, 0, s2>>>(W1, w1T, FF, FHID);
    transpose_rnd<<<dim3(FF / 32, FHID / 32), tb, 0, s2>>>(W2, w2T, FHID, FF);
    ln_kernel<<<(RR + 7) / 8, 256, 0, s2>>>(rel_feat, rln, ln_rel_g, ln_rel_b, RR);
    mma_gemm<<<dim3(FF / 128, 1), 256, GSMEM_BYTES, s2>>>(rln, wrel, fr, RR, FF, FF, nullptr, nullptr, 2);
    cudaEventRecord(evRel, s2);

    // --- main stream: LN ent -> proj GEMM ---
    ln_kernel<<<(NN + 7) / 8, 256>>>(ent_feat, xln, ln_ent_g, ln_ent_b, NN);
    cudaStreamWaitEvent(0, evT4, 0);
    mma_gemm<<<dim3(PF / 128, mT), 256, GSMEM_BYTES>>>(xln, wcat, proj, NN, PF, FF, nullptr, nullptr, 2);

    // join: need CSR + fr before attention
    cudaStreamWaitEvent(0, evCsr, 0);
    cudaStreamWaitEvent(0, evRel, 0);

    // attention + softmax + hop1 -> fa; hops 2-4 ping-pong; hop5 fused with LN
    attn_hop1_kernel<<<NN / 8, 256>>>(attn, fa);
    hop_kernel<<<NN / 8, 256>>>(fa, fb);
    hop_kernel<<<NN / 8, 256>>>(fb, fa);
    hop_kernel<<<NN / 8, 256>>>(fa, fb);
    hop_last_ln_kernel<<<NN / 8, 256>>>(fb, rst, y, ent_feat, ln_ff_g, ln_ff_b);

    // FFN with residual
    mma_gemm<<<dim3(FHID / 128, mT), 256, GSMEM_BYTES>>>(y, w1T, hid, NN, FHID, FF, b1, nullptr, 1 | 2);
    mma_gemm<<<dim3(FF / 128, mT), 256, GSMEM_BYTES>>>(hid, w2T, out, NN, FF, FHID, b2, rst, 0);
}

// round 13
// speedup vs baseline: 2.8208x; 1.0134x over previous
#include <cuda_runtime.h>
#include <cuda_fp16.h>
#include <math.h>
#include <stdint.h>

// Problem constants
#define NN 20000
#define EE 320000
#define RR 100
#define FF 256
#define HH 8
#define DD 32
#define FHID 1024
#define PF 768            // packed projection stride (fh|ftl|fen)
#define ALPHA 0.1f
#define SLOPE 0.2f

// ---------------------------------------------------------------------------
__device__ __forceinline__ uint32_t smem_u32(const void* p) {
    uint32_t a;
    asm("{ .reg .u64 t; cvta.to.shared.u64 t, %1; cvt.u32.u64 %0, t; }" : "=r"(a) : "l"(p));
    return a;
}
#define CP_ASYNC16(dst, src) \
    asm volatile("cp.async.cg.shared.global [%0], [%1], 16;" :: "r"(dst), "l"(src) : "memory")
#define CP_COMMIT() asm volatile("cp.async.commit_group;" ::: "memory")
#define CP_WAIT(n)  asm volatile("cp.async.wait_group %0;" :: "n"(n) : "memory")

#define LDSM_X4(r0, r1, r2, r3, addr) \
    asm volatile("ldmatrix.sync.aligned.m8n8.x4.shared.b16 {%0,%1,%2,%3}, [%4];" \
                 : "=r"(r0), "=r"(r1), "=r"(r2), "=r"(r3) : "r"(addr))
#define MMA_F16(c, a, b) \
    asm volatile("mma.sync.aligned.m16n8k16.row.col.f32.f16.f16.f32 " \
                 "{%0,%1,%2,%3},{%4,%5,%6,%7},{%8,%9},{%0,%1,%2,%3};" \
                 : "+f"((c)[0]), "+f"((c)[1]), "+f"((c)[2]), "+f"((c)[3]) \
                 : "r"((a)[0]), "r"((a)[1]), "r"((a)[2]), "r"((a)[3]), \
                   "r"((b)[0]), "r"((b)[1]))

// load/store 8 halves as 2x float4 (fp32 math in registers)
__device__ __forceinline__ void ld_h8(const __half* p, float4& f0, float4& f1) {
    uint4 u = *(const uint4*)(p);
    const __half2* h = (const __half2*)&u;
    float2 a = __half22float2(h[0]);
    float2 b = __half22float2(h[1]);
    float2 c = __half22float2(h[2]);
    float2 d = __half22float2(h[3]);
    f0 = make_float4(a.x, a.y, b.x, b.y);
    f1 = make_float4(c.x, c.y, d.x, d.y);
}
__device__ __forceinline__ void st_h8(__half* p, float4 f0, float4 f1) {
    __half2 h0 = __floats2half2_rn(f0.x, f0.y);
    __half2 h1 = __floats2half2_rn(f0.z, f0.w);
    __half2 h2 = __floats2half2_rn(f1.x, f1.y);
    __half2 h3 = __floats2half2_rn(f1.z, f1.w);
    uint4 u;
    u.x = *(uint32_t*)&h0; u.y = *(uint32_t*)&h1;
    u.z = *(uint32_t*)&h2; u.w = *(uint32_t*)&h3;
    *(uint4*)(p) = u;
}

// ------------------------- scratch (device globals) -------------------------
__device__ __half g_xln[NN * FF];
__device__ __half g_proj[NN * PF];      // [fh | ftl | fen] packed per row (fp16)
__device__ __half g_rln[RR * FF];
__device__ __half g_fr [RR * FF];
__device__ int    g_cnt [NN];
__device__ int    g_perm[EE];
__device__ int    g_rowptr[NN + 1];
__device__ int    g_srcs[EE];
__device__ int    g_rids[EE];
__device__ float  g_e[EE * HH];
__device__ float  g_a[EE * HH];
__device__ __half g_fa[NN * FF];
__device__ __half g_fb[NN * FF];
__device__ float  g_rst[NN * FF];
__device__ __half g_y  [NN * FF];
__device__ __half g_hid[NN * FHID];
__device__ __half g_wcatT[PF * FF];
__device__ __half g_wrelT [FF * FF];
__device__ __half g_w1T[FHID * FF];
__device__ __half g_w2T[FF * FHID];

// ------------------------- LayerNorm (warp per row, fp16 out) -----------------
__global__ void ln_kernel(const float* __restrict__ in, __half* __restrict__ out,
                          const float* __restrict__ gam, const float* __restrict__ bet,
                          int rows) {
    int warp = threadIdx.x >> 5;
    int row = blockIdx.x * 8 + warp;
    if (row >= rows) return;
    int lane = threadIdx.x & 31;
    const int col = lane * 8;
    const float* ip = in + (size_t)row * FF + col;
    float4 x0 = *(const float4*)(ip);
    float4 x1 = *(const float4*)(ip + 4);
    float s  = x0.x + x0.y + x0.z + x0.w + x1.x + x1.y + x1.z + x1.w;
    float s2 = x0.x*x0.x + x0.y*x0.y + x0.z*x0.z + x0.w*x0.w
             + x1.x*x1.x + x1.y*x1.y + x1.z*x1.z + x1.w*x1.w;
    #pragma unroll
    for (int o = 16; o; o >>= 1) {
        s  += __shfl_xor_sync(0xffffffffu, s,  o);
        s2 += __shfl_xor_sync(0xffffffffu, s2, o);
    }
    float m = s * (1.0f / FF);
    float var = s2 * (1.0f / FF) - m * m;
    float inv = rsqrtf(var + 1e-5f);
    float4 gg0 = *(const float4*)(gam + col);
    float4 gg1 = *(const float4*)(gam + col + 4);
    float4 bb0 = *(const float4*)(bet + col);
    float4 bb1 = *(const float4*)(bet + col + 4);
    float4 o0, o1;
    o0.x = (x0.x - m) * inv * gg0.x + bb0.x;
    o0.y = (x0.y - m) * inv * gg0.y + bb0.y;
    o0.z = (x0.z - m) * inv * gg0.z + bb0.z;
    o0.w = (x0.w - m) * inv * gg0.w + bb0.w;
    o1.x = (x1.x - m) * inv * gg1.x + bb1.x;
    o1.y = (x1.y - m) * inv * gg1.y + bb1.y;
    o1.z = (x1.z - m) * inv * gg1.z + bb1.z;
    o1.w = (x1.w - m) * inv * gg1.w + bb1.w;
    st_h8(out + (size_t)row * FF + col, o0, o1);
}

// ------------------------- weight transpose (fp32 -> fp16 K-major) -----------
__global__ void transpose_rnd(const float* __restrict__ B, __half* __restrict__ BT,
                              int K, int N) {
    __shared__ float t[32][33];
    int n0 = blockIdx.x * 32, k0 = blockIdx.y * 32;
    int x = threadIdx.x, y = threadIdx.y;
    #pragma unroll
    for (int r = 0; r < 32; r += 8)
        t[y + r][x] = B[(size_t)(k0 + y + r) * N + n0 + x];
    __syncthreads();
    #pragma unroll
    for (int r = 0; r < 32; r += 8)
        BT[(size_t)(n0 + y + r) * K + k0 + x] = __float2half_rn(t[x][y + r]);
}
__global__ void transpose4_rnd(const float* __restrict__ Wh, const float* __restrict__ Wt,
                               const float* __restrict__ We, const float* __restrict__ Wr,
                               __half* __restrict__ wcat, __half* __restrict__ wrel) {
    __shared__ float t[32][33];
    int z = blockIdx.z;
    const float* B = (z == 0) ? Wh : (z == 1) ? Wt : (z == 2) ? We : Wr;
    __half* BT = (z < 3) ? (wcat + (size_t)z * FF * FF) : wrel;
    int n0 = blockIdx.x * 32, k0 = blockIdx.y * 32;
    int x = threadIdx.x, y = threadIdx.y;
    #pragma unroll
    for (int r = 0; r < 32; r += 8)
        t[y + r][x] = B[(size_t)(k0 + y + r) * FF + n0 + x];
    __syncthreads();
    #pragma unroll
    for (int r = 0; r < 32; r += 8)
        BT[(size_t)(n0 + y + r) * FF + k0 + x] = __float2half_rn(t[x][y + r]);
}

// ------------------- fp16 mma.sync GEMM (single-sync mainloop) ----------------
#define GSTAGES 3
#define GSTG 32768
#define GSMEM_BYTES (GSTAGES * GSTG)

__global__ void __launch_bounds__(256, 2)
mma_gemm(const __half* __restrict__ A, const __half* __restrict__ BT,
         void* __restrict__ Cv, int M, int Nc, int K,
         const float* __restrict__ bias, const float* __restrict__ res, int mode) {
    extern __shared__ float smemf[];
    const uint32_t sb = smem_u32(smemf);

    const int m0 = blockIdx.y * 128;
    const int n0 = blockIdx.x * 128;
    const int tid = threadIdx.x;
    const int warp = tid >> 5, lane = tid & 31;
    const int wm = warp >> 2, wn = warp & 3;

    const int lrow = tid >> 1, lhalf = tid & 1;
    int aRow = m0 + lrow; if (aRow >= M) aRow = M - 1;
    const __half* aG = A + (size_t)aRow * K + lhalf * 32;
    const __half* bG = BT + (size_t)(n0 + lrow) * K + lhalf * 32;
    const uint32_t sA = sb + (uint32_t)lrow * 128;
    const uint32_t sB = sb + 16384 + (uint32_t)lrow * 128;
    uint32_t swz[4];
    #pragma unroll
    for (int j = 0; j < 4; j++)
        swz[j] = (uint32_t)(((lhalf * 4 + j) ^ (lrow & 7)) << 4);

    const int nCh = K >> 6;

    float c[4][4][4];
    #pragma unroll
    for (int mt = 0; mt < 4; mt++)
        #pragma unroll
        for (int nt = 0; nt < 4; nt++)
            #pragma unroll
            for (int q = 0; q < 4; q++) c[mt][nt][q] = 0.f;

    #pragma unroll
    for (int s = 0; s < 2; s++) {
        const uint32_t off = (uint32_t)s * GSTG;
        const __half* ag = aG + s * 64;
        const __half* bg = bG + s * 64;
        #pragma unroll
        for (int j = 0; j < 4; j++) CP_ASYNC16(sA + off + swz[j], ag + j * 8);
        #pragma unroll
        for (int j = 0; j < 4; j++) CP_ASYNC16(sB + off + swz[j], bg + j * 8);
        CP_COMMIT();
    }

    const int q8 = lane >> 3, r8 = lane & 7;

    for (int i = 0; i < nCh; i++) {
        CP_WAIT(1);              // stage i resident for this thread
        __syncthreads();         // all threads see stage i; all done with stage i-1
        if (i + 2 < nCh) {
            const uint32_t off = (uint32_t)((i + 2) % GSTAGES) * GSTG;
            const __half* ag = aG + (i + 2) * 64;
            const __half* bg = bG + (i + 2) * 64;
            #pragma unroll
            for (int j = 0; j < 4; j++) CP_ASYNC16(sA + off + swz[j], ag + j * 8);
            #pragma unroll
            for (int j = 0; j < 4; j++) CP_ASYNC16(sB + off + swz[j], bg + j * 8);
        }
        CP_COMMIT();

        const uint32_t Ab = sb + (uint32_t)(i % GSTAGES) * GSTG;
        const uint32_t Bb = Ab + 16384;
        #pragma unroll
        for (int ks = 0; ks < 4; ks++) {
            uint32_t a[4][4];
            #pragma unroll
            for (int mt = 0; mt < 4; mt++) {
                const int rl = wm * 64 + mt * 16 + (q8 & 1) * 8 + r8;
                const int kc = ks * 2 + (q8 >> 1);
                const uint32_t ad = Ab + (uint32_t)rl * 128 + (uint32_t)((kc ^ (rl & 7)) << 4);
                LDSM_X4(a[mt][0], a[mt][1], a[mt][2], a[mt][3], ad);
            }
            uint32_t b[4][2];
            #pragma unroll
            for (int p = 0; p < 2; p++) {
                const int nl = wn * 32 + (p * 2 + (q8 >> 1)) * 8 + r8;
                const int kc = ks * 2 + (q8 & 1);
                const uint32_t bd = Bb + (uint32_t)nl * 128 + (uint32_t)((kc ^ (nl & 7)) << 4);
                LDSM_X4(b[p * 2][0], b[p * 2][1], b[p * 2 + 1][0], b[p * 2 + 1][1], bd);
            }
            #pragma unroll
            for (int mt = 0; mt < 4; mt++)
                #pragma unroll
                for (int nt = 0; nt < 4; nt++)
                    MMA_F16(c[mt][nt], a[mt], b[nt]);
        }
    }

    const int g = lane >> 2, t4 = lane & 3;
    #pragma unroll
    for (int mt = 0; mt < 4; mt++) {
        #pragma unroll
        for (int half = 0; half < 2; half++) {
            const int m = m0 + wm * 64 + mt * 16 + g + half * 8;
            if (m < M) {
                #pragma unroll
                for (int nt = 0; nt < 4; nt++) {
                    const int colb = nt * 8 + 2 * t4;
                    const int col = n0 + wn * 32 + colb;
                    float v0 = c[mt][nt][half * 2 + 0];
                    float v1 = c[mt][nt][half * 2 + 1];
                    if (bias) { v0 += bias[col]; v1 += bias[col + 1]; }
                    if (mode & 1) { v0 = fmaxf(v0, 0.f); v1 = fmaxf(v1, 0.f); }
                    if (mode & 2) {
                        __half2 hv = __floats2half2_rn(v0, v1);
                        *(__half2*)((__half*)Cv + (size_t)m * Nc + col) = hv;
                    } else {
                        if (res) {
                            const float* rp = res + (size_t)m * Nc + col;
                            v0 += rp[0]; v1 += rp[1];
                        }
                        float2 v; v.x = v0; v.y = v1;
                        *(float2*)((float*)Cv + (size_t)m * Nc + col) = v;
                    }
                }
            }
        }
    }
}

// ------------------------- CSR build -----------------------------------------
__global__ void count_kernel(const int* __restrict__ dst) {
    int i = blockIdx.x * blockDim.x + threadIdx.x;
    if (i < EE) g_perm[i] = atomicAdd(&g_cnt[dst[i]], 1);
}
__global__ void scan_kernel() {
    __shared__ int ss[1024];
    int t = threadIdx.x;
    const int CH = (NN + 1023) / 1024;
    int base = t * CH;
    int loc = 0;
    for (int i = 0; i < CH; i++) {
        int idx = base + i;
        if (idx < NN) loc += g_cnt[idx];
    }
    ss[t] = loc;
    __syncthreads();
    for (int off = 1; off < 1024; off <<= 1) {
        int v = (t >= off) ? ss[t - off] : 0;
        __syncthreads();
        ss[t] += v;
        __syncthreads();
    }
    int run = (t == 0) ? 0 : ss[t - 1];
    for (int i = 0; i < CH; i++) {
        int idx = base + i;
        if (idx < NN) { g_rowptr[idx] = run; run += g_cnt[idx]; }
    }
    if (t == 0) g_rowptr[NN] = EE;
}
__global__ void scatter_kernel(const int* __restrict__ src, const int* __restrict__ dst,
                               const int* __restrict__ rid) {
    int i = blockIdx.x * blockDim.x + threadIdx.x;
    if (i < EE) {
        int pos = g_rowptr[dst[i]] + g_perm[i];
        g_srcs[pos] = src[i];
        g_rids[pos] = rid[i];
    }
}

// ---------------- edge attention + per-node softmax ---------------------------
__global__ void attn_kernel(const float* __restrict__ attn) {
    int w = (blockIdx.x * blockDim.x + threadIdx.x) >> 5;
    int lane = threadIdx.x & 31;
    if (w >= NN) return;
    int node = w;
    const int h = lane >> 2;
    const int db = (lane & 3) * 8;
    const int off = h * DD + db;

    float4 tl0, tl1;
    ld_h8(g_proj + (size_t)node * PF + FF + off, tl0, tl1);
    float4 av0 = *(const float4*)(attn + off);
    float4 av1 = *(const float4*)(attn + off + 4);

    int beg = g_rowptr[node], end = g_rowptr[node + 1];
    float scale = logf((float)(end - beg)) * (1.0f / DD);

    float mloc = -1e30f;
    for (int p = beg; p < end; p++) {
        int s = g_srcs[p], r = g_rids[p];
        float4 fh0, fh1, fr0, fr1;
        ld_h8(g_proj + (size_t)s * PF + off, fh0, fh1);
        ld_h8(g_fr + (size_t)r * FF + off, fr0, fr1);
        float v = 0.f;
        {
            float x;
            x = fh0.x * tl0.x * fr0.x; x = (x > 0.f) ? x : SLOPE * x; v += x * av0.x;
            x = fh0.y * tl0.y * fr0.y; x = (x > 0.f) ? x : SLOPE * x; v += x * av0.y;
            x = fh0.z * tl0.z * fr0.z; x = (x > 0.f) ? x : SLOPE * x; v += x * av0.z;
            x = fh0.w * tl0.w * fr0.w; x = (x > 0.f) ? x : SLOPE * x; v += x * av0.w;
            x = fh1.x * tl1.x * fr1.x; x = (x > 0.f) ? x : SLOPE * x; v += x * av1.x;
            x = fh1.y * tl1.y * fr1.y; x = (x > 0.f) ? x : SLOPE * x; v += x * av1.y;
            x = fh1.z * tl1.z * fr1.z; x = (x > 0.f) ? x : SLOPE * x; v += x * av1.z;
            x = fh1.w * tl1.w * fr1.w; x = (x > 0.f) ? x : SLOPE * x; v += x * av1.w;
        }
        v += __shfl_xor_sync(0xffffffffu, v, 1);
        v += __shfl_xor_sync(0xffffffffu, v, 2);
        v *= scale;
        mloc = fmaxf(mloc, v);
        if ((lane & 3) == 0) g_e[p * HH + h] = v;
    }
    __syncwarp();

    const int hs = lane & 7, pi = lane >> 3;
    float m = __shfl_sync(0xffffffffu, mloc, hs * 4);
    float ssum = 0.f;
    for (int p = beg + pi; p < end; p += 4) ssum += expf(g_e[p * HH + hs] - m);
    ssum += __shfl_xor_sync(0xffffffffu, ssum, 8);
    ssum += __shfl_xor_sync(0xffffffffu, ssum, 16);
    float inv = 1.0f / ssum;
    for (int p = beg + pi; p < end; p += 4)
        g_a[p * HH + hs] = expf(g_e[p * HH + hs] - m) * inv;
}

// ------------------------- diffusion hop (fp16 -> fp16, strided in) -----------
__global__ void hop_kernel(const __half* __restrict__ fin, int fstride,
                           __half* __restrict__ fout) {
    int w = (blockIdx.x * blockDim.x + threadIdx.x) >> 5;
    int lane = threadIdx.x & 31;
    if (w >= NN) return;
    int node = w;
    const int col = lane * 8;
    const int h = lane >> 2;
    int beg = g_rowptr[node], end = g_rowptr[node + 1];

    float4 a0 = make_float4(0.f, 0.f, 0.f, 0.f);
    float4 a1 = make_float4(0.f, 0.f, 0.f, 0.f);
    int p = beg;
    for (; p + 2 <= end; p += 2) {
        int s0 = g_srcs[p], s1 = g_srcs[p + 1];
        float w0 = g_a[p * HH + h], w1 = g_a[(p + 1) * HH + h];
        float4 f00, f01, f10, f11;
        ld_h8(fin + (size_t)s0 * fstride + col, f00, f01);
        ld_h8(fin + (size_t)s1 * fstride + col, f10, f11);
        a0.x += w0 * f00.x + w1 * f10.x; a0.y += w0 * f00.y + w1 * f10.y;
        a0.z += w0 * f00.z + w1 * f10.z; a0.w += w0 * f00.w + w1 * f10.w;
        a1.x += w0 * f01.x + w1 * f11.x; a1.y += w0 * f01.y + w1 * f11.y;
        a1.z += w0 * f01.z + w1 * f11.z; a1.w += w0 * f01.w + w1 * f11.w;
    }
    for (; p < end; p++) {
        int s = g_srcs[p];
        float av = g_a[p * HH + h];
        float4 f0, f1;
        ld_h8(fin + (size_t)s * fstride + col, f0, f1);
        a0.x += av * f0.x; a0.y += av * f0.y; a0.z += av * f0.z; a0.w += av * f0.w;
        a1.x += av * f1.x; a1.y += av * f1.y; a1.z += av * f1.z; a1.w += av * f1.w;
    }
    float4 e0, e1;
    ld_h8(g_proj + (size_t)node * PF + 2 * FF + col, e0, e1);
    float4 o0, o1;
    o0.x = (1.0f - ALPHA) * a0.x + ALPHA * e0.x;
    o0.y = (1.0f - ALPHA) * a0.y + ALPHA * e0.y;
    o0.z = (1.0f - ALPHA) * a0.z + ALPHA * e0.z;
    o0.w = (1.0f - ALPHA) * a0.w + ALPHA * e0.w;
    o1.x = (1.0f - ALPHA) * a1.x + ALPHA * e1.x;
    o1.y = (1.0f - ALPHA) * a1.y + ALPHA * e1.y;
    o1.z = (1.0f - ALPHA) * a1.z + ALPHA * e1.z;
    o1.w = (1.0f - ALPHA) * a1.w + ALPHA * e1.w;
    st_h8(fout + (size_t)node * FF + col, o0, o1);
}

// ---------- last hop: + ent residual -> rst (fp32) AND y = LN(rst) (fp16) -----
__global__ void hop_last_ln_kernel(const __half* __restrict__ fin,
                                   float* __restrict__ rst, __half* __restrict__ yout,
                                   const float* __restrict__ ent,
                                   const float* __restrict__ gam,
                                   const float* __restrict__ bet) {
    int w = (blockIdx.x * blockDim.x + threadIdx.x) >> 5;
    int lane = threadIdx.x & 31;
    if (w >= NN) return;
    int node = w;
    const int col = lane * 8;
    const int h = lane >> 2;
    int beg = g_rowptr[node], end = g_rowptr[node + 1];

    float4 a0 = make_float4(0.f, 0.f, 0.f, 0.f);
    float4 a1 = make_float4(0.f, 0.f, 0.f, 0.f);
    int p = beg;
    for (; p + 2 <= end; p += 2) {
        int s0 = g_srcs[p], s1 = g_srcs[p + 1];
        float w0 = g_a[p * HH + h], w1 = g_a[(p + 1) * HH + h];
        float4 f00, f01, f10, f11;
        ld_h8(fin + (size_t)s0 * FF + col, f00, f01);
        ld_h8(fin + (size_t)s1 * FF + col, f10, f11);
        a0.x += w0 * f00.x + w1 * f10.x; a0.y += w0 * f00.y + w1 * f10.y;
        a0.z += w0 * f00.z + w1 * f10.z; a0.w += w0 * f00.w + w1 * f10.w;
        a1.x += w0 * f01.x + w1 * f11.x; a1.y += w0 * f01.y + w1 * f11.y;
        a1.z += w0 * f01.z + w1 * f11.z; a1.w += w0 * f01.w + w1 * f11.w;
    }
    for (; p < end; p++) {
        int s = g_srcs[p];
        float av = g_a[p * HH + h];
        float4 f0, f1;
        ld_h8(fin + (size_t)s * FF + col, f0, f1);
        a0.x += av * f0.x; a0.y += av * f0.y; a0.z += av * f0.z; a0.w += av * f0.w;
        a1.x += av * f1.x; a1.y += av * f1.y; a1.z += av * f1.z; a1.w += av * f1.w;
    }
    float4 e0, e1;
    ld_h8(g_proj + (size_t)node * PF + 2 * FF + col, e0, e1);
    const float* ep = ent + (size_t)node * FF + col;
    float4 n0 = *(const float4*)(ep);
    float4 n1 = *(const float4*)(ep + 4);
    float4 o0, o1;
    o0.x = (1.0f - ALPHA) * a0.x + ALPHA * e0.x + n0.x;
    o0.y = (1.0f - ALPHA) * a0.y + ALPHA * e0.y + n0.y;
    o0.z = (1.0f - ALPHA) * a0.z + ALPHA * e0.z + n0.z;
    o0.w = (1.0f - ALPHA) * a0.w + ALPHA * e0.w + n0.w;
    o1.x = (1.0f - ALPHA) * a1.x + ALPHA * e1.x + n1.x;
    o1.y = (1.0f - ALPHA) * a1.y + ALPHA * e1.y + n1.y;
    o1.z = (1.0f - ALPHA) * a1.z + ALPHA * e1.z + n1.z;
    o1.w = (1.0f - ALPHA) * a1.w + ALPHA * e1.w + n1.w;
    float* rp = rst + (size_t)node * FF + col;
    *(float4*)(rp) = o0;
    *(float4*)(rp + 4) = o1;

    float s  = o0.x + o0.y + o0.z + o0.w + o1.x + o1.y + o1.z + o1.w;
    float s2 = o0.x*o0.x + o0.y*o0.y + o0.z*o0.z + o0.w*o0.w
             + o1.x*o1.x + o1.y*o1.y + o1.z*o1.z + o1.w*o1.w;
    #pragma unroll
    for (int o = 16; o; o >>= 1) {
        s  += __shfl_xor_sync(0xffffffffu, s,  o);
        s2 += __shfl_xor_sync(0xffffffffu, s2, o);
    }
    float m = s * (1.0f / FF);
    float var = s2 * (1.0f / FF) - m * m;
    float inv = rsqrtf(var + 1e-5f);
    float4 gg0 = *(const float4*)(gam + col);
    float4 gg1 = *(const float4*)(gam + col + 4);
    float4 bb0 = *(const float4*)(bet + col);
    float4 bb1 = *(const float4*)(bet + col + 4);
    float4 y0, y1;
    y0.x = (o0.x - m) * inv * gg0.x + bb0.x;
    y0.y = (o0.y - m) * inv * gg0.y + bb0.y;
    y0.z = (o0.z - m) * inv * gg0.z + bb0.z;
    y0.w = (o0.w - m) * inv * gg0.w + bb0.w;
    y1.x = (o1.x - m) * inv * gg1.x + bb1.x;
    y1.y = (o1.y - m) * inv * gg1.y + bb1.y;
    y1.z = (o1.z - m) * inv * gg1.z + bb1.z;
    y1.w = (o1.w - m) * inv * gg1.w + bb1.w;
    st_h8(yout + (size_t)node * FF + col, y0, y1);
}

// ------------------------- launcher -------------------------------------------
extern "C" void kernel_launch(void* const* d_in, const int* in_sizes, int n_in,
                              void* d_out, int out_size) {
    const float* ent_feat = (const float*)d_in[0];
    const float* rel_feat = (const float*)d_in[1];
    const float* W_head   = (const float*)d_in[2];
    const float* W_tail   = (const float*)d_in[3];
    const float* W_ent    = (const float*)d_in[4];
    const float* W_rel    = (const float*)d_in[5];
    const float* attn     = (const float*)d_in[6];
    const float* ln_ent_g = (const float*)d_in[7];
    const float* ln_ent_b = (const float*)d_in[8];
    const float* ln_rel_g = (const float*)d_in[9];
    const float* ln_rel_b = (const float*)d_in[10];
    const float* ln_ff_g  = (const float*)d_in[11];
    const float* ln_ff_b  = (const float*)d_in[12];
    const float* W1       = (const float*)d_in[13];
    const float* b1       = (const float*)d_in[14];
    const float* W2       = (const float*)d_in[15];
    const float* b2       = (const float*)d_in[16];
    const int*   src      = (const int*)d_in[17];
    const int*   dst      = (const int*)d_in[18];
    const int*   rid      = (const int*)d_in[19];
    float* out = (float*)d_out;

    cudaFuncSetAttribute(mma_gemm, cudaFuncAttributeMaxDynamicSharedMemorySize, GSMEM_BYTES);

    float *rst;
    __half *xln, *proj, *rln, *fr, *fa, *fb, *y, *hid, *wcat, *wrel, *w1T, *w2T;
    int *cnt;
    cudaGetSymbolAddress((void**)&xln,  g_xln);
    cudaGetSymbolAddress((void**)&proj, g_proj);
    cudaGetSymbolAddress((void**)&rln,  g_rln);
    cudaGetSymbolAddress((void**)&fr,   g_fr);
    cudaGetSymbolAddress((void**)&fa,   g_fa);
    cudaGetSymbolAddress((void**)&fb,   g_fb);
    cudaGetSymbolAddress((void**)&rst,  g_rst);
    cudaGetSymbolAddress((void**)&y,    g_y);
    cudaGetSymbolAddress((void**)&hid,  g_hid);
    cudaGetSymbolAddress((void**)&wcat, g_wcatT);
    cudaGetSymbolAddress((void**)&wrel, g_wrelT);
    cudaGetSymbolAddress((void**)&w1T,  g_w1T);
    cudaGetSymbolAddress((void**)&w2T,  g_w2T);
    cudaGetSymbolAddress((void**)&cnt,  g_cnt);

    static cudaStream_t s1 = nullptr, s2 = nullptr;
    static cudaEvent_t evRoot = nullptr, evT4 = nullptr, evLn = nullptr,
                       evCsr = nullptr, evRel = nullptr, evFen = nullptr, evW = nullptr;
    if (!s1) {
        cudaStreamCreateWithFlags(&s1, cudaStreamNonBlocking);
        cudaStreamCreateWithFlags(&s2, cudaStreamNonBlocking);
        cudaEventCreateWithFlags(&evRoot, cudaEventDisableTiming);
        cudaEventCreateWithFlags(&evT4,   cudaEventDisableTiming);
        cudaEventCreateWithFlags(&evLn,   cudaEventDisableTiming);
        cudaEventCreateWithFlags(&evCsr,  cudaEventDisableTiming);
        cudaEventCreateWithFlags(&evRel,  cudaEventDisableTiming);
        cudaEventCreateWithFlags(&evFen,  cudaEventDisableTiming);
        cudaEventCreateWithFlags(&evW,    cudaEventDisableTiming);
    }

    cudaEventRecord(evRoot, 0);
    cudaStreamWaitEvent(s1, evRoot, 0);
    cudaStreamWaitEvent(s2, evRoot, 0);

    dim3 tb(32, 8);
    const int mT = (NN + 127) / 128;   // 157

    // --- stream s1: CSR build ---
    cudaMemsetAsync(cnt, 0, NN * sizeof(int), s1);
    count_kernel<<<(EE + 255) / 256, 256, 0, s1>>>(dst);
    scan_kernel<<<1, 1024, 0, s1>>>();
    scatter_kernel<<<(EE + 255) / 256, 256, 0, s1>>>(src, dst, rid);
    cudaEventRecord(evCsr, s1);

    // --- stream s2 (phase 1): transpose4 + rel chain ---
    transpose4_rnd<<<dim3(FF / 32, FF / 32, 4), tb, 0, s2>>>(W_head, W_tail, W_ent, W_rel, wcat, wrel);
    cudaEventRecord(evT4, s2);
    ln_kernel<<<(RR + 7) / 8, 256, 0, s2>>>(rel_feat, rln, ln_rel_g, ln_rel_b, RR);
    mma_gemm<<<dim3(FF / 128, 1), 256, GSMEM_BYTES, s2>>>(rln, wrel, fr, RR, FF, FF, nullptr, nullptr, 2);
    cudaEventRecord(evRel, s2);

    // --- main: LN ent ---
    ln_kernel<<<(NN + 7) / 8, 256>>>(ent_feat, xln, ln_ent_g, ln_ent_b, NN);
    cudaEventRecord(evLn, 0);

    // --- stream s2 (phase 2): fen projection (N=256 slice) + FFN weight prep ---
    cudaStreamWaitEvent(s2, evLn, 0);
    mma_gemm<<<dim3(2, mT), 256, GSMEM_BYTES, s2>>>(xln, wcat + (size_t)2 * FF * FF,
                                                    proj + 2 * FF, NN, PF, FF,
                                                    nullptr, nullptr, 2);
    cudaEventRecord(evFen, s2);
    transpose_rnd<<<dim3(FHID / 32, FF / 32), tb, 0, s2>>>(W1, w1T, FF, FHID);
    transpose_rnd<<<dim3(FF / 32, FHID / 32), tb, 0, s2>>>(W2, w2T, FHID, FF);
    cudaEventRecord(evW, s2);

    // --- main: fh|ftl projection (N=512 slice) ---
    cudaStreamWaitEvent(0, evT4, 0);
    mma_gemm<<<dim3(4, mT), 256, GSMEM_BYTES>>>(xln, wcat, proj, NN, PF, FF, nullptr, nullptr, 2);

    // join for attention (CSR + fr); fen GEMM overlaps with attn
    cudaStreamWaitEvent(0, evCsr, 0);
    cudaStreamWaitEvent(0, evRel, 0);
    attn_kernel<<<NN / 8, 256>>>(attn);

    // hops: need fen now
    cudaStreamWaitEvent(0, evFen, 0);
    hop_kernel<<<NN / 8, 256>>>(proj + 2 * FF, PF, fa);
    hop_kernel<<<NN / 8, 256>>>(fa, FF, fb);
    hop_kernel<<<NN / 8, 256>>>(fb, FF, fa);
    hop_kernel<<<NN / 8, 256>>>(fa, FF, fb);
    hop_last_ln_kernel<<<NN / 8, 256>>>(fb, rst, y, ent_feat, ln_ff_g, ln_ff_b);

    // FFN with residual
    cudaStreamWaitEvent(0, evW, 0);
    mma_gemm<<<dim3(FHID / 128, mT), 256, GSMEM_BYTES>>>(y, w1T, hid, NN, FHID, FF, b1, nullptr, 1 | 2);
    mma_gemm<<<dim3(FF / 128, mT), 256, GSMEM_BYTES>>>(hid, w2T, out, NN, FF, FHID, b2, rst, 0);
}